// round 6
// baseline (speedup 1.0000x reference)
#include <cuda_runtime.h>
#include <cuda_bf16.h>
#include <math.h>
#include <stdint.h>

#define NT  32768
#define CC  128
#define BB  64
#define NNODE 512
#define HH  4
#define DHD 32
#define EE  524288

// ---------------- scratch ----------------
__device__ int   g_deg[NT];
__device__ int   g_off[NT+1];
__device__ int   g_cur[NT];
__device__ int   g_nbr[EE];
__device__ float g_hlocal[NT*CC];
__device__ float g_hattn[NT*CC];
__device__ float g_comb[NT*CC];
__device__ float g_out2[NT*CC];
__device__ float g_sums[3*2*CC];
__device__ float g_scale[3*CC];
__device__ float g_shift[3*CC];

__device__ __nv_bfloat16 g_xs[NT*384];       // [hi|lo|hi]
__device__ __nv_bfloat16 g_aggs[NT*384];
__device__ __nv_bfloat16 g_obufs[NT*384];
__device__ __nv_bfloat16 g_combs[NT*384];
__device__ __nv_bfloat16 g_hiddens[NT*768];
__device__ __nv_bfloat16 g_Wcs[128*384];     // [hi|hi|lo]
__device__ __nv_bfloat16 g_ipws[384*384];
__device__ __nv_bfloat16 g_opws[128*384];
__device__ __nv_bfloat16 g_Wm1s[256*384];
__device__ __nv_bfloat16 g_Wm2s[128*768];
__device__ __nv_bfloat16 g_qs[BB*HH*NNODE*64];
__device__ __nv_bfloat16 g_ks[BB*HH*NNODE*64];
__device__ __nv_bfloat16 g_vs[BB*HH*NNODE*64];

// ---------------- helpers ----------------
__device__ __forceinline__ uint32_t smem_u32(const void* p) {
    uint32_t a;
    asm("{ .reg .u64 t; cvta.to.shared.u64 t, %1; cvt.u32.u64 %0, t; }" : "=r"(a) : "l"(p));
    return a;
}
__device__ __forceinline__ uint32_t pack_bf2(__nv_bfloat16 a, __nv_bfloat16 b) {
    return (uint32_t)__bfloat16_as_ushort(a) | ((uint32_t)__bfloat16_as_ushort(b) << 16);
}
__device__ __forceinline__ void split_bf(float v, __nv_bfloat16& hi, __nv_bfloat16& lo) {
    hi = __float2bfloat16(v);
    lo = __float2bfloat16(v - __bfloat162float(hi));
}
__device__ __forceinline__ void ldmx4(uint32_t* r, uint32_t addr) {
    asm volatile("ldmatrix.sync.aligned.m8n8.x4.shared.b16 {%0,%1,%2,%3}, [%4];"
        : "=r"(r[0]), "=r"(r[1]), "=r"(r[2]), "=r"(r[3]) : "r"(addr));
}
__device__ __forceinline__ void mma_bf(float* c, const uint32_t* a, uint32_t b0, uint32_t b1) {
    asm volatile("mma.sync.aligned.m16n8k16.row.col.f32.bf16.bf16.f32 "
        "{%0,%1,%2,%3}, {%4,%5,%6,%7}, {%8,%9}, {%0,%1,%2,%3};"
        : "+f"(c[0]), "+f"(c[1]), "+f"(c[2]), "+f"(c[3])
        : "r"(a[0]), "r"(a[1]), "r"(a[2]), "r"(a[3]), "r"(b0), "r"(b1));
}
__device__ __forceinline__ void store_a128(__nv_bfloat16* base, int r, int c, float v) {
    __nv_bfloat16 hi, lo; split_bf(v, hi, lo);
    __nv_bfloat16* o = base + (size_t)r * 384;
    o[c] = hi; o[128 + c] = lo; o[256 + c] = hi;
}
__device__ __forceinline__ void store_w(__nv_bfloat16* base, int r, int c, int K, float v) {
    __nv_bfloat16 hi, lo; split_bf(v, hi, lo);
    __nv_bfloat16* o = base + (size_t)(3*r) * K;
    o[c] = hi; o[K + c] = hi; o[2*K + c] = lo;
}

// ---------------- CSR build ----------------
__global__ void k_zero() {
    int i = blockIdx.x * blockDim.x + threadIdx.x;
    if (i < NT) g_deg[i] = 0;
    if (i < 3*2*CC) g_sums[i] = 0.f;
}
__global__ void k_deg(const int* __restrict__ dst) {
    int i = blockIdx.x * blockDim.x + threadIdx.x;
    if (i < EE) atomicAdd(&g_deg[dst[i]], 1);
}
__global__ void k_scan() {
    __shared__ int ssum[1024];
    int t = threadIdx.x;
    int base = t * 32;
    int s = 0;
    #pragma unroll
    for (int i = 0; i < 32; i++) s += g_deg[base + i];
    ssum[t] = s;
    __syncthreads();
    for (int off = 1; off < 1024; off <<= 1) {
        int tmp = (t >= off) ? ssum[t - off] : 0;
        __syncthreads();
        ssum[t] += tmp;
        __syncthreads();
    }
    int run = ssum[t] - s;
    #pragma unroll
    for (int i = 0; i < 32; i++) {
        g_off[base + i] = run;
        g_cur[base + i] = run;
        run += g_deg[base + i];
    }
    if (t == 1023) g_off[NT] = run;
}
__global__ void k_fill(const int* __restrict__ src, const int* __restrict__ dst) {
    int i = blockIdx.x * blockDim.x + threadIdx.x;
    if (i < EE) {
        int p = atomicAdd(&g_cur[dst[i]], 1);
        g_nbr[p] = src[i];
    }
}

// ---------------- one prep kernel: all splits ----------------
// layout of index space: x(4194304) | Wc(16384) | ipw(49152) | opw(16384) | Wm1(32768) | Wm2(32768)
__global__ void k_prep(const float* __restrict__ x, const float* __restrict__ Wc,
                       const float* __restrict__ ipw, const float* __restrict__ opw,
                       const float* __restrict__ Wm1, const float* __restrict__ Wm2) {
    int i = blockIdx.x * 256 + threadIdx.x;
    if (i < 4194304) { store_a128(g_xs, i >> 7, i & 127, x[i]); return; }
    i -= 4194304;
    if (i < 16384) { store_w(g_Wcs, i >> 7, i & 127, 128, Wc[i]); return; }
    i -= 16384;
    if (i < 49152) { store_w(g_ipws, i >> 7, i & 127, 128, ipw[i]); return; }
    i -= 49152;
    if (i < 16384) { store_w(g_opws, i >> 7, i & 127, 128, opw[i]); return; }
    i -= 16384;
    if (i < 32768) { store_w(g_Wm1s, i >> 7, i & 127, 128, Wm1[i]); return; }
    i -= 32768;
    store_w(g_Wm2s, i >> 8, i & 255, 256, Wm2[i]);
}

// ---------------- mean aggregation ----------------
__global__ void k_agg(const float* __restrict__ x) {
    __shared__ int snbr[128];
    int n = blockIdx.x, c = threadIdx.x;
    int s0 = g_off[n], s1 = g_off[n+1];
    float acc = 0.f;
    for (int j0 = s0; j0 < s1; j0 += 128) {
        int m = min(128, s1 - j0);
        __syncthreads();
        if (c < m) snbr[c] = g_nbr[j0 + c];
        __syncthreads();
        for (int jj = 0; jj < m; jj++) acc += x[snbr[jj]*CC + c];
    }
    float d = (float)(s1 - s0);
    store_a128(g_aggs, n, c, acc / fmaxf(d, 1.f));
}

// ---------------- GEMM mainloop macro body (shared by kernels) ----------------
#define MG_SMEM (2*32768)

__device__ __forceinline__ void mg_mainloop(
    const __nv_bfloat16* __restrict__ Ap, const __nv_bfloat16* __restrict__ Wp,
    int Kp, char* smem, uint32_t sbase, int t, int lane, int mrow, int ncol,
    float acc[4][4][4])
{
    const int nch = Kp >> 6;
    auto load_chunk = [&](int ck, int buf) {
        int kc = ck * 64;
        #pragma unroll
        for (int i = 0; i < 8; i++) {
            int u = t + 256*i;
            int row_all = u >> 3, seg = u & 7;
            int isB = row_all >> 7;
            int row = row_all & 127;
            const __nv_bfloat16* src = (isB ? Wp : Ap) + (size_t)row * Kp + kc + seg*8;
            uint32_t dst = sbase + buf*32768 + isB*16384 + row*128 + ((seg ^ (row & 7)) * 16);
            asm volatile("cp.async.cg.shared.global [%0], [%1], 16;" :: "r"(dst), "l"(src));
        }
        asm volatile("cp.async.commit_group;" ::: "memory");
    };
    load_chunk(0, 0);
    for (int ck = 0; ck < nch; ck++) {
        if (ck + 1 < nch) {
            load_chunk(ck + 1, (ck + 1) & 1);
            asm volatile("cp.async.wait_group 1;" ::: "memory");
        } else {
            asm volatile("cp.async.wait_group 0;" ::: "memory");
        }
        __syncthreads();
        uint32_t Ab = sbase + (ck & 1)*32768;
        uint32_t Bb = Ab + 16384;
        #pragma unroll
        for (int s = 0; s < 4; s++) {
            int segsw = ((s*2 + (lane >> 4)) ^ (lane & 7)) * 16;
            uint32_t af[4][4];
            #pragma unroll
            for (int mt = 0; mt < 4; mt++)
                ldmx4(af[mt], Ab + (mrow + mt*16 + (lane & 15))*128 + segsw);
            uint32_t bf[4][2];
            #pragma unroll
            for (int half = 0; half < 2; half++) {
                uint32_t r4[4];
                ldmx4(r4, Bb + (ncol + half*16 + (lane & 15))*128 + segsw);
                bf[half*2+0][0] = r4[0]; bf[half*2+0][1] = r4[2];
                bf[half*2+1][0] = r4[1]; bf[half*2+1][1] = r4[3];
            }
            #pragma unroll
            for (int mt = 0; mt < 4; mt++)
                #pragma unroll
                for (int nt = 0; nt < 4; nt++)
                    mma_bf(acc[mt][nt], af[mt], bf[nt][0], bf[nt][1]);
        }
        __syncthreads();
    }
}

// stats flush: per-thread partial sums (8 cols) -> smem -> global atomic
__device__ __forceinline__ void mg_stats_flush(char* smem, int t, int lane, int ncol,
                                               const float* csum, const float* csq, int which) {
    float* ssum = (float*)smem;       // [128]
    float* ssq  = ssum + 128;         // [128]
    if (t < 256) { ((float*)smem)[t] = 0.f; }
    __syncthreads();
    #pragma unroll
    for (int nt = 0; nt < 4; nt++) {
        int c0 = ncol + nt*8 + 2*(lane & 3);
        atomicAdd(&ssum[c0],   csum[nt*2+0]);
        atomicAdd(&ssum[c0+1], csum[nt*2+1]);
        atomicAdd(&ssq[c0],    csq[nt*2+0]);
        atomicAdd(&ssq[c0+1],  csq[nt*2+1]);
    }
    __syncthreads();
    if (t < 128) {
        atomicAdd(&g_sums[which*256 + t],       ssum[t]);
        atomicAdd(&g_sums[which*256 + 128 + t], ssq[t]);
    }
}

// ---------------- merged local + QKV GEMM: grid (NT/128, 4) ----------------
__global__ __launch_bounds__(256) void k_mg_lqkv(
    const float* __restrict__ ipb, const float* __restrict__ bc, const float* __restrict__ x)
{
    extern __shared__ char smem[];
    const int t = threadIdx.x, lane = t & 31, w = t >> 5;
    const int bm = blockIdx.x, by = blockIdx.y;
    const uint32_t sbase = smem_u32(smem);
    const int mrow = (w >> 2) * 64;
    const int ncol = (w & 3) * 32;
    const __nv_bfloat16* Ap = ((by == 3) ? g_aggs : g_xs) + (size_t)bm * 128 * 384;
    const __nv_bfloat16* Wp = (by == 3) ? g_Wcs : (g_ipws + (size_t)by * 128 * 384);

    float acc[4][4][4];
    #pragma unroll
    for (int a = 0; a < 4; a++)
        #pragma unroll
        for (int b = 0; b < 4; b++)
            #pragma unroll
            for (int c = 0; c < 4; c++) acc[a][b][c] = 0.f;

    mg_mainloop(Ap, Wp, 384, smem, sbase, t, lane, mrow, ncol, acc);

    const float* bias = (by == 3) ? bc : (ipb + by*128);
    float csum[8] = {}, csq[8] = {};
    #pragma unroll
    for (int mt = 0; mt < 4; mt++) {
        int m0 = bm*128 + mrow + mt*16 + (lane >> 2);
        #pragma unroll
        for (int nt = 0; nt < 4; nt++) {
            int nl = ncol + nt*8 + 2*(lane & 3);
            float bv0 = bias[nl], bv1 = bias[nl+1];
            #pragma unroll
            for (int hh = 0; hh < 2; hh++) {
                int m = m0 + hh*8;
                float v0 = acc[mt][nt][hh*2+0] + bv0;
                float v1 = acc[mt][nt][hh*2+1] + bv1;
                if (by < 3) {
                    int h = nl >> 5, d = nl & 31;
                    __nv_bfloat16* dp = (by == 0) ? g_qs : (by == 1) ? g_ks : g_vs;
                    int bh = (m >> 9)*HH + h;
                    __nv_bfloat16 h0, l0, h1, l1;
                    split_bf(v0, h0, l0); split_bf(v1, h1, l1);
                    __nv_bfloat16* dst = dp + ((size_t)bh*NNODE + (m & 511))*64 + d;
                    *(uint32_t*)(dst)      = pack_bf2(h0, h1);
                    *(uint32_t*)(dst + 32) = pack_bf2(l0, l1);
                } else {
                    const float2 rv = *(const float2*)(x + (size_t)m*128 + nl);
                    v0 += rv.x; v1 += rv.y;
                    *(float2*)(g_hlocal + (size_t)m*128 + nl) = make_float2(v0, v1);
                    csum[nt*2+0] += v0; csq[nt*2+0] += v0*v0;
                    csum[nt*2+1] += v1; csq[nt*2+1] += v1*v1;
                }
            }
        }
    }
    if (by == 3) {
        __syncthreads();
        mg_stats_flush(smem, t, lane, ncol, csum, csq, 0);
    }
}

// ---------------- generic GEMM: EPI 1 = +bias+resid->fp32 (+stats WHICH>=0); 2 = relu->hiddens ----------------
template<int EPI, int WHICH>
__global__ __launch_bounds__(256) void k_mgemm(
    const __nv_bfloat16* __restrict__ A, const __nv_bfloat16* __restrict__ W,
    const float* __restrict__ bias, const float* __restrict__ resid,
    float* __restrict__ out, int Kp, int Nout)
{
    extern __shared__ char smem[];
    const int t = threadIdx.x, lane = t & 31, w = t >> 5;
    const int bm = blockIdx.x, bn = blockIdx.y;
    const uint32_t sbase = smem_u32(smem);
    const int mrow = (w >> 2) * 64;
    const int ncol = (w & 3) * 32;
    const __nv_bfloat16* Ap = A + (size_t)bm * 128 * Kp;
    const __nv_bfloat16* Wp = W + (size_t)bn * 128 * Kp;

    float acc[4][4][4];
    #pragma unroll
    for (int a = 0; a < 4; a++)
        #pragma unroll
        for (int b = 0; b < 4; b++)
            #pragma unroll
            for (int c = 0; c < 4; c++) acc[a][b][c] = 0.f;

    mg_mainloop(Ap, Wp, Kp, smem, sbase, t, lane, mrow, ncol, acc);

    float csum[8] = {}, csq[8] = {};
    #pragma unroll
    for (int mt = 0; mt < 4; mt++) {
        int m0 = bm*128 + mrow + mt*16 + (lane >> 2);
        #pragma unroll
        for (int nt = 0; nt < 4; nt++) {
            int nl = ncol + nt*8 + 2*(lane & 3);
            int ng = bn*128 + nl;
            float bv0 = bias[ng], bv1 = bias[ng+1];
            #pragma unroll
            for (int hh = 0; hh < 2; hh++) {
                int m = m0 + hh*8;
                float v0 = acc[mt][nt][hh*2+0] + bv0;
                float v1 = acc[mt][nt][hh*2+1] + bv1;
                if (EPI == 2) {
                    v0 = fmaxf(v0, 0.f); v1 = fmaxf(v1, 0.f);
                    __nv_bfloat16 h0, l0, h1, l1;
                    split_bf(v0, h0, l0); split_bf(v1, h1, l1);
                    __nv_bfloat16* dst = g_hiddens + (size_t)m*768 + ng;
                    *(uint32_t*)(dst)       = pack_bf2(h0, h1);
                    *(uint32_t*)(dst + 256) = pack_bf2(l0, l1);
                    *(uint32_t*)(dst + 512) = pack_bf2(h0, h1);
                } else {
                    const float2 rv = *(const float2*)(resid + (size_t)m*Nout + ng);
                    v0 += rv.x; v1 += rv.y;
                    *(float2*)(out + (size_t)m*Nout + ng) = make_float2(v0, v1);
                    if (WHICH >= 0) {
                        csum[nt*2+0] += v0; csq[nt*2+0] += v0*v0;
                        csum[nt*2+1] += v1; csq[nt*2+1] += v1*v1;
                    }
                }
            }
        }
    }
    if (EPI == 1 && WHICH >= 0) {
        __syncthreads();
        mg_stats_flush(smem, t, lane, ncol, csum, csq, WHICH);
    }
}

// ---------------- flash attention (unchanged from R5) ----------------
#define FA_SMEM (3*65536)
__global__ __launch_bounds__(256, 1) void k_fattn() {
    extern __shared__ char sm2[];
    const uint32_t sb = smem_u32(sm2);
    const uint32_t Qb = sb, Kb = sb + 65536, Vb = sb + 131072;
    const int bh = blockIdx.x, t = threadIdx.x, lane = t & 31, w = t >> 5;
    const __nv_bfloat16* qg = g_qs + (size_t)bh * NNODE * 64;
    const __nv_bfloat16* kg = g_ks + (size_t)bh * NNODE * 64;
    const __nv_bfloat16* vg = g_vs + (size_t)bh * NNODE * 64;

    for (int i = t; i < 4096; i += 256) {
        int r = i >> 3, s = i & 7;
        uint32_t off = (uint32_t)(r*128 + ((s ^ (r & 7)) * 16));
        *(float4*)(sm2 + off)          = *(const float4*)(qg + r*64 + s*8);
        *(float4*)(sm2 + 65536 + off)  = *(const float4*)(kg + r*64 + s*8);
    }
    for (int i = t; i < 4096; i += 256) {
        int j = i & 511, s = i >> 9;
        float4 v4 = *(const float4*)(vg + j*64 + s*8);
        const __nv_bfloat16* pv = (const __nv_bfloat16*)&v4;
        #pragma unroll
        for (int k = 0; k < 8; k++) {
            int d = s*8 + k;
            *(__nv_bfloat16*)(sm2 + 131072 + d*1024 + (((j >> 3) ^ (d & 7)) * 16) + (j & 7)*2) = pv[k];
        }
    }
    __syncthreads();

    const int q0 = w * 64;
    uint32_t aqh[4][2][4];
    #pragma unroll
    for (int mt = 0; mt < 4; mt++)
        #pragma unroll
        for (int kc = 0; kc < 2; kc++) {
            int row = q0 + mt*16 + (lane & 15);
            ldmx4(aqh[mt][kc], Qb + row*128 + (((kc*2 + (lane >> 4)) ^ (row & 7)) * 16));
        }

    float of[4][4][4];
    #pragma unroll
    for (int a = 0; a < 4; a++)
        #pragma unroll
        for (int b = 0; b < 4; b++)
            #pragma unroll
            for (int c = 0; c < 4; c++) of[a][b][c] = 0.f;
    float mrow[4][2], lrow[4][2];
    #pragma unroll
    for (int a = 0; a < 4; a++) { mrow[a][0] = -1e30f; mrow[a][1] = -1e30f; lrow[a][0] = 0.f; lrow[a][1] = 0.f; }

    const float sc = 0.17677669529663687f;

    for (int jb = 0; jb < 32; jb++) {
        const int j0 = jb * 16;
        uint32_t bk[4][2][2];
        #pragma unroll
        for (int kc = 0; kc < 4; kc++) {
            int row = j0 + (lane & 15);
            uint32_t r4[4];
            ldmx4(r4, Kb + row*128 + (((kc*2 + (lane >> 4)) ^ (row & 7)) * 16));
            bk[kc][0][0] = r4[0]; bk[kc][0][1] = r4[2];
            bk[kc][1][0] = r4[1]; bk[kc][1][1] = r4[3];
        }
        float c[4][2][4];
        #pragma unroll
        for (int a = 0; a < 4; a++)
            #pragma unroll
            for (int b = 0; b < 2; b++)
                #pragma unroll
                for (int e = 0; e < 4; e++) c[a][b][e] = 0.f;
        #pragma unroll
        for (int mt = 0; mt < 4; mt++) {
            uint32_t aql[2][4];
            #pragma unroll
            for (int kc = 0; kc < 2; kc++) {
                int row = q0 + mt*16 + (lane & 15);
                ldmx4(aql[kc], Qb + row*128 + ((((kc + 2)*2 + (lane >> 4)) ^ (row & 7)) * 16));
            }
            #pragma unroll
            for (int nt = 0; nt < 2; nt++) {
                mma_bf(c[mt][nt], aqh[mt][0], bk[0][nt][0], bk[0][nt][1]);
                mma_bf(c[mt][nt], aqh[mt][1], bk[1][nt][0], bk[1][nt][1]);
                mma_bf(c[mt][nt], aql[0],     bk[0][nt][0], bk[0][nt][1]);
                mma_bf(c[mt][nt], aql[1],     bk[1][nt][0], bk[1][nt][1]);
                mma_bf(c[mt][nt], aqh[mt][0], bk[2][nt][0], bk[2][nt][1]);
                mma_bf(c[mt][nt], aqh[mt][1], bk[3][nt][0], bk[3][nt][1]);
            }
        }
        #pragma unroll
        for (int mt = 0; mt < 4; mt++)
            #pragma unroll
            for (int h = 0; h < 2; h++) {
                float s0 = c[mt][0][h*2]*sc, s1 = c[mt][0][h*2+1]*sc;
                float s2 = c[mt][1][h*2]*sc, s3 = c[mt][1][h*2+1]*sc;
                float mx = fmaxf(fmaxf(s0, s1), fmaxf(s2, s3));
                mx = fmaxf(mx, __shfl_xor_sync(0xffffffffu, mx, 1));
                mx = fmaxf(mx, __shfl_xor_sync(0xffffffffu, mx, 2));
                float mnew = fmaxf(mrow[mt][h], mx);
                float fac = __expf(mrow[mt][h] - mnew);
                mrow[mt][h] = mnew;
                float p0 = __expf(s0 - mnew), p1 = __expf(s1 - mnew);
                float p2 = __expf(s2 - mnew), p3 = __expf(s3 - mnew);
                c[mt][0][h*2] = p0; c[mt][0][h*2+1] = p1;
                c[mt][1][h*2] = p2; c[mt][1][h*2+1] = p3;
                float rs = p0 + p1 + p2 + p3;
                rs += __shfl_xor_sync(0xffffffffu, rs, 1);
                rs += __shfl_xor_sync(0xffffffffu, rs, 2);
                lrow[mt][h] = lrow[mt][h]*fac + rs;
                #pragma unroll
                for (int nt = 0; nt < 4; nt++) { of[mt][nt][h*2] *= fac; of[mt][nt][h*2+1] *= fac; }
            }
        uint32_t pah[4][4], pal[4][4];
        #pragma unroll
        for (int mt = 0; mt < 4; mt++) {
            __nv_bfloat16 hx, lx, hy, ly;
            split_bf(c[mt][0][0], hx, lx); split_bf(c[mt][0][1], hy, ly);
            pah[mt][0] = pack_bf2(hx, hy); pal[mt][0] = pack_bf2(lx, ly);
            split_bf(c[mt][0][2], hx, lx); split_bf(c[mt][0][3], hy, ly);
            pah[mt][1] = pack_bf2(hx, hy); pal[mt][1] = pack_bf2(lx, ly);
            split_bf(c[mt][1][0], hx, lx); split_bf(c[mt][1][1], hy, ly);
            pah[mt][2] = pack_bf2(hx, hy); pal[mt][2] = pack_bf2(lx, ly);
            split_bf(c[mt][1][2], hx, lx); split_bf(c[mt][1][3], hy, ly);
            pah[mt][3] = pack_bf2(hx, hy); pal[mt][3] = pack_bf2(lx, ly);
        }
        uint32_t bvh[4][2], bvl[4][2];
        #pragma unroll
        for (int dh = 0; dh < 2; dh++) {
            int rowh = dh*16 + (lane & 15);
            uint32_t r4[4];
            ldmx4(r4, Vb + rowh*1024 + (((((j0 >> 3) + (lane >> 4)) ^ (rowh & 7))) * 16));
            bvh[dh*2+0][0] = r4[0]; bvh[dh*2+0][1] = r4[2];
            bvh[dh*2+1][0] = r4[1]; bvh[dh*2+1][1] = r4[3];
            int rowl = rowh + 32;
            ldmx4(r4, Vb + rowl*1024 + (((((j0 >> 3) + (lane >> 4)) ^ (rowl & 7))) * 16));
            bvl[dh*2+0][0] = r4[0]; bvl[dh*2+0][1] = r4[2];
            bvl[dh*2+1][0] = r4[1]; bvl[dh*2+1][1] = r4[3];
        }
        #pragma unroll
        for (int mt = 0; mt < 4; mt++)
            #pragma unroll
            for (int nt = 0; nt < 4; nt++) {
                mma_bf(of[mt][nt], pah[mt], bvh[nt][0], bvh[nt][1]);
                mma_bf(of[mt][nt], pal[mt], bvh[nt][0], bvh[nt][1]);
                mma_bf(of[mt][nt], pah[mt], bvl[nt][0], bvl[nt][1]);
            }
    }

    const int b = bh >> 2, h4 = bh & 3;
    #pragma unroll
    for (int mt = 0; mt < 4; mt++)
        #pragma unroll
        for (int h = 0; h < 2; h++) {
            float inv = 1.f / lrow[mt][h];
            int q = q0 + mt*16 + (lane >> 2) + h*8;
            __nv_bfloat16* base = g_obufs + ((size_t)(b*NNODE + q))*384 + h4*DHD;
            #pragma unroll
            for (int nt = 0; nt < 4; nt++) {
                int d = nt*8 + 2*(lane & 3);
                float v0 = of[mt][nt][h*2]   * inv;
                float v1 = of[mt][nt][h*2+1] * inv;
                __nv_bfloat16 h0, l0, h1, l1;
                split_bf(v0, h0, l0); split_bf(v1, h1, l1);
                *(uint32_t*)(base + d)       = pack_bf2(h0, h1);
                *(uint32_t*)(base + 128 + d) = pack_bf2(l0, l1);
                *(uint32_t*)(base + 256 + d) = pack_bf2(h0, h1);
            }
        }
}

// ---------------- finalize / combine / final ----------------
__global__ void k_fin12(const float* __restrict__ gn1, const float* __restrict__ bn1,
                        const float* __restrict__ gn2, const float* __restrict__ bn2) {
    int t = threadIdx.x;
    int which = t >> 7, c = t & 127;
    const float* g = which ? gn2 : gn1;
    const float* b = which ? bn2 : bn1;
    float s  = g_sums[which*256 + c];
    float s2 = g_sums[which*256 + 128 + c];
    float m  = s / (float)NT;
    float v  = s2 / (float)NT - m*m;
    float scale = g[c] * rsqrtf(v + 1e-5f);
    g_scale[which*128 + c] = scale;
    g_shift[which*128 + c] = b[c] - m*scale;
}
__global__ void k_fin3(const float* __restrict__ g, const float* __restrict__ b) {
    int c = threadIdx.x;
    float s  = g_sums[2*256 + c];
    float s2 = g_sums[2*256 + 128 + c];
    float m  = s / (float)NT;
    float v  = s2 / (float)NT - m*m;
    float scale = g[c] * rsqrtf(v + 1e-5f);
    g_scale[2*128 + c] = scale;
    g_shift[2*128 + c] = b[c] - m*scale;
}

__global__ void k_combine() {
    int i = blockIdx.x * blockDim.x + threadIdx.x;
    int c = (i*4) & 127;
    int r = (i*4) >> 7;
    float4 a  = *(const float4*)(g_hlocal + (size_t)i*4);
    float4 bb = *(const float4*)(g_hattn + (size_t)i*4);
    float4 s1 = *(const float4*)(g_scale + c);
    float4 h1 = *(const float4*)(g_shift + c);
    float4 s2 = *(const float4*)(g_scale + 128 + c);
    float4 h2 = *(const float4*)(g_shift + 128 + c);
    float4 o;
    o.x = a.x*s1.x + h1.x + bb.x*s2.x + h2.x;
    o.y = a.y*s1.y + h1.y + bb.y*s2.y + h2.y;
    o.z = a.z*s1.z + h1.z + bb.z*s2.z + h2.z;
    o.w = a.w*s1.w + h1.w + bb.w*s2.w + h2.w;
    *(float4*)(g_comb + (size_t)i*4) = o;
    float vv[4] = {o.x, o.y, o.z, o.w};
    __nv_bfloat16 hi[4], lo[4];
    #pragma unroll
    for (int k = 0; k < 4; k++) split_bf(vv[k], hi[k], lo[k]);
    __nv_bfloat16* dst = g_combs + (size_t)r*384 + c;
    *(uint32_t*)(dst)       = pack_bf2(hi[0], hi[1]);
    *(uint32_t*)(dst + 2)   = pack_bf2(hi[2], hi[3]);
    *(uint32_t*)(dst + 128) = pack_bf2(lo[0], lo[1]);
    *(uint32_t*)(dst + 130) = pack_bf2(lo[2], lo[3]);
    *(uint32_t*)(dst + 256) = pack_bf2(hi[0], hi[1]);
    *(uint32_t*)(dst + 258) = pack_bf2(hi[2], hi[3]);
}

__global__ void k_final(float* __restrict__ out) {
    int i = blockIdx.x * blockDim.x + threadIdx.x;
    int c = (i*4) & 127;
    float4 a  = *(const float4*)(g_out2 + (size_t)i*4);
    float4 s3 = *(const float4*)(g_scale + 256 + c);
    float4 h3 = *(const float4*)(g_shift + 256 + c);
    float4 o;
    o.x = a.x*s3.x + h3.x;
    o.y = a.y*s3.y + h3.y;
    o.z = a.z*s3.z + h3.z;
    o.w = a.w*s3.w + h3.w;
    *(float4*)(out + (size_t)i*4) = o;
}

// ---------------- launch ----------------
extern "C" void kernel_launch(void* const* d_in, const int* in_sizes, int n_in,
                              void* d_out, int out_size) {
    const float* x   = (const float*)d_in[0];
    const int*   ei  = (const int*)  d_in[1];
    const float* Wc  = (const float*)d_in[2];
    const float* bc  = (const float*)d_in[3];
    const float* ipw = (const float*)d_in[4];
    const float* ipb = (const float*)d_in[5];
    const float* opw = (const float*)d_in[6];
    const float* opb = (const float*)d_in[7];
    const float* gn1 = (const float*)d_in[8];
    const float* bn1 = (const float*)d_in[9];
    const float* gn2 = (const float*)d_in[10];
    const float* bn2 = (const float*)d_in[11];
    const float* gn3 = (const float*)d_in[12];
    const float* bn3 = (const float*)d_in[13];
    const float* Wm1 = (const float*)d_in[14];
    const float* bm1 = (const float*)d_in[15];
    const float* Wm2 = (const float*)d_in[16];
    const float* bm2 = (const float*)d_in[17];
    const int* src = ei;
    const int* dst = ei + EE;

    void *p_hattn, *p_comb, *p_out2, *p_obufs, *p_combs, *p_hiddens, *p_opws, *p_Wm1s, *p_Wm2s;
    cudaGetSymbolAddress(&p_hattn,  g_hattn);
    cudaGetSymbolAddress(&p_comb,   g_comb);
    cudaGetSymbolAddress(&p_out2,   g_out2);
    cudaGetSymbolAddress(&p_obufs,  g_obufs);
    cudaGetSymbolAddress(&p_combs,  g_combs);
    cudaGetSymbolAddress(&p_hiddens,g_hiddens);
    cudaGetSymbolAddress(&p_opws,   g_opws);
    cudaGetSymbolAddress(&p_Wm1s,   g_Wm1s);
    cudaGetSymbolAddress(&p_Wm2s,   g_Wm2s);

    cudaFuncSetAttribute(k_fattn, cudaFuncAttributeMaxDynamicSharedMemorySize, FA_SMEM);
    cudaFuncSetAttribute(k_mg_lqkv, cudaFuncAttributeMaxDynamicSharedMemorySize, MG_SMEM);
    cudaFuncSetAttribute(k_mgemm<1,1>,  cudaFuncAttributeMaxDynamicSharedMemorySize, MG_SMEM);
    cudaFuncSetAttribute(k_mgemm<2,-1>, cudaFuncAttributeMaxDynamicSharedMemorySize, MG_SMEM);
    cudaFuncSetAttribute(k_mgemm<1,2>,  cudaFuncAttributeMaxDynamicSharedMemorySize, MG_SMEM);

    k_zero<<<NT/256, 256>>>();
    k_deg<<<EE/256, 256>>>(dst);
    k_scan<<<1, 1024>>>();
    k_fill<<<EE/256, 256>>>(src, dst);

    k_prep<<<16960, 256>>>(x, Wc, ipw, opw, Wm1, Wm2);
    k_agg<<<NT, 128>>>(x);

    // merged local + QKV
    k_mg_lqkv<<<dim3(NT/128, 4), 256, MG_SMEM>>>(ipb, bc, x);

    k_fattn<<<BB*HH, 256, FA_SMEM>>>();

    // out_proj: hattn = obufs@opws^T + opb + x  (+stats which=1)
    k_mgemm<1,1><<<dim3(NT/128, 1), 256, MG_SMEM>>>(
        (const __nv_bfloat16*)p_obufs, (const __nv_bfloat16*)p_opws, opb, x, (float*)p_hattn, 384, 128);

    k_fin12<<<1, 256>>>(gn1, bn1, gn2, bn2);
    k_combine<<<NT*CC/4/256, 256>>>();

    // mlp1
    k_mgemm<2,-1><<<dim3(NT/128, 2), 256, MG_SMEM>>>(
        (const __nv_bfloat16*)p_combs, (const __nv_bfloat16*)p_Wm1s, bm1, nullptr, nullptr, 384, 256);

    // mlp2 (+stats which=2)
    k_mgemm<1,2><<<dim3(NT/128, 1), 256, MG_SMEM>>>(
        (const __nv_bfloat16*)p_hiddens, (const __nv_bfloat16*)p_Wm2s, bm2, (const float*)p_comb, (float*)p_out2, 768, 128);

    k_fin3<<<1, 128>>>(gn3, bn3);
    k_final<<<NT*CC/4/256, 256>>>((float*)d_out);
}

// round 7
// speedup vs baseline: 1.2799x; 1.2799x over previous
#include <cuda_runtime.h>
#include <cuda_bf16.h>
#include <math.h>
#include <stdint.h>

#define NT  32768
#define CC  128
#define BB  64
#define NNODE 512
#define HH  4
#define DHD 32
#define EE  524288

// ---------------- scratch ----------------
__device__ int   g_deg[NT];
__device__ int   g_off[NT+1];
__device__ int   g_cur[NT];
__device__ int   g_nbr[EE];
__device__ float g_hlocal[NT*CC];
__device__ float g_hattn[NT*CC];
__device__ float g_comb[NT*CC];
__device__ float g_out2[NT*CC];
__device__ float g_sums[3*2*CC];
__device__ float g_scale[3*CC];
__device__ float g_shift[3*CC];

__device__ __nv_bfloat16 g_xs[NT*384];       // [hi|lo|hi]
__device__ __nv_bfloat16 g_aggs[NT*384];
__device__ __nv_bfloat16 g_obufs[NT*384];
__device__ __nv_bfloat16 g_combs[NT*384];
__device__ __nv_bfloat16 g_hiddens[NT*768];
__device__ __nv_bfloat16 g_Wcs[128*384];     // [hi|hi|lo]
__device__ __nv_bfloat16 g_ipws[384*384];
__device__ __nv_bfloat16 g_opws[128*384];
__device__ __nv_bfloat16 g_Wm1s[256*384];
__device__ __nv_bfloat16 g_Wm2s[128*768];
__device__ __nv_bfloat16 g_qs[BB*HH*NNODE*64];
__device__ __nv_bfloat16 g_ks[BB*HH*NNODE*64];
__device__ __nv_bfloat16 g_vs[BB*HH*NNODE*64];

// ---------------- helpers ----------------
__device__ __forceinline__ uint32_t smem_u32(const void* p) {
    uint32_t a;
    asm("{ .reg .u64 t; cvta.to.shared.u64 t, %1; cvt.u32.u64 %0, t; }" : "=r"(a) : "l"(p));
    return a;
}
__device__ __forceinline__ uint32_t pack_bf2(__nv_bfloat16 a, __nv_bfloat16 b) {
    return (uint32_t)__bfloat16_as_ushort(a) | ((uint32_t)__bfloat16_as_ushort(b) << 16);
}
__device__ __forceinline__ void split_bf(float v, __nv_bfloat16& hi, __nv_bfloat16& lo) {
    hi = __float2bfloat16(v);
    lo = __float2bfloat16(v - __bfloat162float(hi));
}
__device__ __forceinline__ void ldmx4(uint32_t* r, uint32_t addr) {
    asm volatile("ldmatrix.sync.aligned.m8n8.x4.shared.b16 {%0,%1,%2,%3}, [%4];"
        : "=r"(r[0]), "=r"(r[1]), "=r"(r[2]), "=r"(r[3]) : "r"(addr));
}
__device__ __forceinline__ void mma_bf(float* c, const uint32_t* a, uint32_t b0, uint32_t b1) {
    asm volatile("mma.sync.aligned.m16n8k16.row.col.f32.bf16.bf16.f32 "
        "{%0,%1,%2,%3}, {%4,%5,%6,%7}, {%8,%9}, {%0,%1,%2,%3};"
        : "+f"(c[0]), "+f"(c[1]), "+f"(c[2]), "+f"(c[3])
        : "r"(a[0]), "r"(a[1]), "r"(a[2]), "r"(a[3]), "r"(b0), "r"(b1));
}
__device__ __forceinline__ void store_a128(__nv_bfloat16* base, int r, int c, float v) {
    __nv_bfloat16 hi, lo; split_bf(v, hi, lo);
    __nv_bfloat16* o = base + (size_t)r * 384;
    o[c] = hi; o[128 + c] = lo; o[256 + c] = hi;
}
__device__ __forceinline__ void store_w(__nv_bfloat16* base, int r, int c, int K, float v) {
    __nv_bfloat16 hi, lo; split_bf(v, hi, lo);
    __nv_bfloat16* o = base + (size_t)(3*r) * K;
    o[c] = hi; o[K + c] = hi; o[2*K + c] = lo;
}

// ---------------- CSR build ----------------
__global__ void k_zero() {
    int i = blockIdx.x * blockDim.x + threadIdx.x;
    if (i < NT) g_deg[i] = 0;
    if (i < 3*2*CC) g_sums[i] = 0.f;
}
__global__ void k_deg(const int* __restrict__ dst) {
    int i = blockIdx.x * blockDim.x + threadIdx.x;
    if (i < EE) atomicAdd(&g_deg[dst[i]], 1);
}
__global__ void k_scan() {
    __shared__ int ssum[1024];
    int t = threadIdx.x;
    int base = t * 32;
    int s = 0;
    #pragma unroll
    for (int i = 0; i < 32; i++) s += g_deg[base + i];
    ssum[t] = s;
    __syncthreads();
    for (int off = 1; off < 1024; off <<= 1) {
        int tmp = (t >= off) ? ssum[t - off] : 0;
        __syncthreads();
        ssum[t] += tmp;
        __syncthreads();
    }
    int run = ssum[t] - s;
    #pragma unroll
    for (int i = 0; i < 32; i++) {
        g_off[base + i] = run;
        g_cur[base + i] = run;
        run += g_deg[base + i];
    }
    if (t == 1023) g_off[NT] = run;
}
__global__ void k_fill(const int* __restrict__ src, const int* __restrict__ dst) {
    int i = blockIdx.x * blockDim.x + threadIdx.x;
    if (i < EE) {
        int p = atomicAdd(&g_cur[dst[i]], 1);
        g_nbr[p] = src[i];
    }
}

// ---------------- one prep kernel: all splits ----------------
__global__ void k_prep(const float* __restrict__ x, const float* __restrict__ Wc,
                       const float* __restrict__ ipw, const float* __restrict__ opw,
                       const float* __restrict__ Wm1, const float* __restrict__ Wm2) {
    int i = blockIdx.x * 256 + threadIdx.x;
    if (i < 4194304) { store_a128(g_xs, i >> 7, i & 127, x[i]); return; }
    i -= 4194304;
    if (i < 16384) { store_w(g_Wcs, i >> 7, i & 127, 128, Wc[i]); return; }
    i -= 16384;
    if (i < 49152) { store_w(g_ipws, i >> 7, i & 127, 128, ipw[i]); return; }
    i -= 49152;
    if (i < 16384) { store_w(g_opws, i >> 7, i & 127, 128, opw[i]); return; }
    i -= 16384;
    if (i < 32768) { store_w(g_Wm1s, i >> 7, i & 127, 128, Wm1[i]); return; }
    i -= 32768;
    store_w(g_Wm2s, i >> 8, i & 255, 256, Wm2[i]);
}

// ---------------- mean aggregation ----------------
__global__ void k_agg(const float* __restrict__ x) {
    __shared__ int snbr[128];
    int n = blockIdx.x, c = threadIdx.x;
    int s0 = g_off[n], s1 = g_off[n+1];
    float acc = 0.f;
    for (int j0 = s0; j0 < s1; j0 += 128) {
        int m = min(128, s1 - j0);
        __syncthreads();
        if (c < m) snbr[c] = g_nbr[j0 + c];
        __syncthreads();
        for (int jj = 0; jj < m; jj++) acc += x[snbr[jj]*CC + c];
    }
    float d = (float)(s1 - s0);
    store_a128(g_aggs, n, c, acc / fmaxf(d, 1.f));
}

// ---------------- GEMM mainloop ----------------
#define MG_SMEM (2*32768)

__device__ __forceinline__ void mg_mainloop(
    const __nv_bfloat16* __restrict__ Ap, const __nv_bfloat16* __restrict__ Wp,
    int Kp, char* smem, uint32_t sbase, int t, int lane, int mrow, int ncol,
    float acc[4][4][4])
{
    const int nch = Kp >> 6;
    auto load_chunk = [&](int ck, int buf) {
        int kc = ck * 64;
        #pragma unroll
        for (int i = 0; i < 8; i++) {
            int u = t + 256*i;
            int row_all = u >> 3, seg = u & 7;
            int isB = row_all >> 7;
            int row = row_all & 127;
            const __nv_bfloat16* src = (isB ? Wp : Ap) + (size_t)row * Kp + kc + seg*8;
            uint32_t dst = sbase + buf*32768 + isB*16384 + row*128 + ((seg ^ (row & 7)) * 16);
            asm volatile("cp.async.cg.shared.global [%0], [%1], 16;" :: "r"(dst), "l"(src));
        }
        asm volatile("cp.async.commit_group;" ::: "memory");
    };
    load_chunk(0, 0);
    for (int ck = 0; ck < nch; ck++) {
        if (ck + 1 < nch) {
            load_chunk(ck + 1, (ck + 1) & 1);
            asm volatile("cp.async.wait_group 1;" ::: "memory");
        } else {
            asm volatile("cp.async.wait_group 0;" ::: "memory");
        }
        __syncthreads();
        uint32_t Ab = sbase + (ck & 1)*32768;
        uint32_t Bb = Ab + 16384;
        #pragma unroll
        for (int s = 0; s < 4; s++) {
            int segsw = ((s*2 + (lane >> 4)) ^ (lane & 7)) * 16;
            uint32_t af[4][4];
            #pragma unroll
            for (int mt = 0; mt < 4; mt++)
                ldmx4(af[mt], Ab + (mrow + mt*16 + (lane & 15))*128 + segsw);
            uint32_t bf[4][2];
            #pragma unroll
            for (int half = 0; half < 2; half++) {
                uint32_t r4[4];
                ldmx4(r4, Bb + (ncol + half*16 + (lane & 15))*128 + segsw);
                bf[half*2+0][0] = r4[0]; bf[half*2+0][1] = r4[2];
                bf[half*2+1][0] = r4[1]; bf[half*2+1][1] = r4[3];
            }
            #pragma unroll
            for (int mt = 0; mt < 4; mt++)
                #pragma unroll
                for (int nt = 0; nt < 4; nt++)
                    mma_bf(acc[mt][nt], af[mt], bf[nt][0], bf[nt][1]);
        }
        __syncthreads();
    }
}

__device__ __forceinline__ void mg_stats_flush(char* smem, int t, int lane, int ncol,
                                               const float* csum, const float* csq, int which) {
    float* ssum = (float*)smem;
    float* ssq  = ssum + 128;
    if (t < 256) { ((float*)smem)[t] = 0.f; }
    __syncthreads();
    #pragma unroll
    for (int nt = 0; nt < 4; nt++) {
        int c0 = ncol + nt*8 + 2*(lane & 3);
        atomicAdd(&ssum[c0],   csum[nt*2+0]);
        atomicAdd(&ssum[c0+1], csum[nt*2+1]);
        atomicAdd(&ssq[c0],    csq[nt*2+0]);
        atomicAdd(&ssq[c0+1],  csq[nt*2+1]);
    }
    __syncthreads();
    if (t < 128) {
        atomicAdd(&g_sums[which*256 + t],       ssum[t]);
        atomicAdd(&g_sums[which*256 + 128 + t], ssq[t]);
    }
}

// EPI: 1 = +bias+resid -> fp32 out (+stats WHICH>=0) ; 2 = relu -> hiddens ; 3 = QKV bf16 split scatter
template<int EPI, int WHICH>
__global__ __launch_bounds__(256) void k_mgemm(
    const __nv_bfloat16* __restrict__ A, const __nv_bfloat16* __restrict__ W,
    const float* __restrict__ bias, const float* __restrict__ resid,
    float* __restrict__ out, int Kp, int Nout)
{
    extern __shared__ char smem[];
    const int t = threadIdx.x, lane = t & 31, w = t >> 5;
    const int bm = blockIdx.x, bn = blockIdx.y;
    const uint32_t sbase = smem_u32(smem);
    const int mrow = (w >> 2) * 64;
    const int ncol = (w & 3) * 32;
    const __nv_bfloat16* Ap = A + (size_t)bm * 128 * Kp;
    const __nv_bfloat16* Wp = W + (size_t)bn * 128 * Kp;

    float acc[4][4][4];
    #pragma unroll
    for (int a = 0; a < 4; a++)
        #pragma unroll
        for (int b = 0; b < 4; b++)
            #pragma unroll
            for (int c = 0; c < 4; c++) acc[a][b][c] = 0.f;

    mg_mainloop(Ap, Wp, Kp, smem, sbase, t, lane, mrow, ncol, acc);

    float csum[8] = {}, csq[8] = {};
    #pragma unroll
    for (int mt = 0; mt < 4; mt++) {
        int m0 = bm*128 + mrow + mt*16 + (lane >> 2);
        #pragma unroll
        for (int nt = 0; nt < 4; nt++) {
            int nl = ncol + nt*8 + 2*(lane & 3);
            int ng = bn*128 + nl;
            float bv0 = bias[ng], bv1 = bias[ng+1];
            #pragma unroll
            for (int hh = 0; hh < 2; hh++) {
                int m = m0 + hh*8;
                float v0 = acc[mt][nt][hh*2+0] + bv0;
                float v1 = acc[mt][nt][hh*2+1] + bv1;
                if (EPI == 3) {
                    int h = nl >> 5, d = nl & 31;
                    __nv_bfloat16* dp = (bn == 0) ? g_qs : (bn == 1) ? g_ks : g_vs;
                    int bh = (m >> 9)*HH + h;
                    __nv_bfloat16 h0, l0, h1, l1;
                    split_bf(v0, h0, l0); split_bf(v1, h1, l1);
                    __nv_bfloat16* dst = dp + ((size_t)bh*NNODE + (m & 511))*64 + d;
                    *(uint32_t*)(dst)      = pack_bf2(h0, h1);
                    *(uint32_t*)(dst + 32) = pack_bf2(l0, l1);
                } else if (EPI == 2) {
                    v0 = fmaxf(v0, 0.f); v1 = fmaxf(v1, 0.f);
                    __nv_bfloat16 h0, l0, h1, l1;
                    split_bf(v0, h0, l0); split_bf(v1, h1, l1);
                    __nv_bfloat16* dst = g_hiddens + (size_t)m*768 + ng;
                    *(uint32_t*)(dst)       = pack_bf2(h0, h1);
                    *(uint32_t*)(dst + 256) = pack_bf2(l0, l1);
                    *(uint32_t*)(dst + 512) = pack_bf2(h0, h1);
                } else {
                    const float2 rv = *(const float2*)(resid + (size_t)m*Nout + ng);
                    v0 += rv.x; v1 += rv.y;
                    *(float2*)(out + (size_t)m*Nout + ng) = make_float2(v0, v1);
                    if (WHICH >= 0) {
                        csum[nt*2+0] += v0; csq[nt*2+0] += v0*v0;
                        csum[nt*2+1] += v1; csq[nt*2+1] += v1*v1;
                    }
                }
            }
        }
    }
    if (EPI == 1 && WHICH >= 0) {
        __syncthreads();
        mg_stats_flush(smem, t, lane, ncol, csum, csq, WHICH);
    }
}

// ---------------- flash attention ----------------
#define FA_SMEM (3*65536)
__global__ __launch_bounds__(256, 1) void k_fattn() {
    extern __shared__ char sm2[];
    const uint32_t sb = smem_u32(sm2);
    const uint32_t Qb = sb, Kb = sb + 65536, Vb = sb + 131072;
    const int bh = blockIdx.x, t = threadIdx.x, lane = t & 31, w = t >> 5;
    const __nv_bfloat16* qg = g_qs + (size_t)bh * NNODE * 64;
    const __nv_bfloat16* kg = g_ks + (size_t)bh * NNODE * 64;
    const __nv_bfloat16* vg = g_vs + (size_t)bh * NNODE * 64;

    for (int i = t; i < 4096; i += 256) {
        int r = i >> 3, s = i & 7;
        uint32_t off = (uint32_t)(r*128 + ((s ^ (r & 7)) * 16));
        *(float4*)(sm2 + off)          = *(const float4*)(qg + r*64 + s*8);
        *(float4*)(sm2 + 65536 + off)  = *(const float4*)(kg + r*64 + s*8);
    }
    for (int i = t; i < 4096; i += 256) {
        int j = i & 511, s = i >> 9;
        float4 v4 = *(const float4*)(vg + j*64 + s*8);
        const __nv_bfloat16* pv = (const __nv_bfloat16*)&v4;
        #pragma unroll
        for (int k = 0; k < 8; k++) {
            int d = s*8 + k;
            *(__nv_bfloat16*)(sm2 + 131072 + d*1024 + (((j >> 3) ^ (d & 7)) * 16) + (j & 7)*2) = pv[k];
        }
    }
    __syncthreads();

    const int q0 = w * 64;
    uint32_t aqh[4][2][4];
    #pragma unroll
    for (int mt = 0; mt < 4; mt++)
        #pragma unroll
        for (int kc = 0; kc < 2; kc++) {
            int row = q0 + mt*16 + (lane & 15);
            ldmx4(aqh[mt][kc], Qb + row*128 + (((kc*2 + (lane >> 4)) ^ (row & 7)) * 16));
        }

    float of[4][4][4];
    #pragma unroll
    for (int a = 0; a < 4; a++)
        #pragma unroll
        for (int b = 0; b < 4; b++)
            #pragma unroll
            for (int c = 0; c < 4; c++) of[a][b][c] = 0.f;
    float mrow[4][2], lrow[4][2];
    #pragma unroll
    for (int a = 0; a < 4; a++) { mrow[a][0] = -1e30f; mrow[a][1] = -1e30f; lrow[a][0] = 0.f; lrow[a][1] = 0.f; }

    const float sc = 0.17677669529663687f;

    for (int jb = 0; jb < 32; jb++) {
        const int j0 = jb * 16;
        uint32_t bk[4][2][2];
        #pragma unroll
        for (int kc = 0; kc < 4; kc++) {
            int row = j0 + (lane & 15);
            uint32_t r4[4];
            ldmx4(r4, Kb + row*128 + (((kc*2 + (lane >> 4)) ^ (row & 7)) * 16));
            bk[kc][0][0] = r4[0]; bk[kc][0][1] = r4[2];
            bk[kc][1][0] = r4[1]; bk[kc][1][1] = r4[3];
        }
        float c[4][2][4];
        #pragma unroll
        for (int a = 0; a < 4; a++)
            #pragma unroll
            for (int b = 0; b < 2; b++)
                #pragma unroll
                for (int e = 0; e < 4; e++) c[a][b][e] = 0.f;
        #pragma unroll
        for (int mt = 0; mt < 4; mt++) {
            uint32_t aql[2][4];
            #pragma unroll
            for (int kc = 0; kc < 2; kc++) {
                int row = q0 + mt*16 + (lane & 15);
                ldmx4(aql[kc], Qb + row*128 + ((((kc + 2)*2 + (lane >> 4)) ^ (row & 7)) * 16));
            }
            #pragma unroll
            for (int nt = 0; nt < 2; nt++) {
                mma_bf(c[mt][nt], aqh[mt][0], bk[0][nt][0], bk[0][nt][1]);
                mma_bf(c[mt][nt], aqh[mt][1], bk[1][nt][0], bk[1][nt][1]);
                mma_bf(c[mt][nt], aql[0],     bk[0][nt][0], bk[0][nt][1]);
                mma_bf(c[mt][nt], aql[1],     bk[1][nt][0], bk[1][nt][1]);
                mma_bf(c[mt][nt], aqh[mt][0], bk[2][nt][0], bk[2][nt][1]);
                mma_bf(c[mt][nt], aqh[mt][1], bk[3][nt][0], bk[3][nt][1]);
            }
        }
        #pragma unroll
        for (int mt = 0; mt < 4; mt++)
            #pragma unroll
            for (int h = 0; h < 2; h++) {
                float s0 = c[mt][0][h*2]*sc, s1 = c[mt][0][h*2+1]*sc;
                float s2 = c[mt][1][h*2]*sc, s3 = c[mt][1][h*2+1]*sc;
                float mx = fmaxf(fmaxf(s0, s1), fmaxf(s2, s3));
                mx = fmaxf(mx, __shfl_xor_sync(0xffffffffu, mx, 1));
                mx = fmaxf(mx, __shfl_xor_sync(0xffffffffu, mx, 2));
                float mnew = fmaxf(mrow[mt][h], mx);
                float fac = __expf(mrow[mt][h] - mnew);
                mrow[mt][h] = mnew;
                float p0 = __expf(s0 - mnew), p1 = __expf(s1 - mnew);
                float p2 = __expf(s2 - mnew), p3 = __expf(s3 - mnew);
                c[mt][0][h*2] = p0; c[mt][0][h*2+1] = p1;
                c[mt][1][h*2] = p2; c[mt][1][h*2+1] = p3;
                float rs = p0 + p1 + p2 + p3;
                rs += __shfl_xor_sync(0xffffffffu, rs, 1);
                rs += __shfl_xor_sync(0xffffffffu, rs, 2);
                lrow[mt][h] = lrow[mt][h]*fac + rs;
                #pragma unroll
                for (int nt = 0; nt < 4; nt++) { of[mt][nt][h*2] *= fac; of[mt][nt][h*2+1] *= fac; }
            }
        uint32_t pah[4][4], pal[4][4];
        #pragma unroll
        for (int mt = 0; mt < 4; mt++) {
            __nv_bfloat16 hx, lx, hy, ly;
            split_bf(c[mt][0][0], hx, lx); split_bf(c[mt][0][1], hy, ly);
            pah[mt][0] = pack_bf2(hx, hy); pal[mt][0] = pack_bf2(lx, ly);
            split_bf(c[mt][0][2], hx, lx); split_bf(c[mt][0][3], hy, ly);
            pah[mt][1] = pack_bf2(hx, hy); pal[mt][1] = pack_bf2(lx, ly);
            split_bf(c[mt][1][0], hx, lx); split_bf(c[mt][1][1], hy, ly);
            pah[mt][2] = pack_bf2(hx, hy); pal[mt][2] = pack_bf2(lx, ly);
            split_bf(c[mt][1][2], hx, lx); split_bf(c[mt][1][3], hy, ly);
            pah[mt][3] = pack_bf2(hx, hy); pal[mt][3] = pack_bf2(lx, ly);
        }
        uint32_t bvh[4][2], bvl[4][2];
        #pragma unroll
        for (int dh = 0; dh < 2; dh++) {
            int rowh = dh*16 + (lane & 15);
            uint32_t r4[4];
            ldmx4(r4, Vb + rowh*1024 + (((((j0 >> 3) + (lane >> 4)) ^ (rowh & 7))) * 16));
            bvh[dh*2+0][0] = r4[0]; bvh[dh*2+0][1] = r4[2];
            bvh[dh*2+1][0] = r4[1]; bvh[dh*2+1][1] = r4[3];
            int rowl = rowh + 32;
            ldmx4(r4, Vb + rowl*1024 + (((((j0 >> 3) + (lane >> 4)) ^ (rowl & 7))) * 16));
            bvl[dh*2+0][0] = r4[0]; bvl[dh*2+0][1] = r4[2];
            bvl[dh*2+1][0] = r4[1]; bvl[dh*2+1][1] = r4[3];
        }
        #pragma unroll
        for (int mt = 0; mt < 4; mt++)
            #pragma unroll
            for (int nt = 0; nt < 4; nt++) {
                mma_bf(of[mt][nt], pah[mt], bvh[nt][0], bvh[nt][1]);
                mma_bf(of[mt][nt], pal[mt], bvh[nt][0], bvh[nt][1]);
                mma_bf(of[mt][nt], pah[mt], bvl[nt][0], bvl[nt][1]);
            }
    }

    const int b = bh >> 2, h4 = bh & 3;
    #pragma unroll
    for (int mt = 0; mt < 4; mt++)
        #pragma unroll
        for (int h = 0; h < 2; h++) {
            float inv = 1.f / lrow[mt][h];
            int q = q0 + mt*16 + (lane >> 2) + h*8;
            __nv_bfloat16* base = g_obufs + ((size_t)(b*NNODE + q))*384 + h4*DHD;
            #pragma unroll
            for (int nt = 0; nt < 4; nt++) {
                int d = nt*8 + 2*(lane & 3);
                float v0 = of[mt][nt][h*2]   * inv;
                float v1 = of[mt][nt][h*2+1] * inv;
                __nv_bfloat16 h0, l0, h1, l1;
                split_bf(v0, h0, l0); split_bf(v1, h1, l1);
                *(uint32_t*)(base + d)       = pack_bf2(h0, h1);
                *(uint32_t*)(base + 128 + d) = pack_bf2(l0, l1);
                *(uint32_t*)(base + 256 + d) = pack_bf2(h0, h1);
            }
        }
}

// ---------------- finalize / combine / final ----------------
__global__ void k_fin12(const float* __restrict__ gn1, const float* __restrict__ bn1,
                        const float* __restrict__ gn2, const float* __restrict__ bn2) {
    int t = threadIdx.x;
    int which = t >> 7, c = t & 127;
    const float* g = which ? gn2 : gn1;
    const float* b = which ? bn2 : bn1;
    float s  = g_sums[which*256 + c];
    float s2 = g_sums[which*256 + 128 + c];
    float m  = s / (float)NT;
    float v  = s2 / (float)NT - m*m;
    float scale = g[c] * rsqrtf(v + 1e-5f);
    g_scale[which*128 + c] = scale;
    g_shift[which*128 + c] = b[c] - m*scale;
}
__global__ void k_fin3(const float* __restrict__ g, const float* __restrict__ b) {
    int c = threadIdx.x;
    float s  = g_sums[2*256 + c];
    float s2 = g_sums[2*256 + 128 + c];
    float m  = s / (float)NT;
    float v  = s2 / (float)NT - m*m;
    float scale = g[c] * rsqrtf(v + 1e-5f);
    g_scale[2*128 + c] = scale;
    g_shift[2*128 + c] = b[c] - m*scale;
}

__global__ void k_combine() {
    int i = blockIdx.x * blockDim.x + threadIdx.x;
    int c = (i*4) & 127;
    int r = (i*4) >> 7;
    float4 a  = *(const float4*)(g_hlocal + (size_t)i*4);
    float4 bb = *(const float4*)(g_hattn + (size_t)i*4);
    float4 s1 = *(const float4*)(g_scale + c);
    float4 h1 = *(const float4*)(g_shift + c);
    float4 s2 = *(const float4*)(g_scale + 128 + c);
    float4 h2 = *(const float4*)(g_shift + 128 + c);
    float4 o;
    o.x = a.x*s1.x + h1.x + bb.x*s2.x + h2.x;
    o.y = a.y*s1.y + h1.y + bb.y*s2.y + h2.y;
    o.z = a.z*s1.z + h1.z + bb.z*s2.z + h2.z;
    o.w = a.w*s1.w + h1.w + bb.w*s2.w + h2.w;
    *(float4*)(g_comb + (size_t)i*4) = o;
    float vv[4] = {o.x, o.y, o.z, o.w};
    __nv_bfloat16 hi[4], lo[4];
    #pragma unroll
    for (int k = 0; k < 4; k++) split_bf(vv[k], hi[k], lo[k]);
    __nv_bfloat16* dst = g_combs + (size_t)r*384 + c;
    *(uint32_t*)(dst)       = pack_bf2(hi[0], hi[1]);
    *(uint32_t*)(dst + 2)   = pack_bf2(hi[2], hi[3]);
    *(uint32_t*)(dst + 128) = pack_bf2(lo[0], lo[1]);
    *(uint32_t*)(dst + 130) = pack_bf2(lo[2], lo[3]);
    *(uint32_t*)(dst + 256) = pack_bf2(hi[0], hi[1]);
    *(uint32_t*)(dst + 258) = pack_bf2(hi[2], hi[3]);
}

__global__ void k_final(float* __restrict__ out) {
    int i = blockIdx.x * blockDim.x + threadIdx.x;
    int c = (i*4) & 127;
    float4 a  = *(const float4*)(g_out2 + (size_t)i*4);
    float4 s3 = *(const float4*)(g_scale + 256 + c);
    float4 h3 = *(const float4*)(g_shift + 256 + c);
    float4 o;
    o.x = a.x*s3.x + h3.x;
    o.y = a.y*s3.y + h3.y;
    o.z = a.z*s3.z + h3.z;
    o.w = a.w*s3.w + h3.w;
    *(float4*)(out + (size_t)i*4) = o;
}

// ---------------- launch ----------------
extern "C" void kernel_launch(void* const* d_in, const int* in_sizes, int n_in,
                              void* d_out, int out_size) {
    const float* x   = (const float*)d_in[0];
    const int*   ei  = (const int*)  d_in[1];
    const float* Wc  = (const float*)d_in[2];
    const float* bc  = (const float*)d_in[3];
    const float* ipw = (const float*)d_in[4];
    const float* ipb = (const float*)d_in[5];
    const float* opw = (const float*)d_in[6];
    const float* opb = (const float*)d_in[7];
    const float* gn1 = (const float*)d_in[8];
    const float* bn1 = (const float*)d_in[9];
    const float* gn2 = (const float*)d_in[10];
    const float* bn2 = (const float*)d_in[11];
    const float* gn3 = (const float*)d_in[12];
    const float* bn3 = (const float*)d_in[13];
    const float* Wm1 = (const float*)d_in[14];
    const float* bm1 = (const float*)d_in[15];
    const float* Wm2 = (const float*)d_in[16];
    const float* bm2 = (const float*)d_in[17];
    const int* src = ei;
    const int* dst = ei + EE;

    void *p_hlocal, *p_hattn, *p_comb, *p_out2, *p_xs, *p_aggs, *p_obufs, *p_combs, *p_hiddens;
    void *p_Wcs, *p_ipws, *p_opws, *p_Wm1s, *p_Wm2s;
    cudaGetSymbolAddress(&p_hlocal, g_hlocal);
    cudaGetSymbolAddress(&p_hattn,  g_hattn);
    cudaGetSymbolAddress(&p_comb,   g_comb);
    cudaGetSymbolAddress(&p_out2,   g_out2);
    cudaGetSymbolAddress(&p_xs,     g_xs);
    cudaGetSymbolAddress(&p_aggs,   g_aggs);
    cudaGetSymbolAddress(&p_obufs,  g_obufs);
    cudaGetSymbolAddress(&p_combs,  g_combs);
    cudaGetSymbolAddress(&p_hiddens,g_hiddens);
    cudaGetSymbolAddress(&p_Wcs,    g_Wcs);
    cudaGetSymbolAddress(&p_ipws,   g_ipws);
    cudaGetSymbolAddress(&p_opws,   g_opws);
    cudaGetSymbolAddress(&p_Wm1s,   g_Wm1s);
    cudaGetSymbolAddress(&p_Wm2s,   g_Wm2s);

    cudaFuncSetAttribute(k_fattn, cudaFuncAttributeMaxDynamicSharedMemorySize, FA_SMEM);
    cudaFuncSetAttribute(k_mgemm<3,-1>, cudaFuncAttributeMaxDynamicSharedMemorySize, MG_SMEM);
    cudaFuncSetAttribute(k_mgemm<1,0>,  cudaFuncAttributeMaxDynamicSharedMemorySize, MG_SMEM);
    cudaFuncSetAttribute(k_mgemm<1,1>,  cudaFuncAttributeMaxDynamicSharedMemorySize, MG_SMEM);
    cudaFuncSetAttribute(k_mgemm<2,-1>, cudaFuncAttributeMaxDynamicSharedMemorySize, MG_SMEM);
    cudaFuncSetAttribute(k_mgemm<1,2>,  cudaFuncAttributeMaxDynamicSharedMemorySize, MG_SMEM);

    // static side stream + events (created once; no device memory, deterministic work)
    static cudaStream_t s2 = nullptr;
    static cudaEvent_t e0 = nullptr, e_prep = nullptr, e_loc = nullptr;
    if (s2 == nullptr) {
        cudaStreamCreateWithFlags(&s2, cudaStreamNonBlocking);
        cudaEventCreateWithFlags(&e0,     cudaEventDisableTiming);
        cudaEventCreateWithFlags(&e_prep, cudaEventDisableTiming);
        cudaEventCreateWithFlags(&e_loc,  cudaEventDisableTiming);
    }

    // ---- main stream: zero, then fork ----
    k_zero<<<NT/256, 256>>>();
    cudaEventRecord(e0, 0);
    cudaStreamWaitEvent(s2, e0, 0);

    // ---- side stream (spine B): CSR -> agg -> local GEMM ----
    k_deg<<<EE/256, 256, 0, s2>>>(dst);
    k_scan<<<1, 1024, 0, s2>>>();
    k_fill<<<EE/256, 256, 0, s2>>>(src, dst);
    k_agg<<<NT, 128, 0, s2>>>(x);

    // ---- main stream (spine A): prep -> QKV -> attention -> out_proj ----
    k_prep<<<16960, 256>>>(x, Wc, ipw, opw, Wm1, Wm2);
    cudaEventRecord(e_prep, 0);

    k_mgemm<3,-1><<<dim3(NT/128, 3), 256, MG_SMEM>>>(
        (const __nv_bfloat16*)p_xs, (const __nv_bfloat16*)p_ipws, ipb, nullptr, nullptr, 384, 384);

    k_fattn<<<BB*HH, 256, FA_SMEM>>>();

    k_mgemm<1,1><<<dim3(NT/128, 1), 256, MG_SMEM>>>(
        (const __nv_bfloat16*)p_obufs, (const __nv_bfloat16*)p_opws, opb, x, (float*)p_hattn, 384, 128);

    // ---- side stream: local GEMM (needs g_Wcs from prep + g_aggs) ----
    cudaStreamWaitEvent(s2, e_prep, 0);
    k_mgemm<1,0><<<dim3(NT/128, 1), 256, MG_SMEM, s2>>>(
        (const __nv_bfloat16*)p_aggs, (const __nv_bfloat16*)p_Wcs, bc, x, (float*)p_hlocal, 384, 128);
    cudaEventRecord(e_loc, s2);

    // ---- join, finish on main stream ----
    cudaStreamWaitEvent(0, e_loc, 0);
    k_fin12<<<1, 256>>>(gn1, bn1, gn2, bn2);
    k_combine<<<NT*CC/4/256, 256>>>();

    k_mgemm<2,-1><<<dim3(NT/128, 2), 256, MG_SMEM>>>(
        (const __nv_bfloat16*)p_combs, (const __nv_bfloat16*)p_Wm1s, bm1, nullptr, nullptr, 384, 256);

    k_mgemm<1,2><<<dim3(NT/128, 1), 256, MG_SMEM>>>(
        (const __nv_bfloat16*)p_hiddens, (const __nv_bfloat16*)p_Wm2s, bm2, (const float*)p_comb, (float*)p_out2, 768, 128);

    k_fin3<<<1, 128>>>(gn3, bn3);
    k_final<<<NT*CC/4/256, 256>>>((float*)d_out);
}

// round 8
// speedup vs baseline: 1.3262x; 1.0362x over previous
#include <cuda_runtime.h>
#include <cuda_bf16.h>
#include <math.h>
#include <stdint.h>

#define NT  32768
#define CC  128
#define BB  64
#define NNODE 512
#define HH  4
#define DHD 32
#define EE  524288

// ---------------- scratch ----------------
__device__ int   g_deg[NT];
__device__ int   g_off[NT+1];
__device__ int   g_cur[NT];
__device__ int   g_nbr[EE];
__device__ float g_hlocal[NT*CC];
__device__ float g_hattn[NT*CC];
__device__ float g_comb[NT*CC];
__device__ float g_out2[NT*CC];
__device__ float g_sums[3*2*CC];
__device__ float g_scale[3*CC];
__device__ float g_shift[3*CC];

__device__ __nv_bfloat16 g_aggs[NT*384];     // [hi|lo|hi]
__device__ __nv_bfloat16 g_obufs[NT*384];
__device__ __nv_bfloat16 g_combs[NT*384];
__device__ __nv_bfloat16 g_hiddens[NT*768];
__device__ __nv_bfloat16 g_Wcs[128*384];     // [hi|hi|lo]
__device__ __nv_bfloat16 g_ipws[384*384];
__device__ __nv_bfloat16 g_opws[128*384];
__device__ __nv_bfloat16 g_Wm1s[256*384];
__device__ __nv_bfloat16 g_Wm2s[128*768];
__device__ __nv_bfloat16 g_qs[BB*HH*NNODE*64];
__device__ __nv_bfloat16 g_ks[BB*HH*NNODE*64];
__device__ __nv_bfloat16 g_vs[BB*HH*NNODE*64];

// ---------------- helpers ----------------
__device__ __forceinline__ uint32_t smem_u32(const void* p) {
    uint32_t a;
    asm("{ .reg .u64 t; cvta.to.shared.u64 t, %1; cvt.u32.u64 %0, t; }" : "=r"(a) : "l"(p));
    return a;
}
__device__ __forceinline__ uint32_t pack_bf2(__nv_bfloat16 a, __nv_bfloat16 b) {
    return (uint32_t)__bfloat16_as_ushort(a) | ((uint32_t)__bfloat16_as_ushort(b) << 16);
}
__device__ __forceinline__ void split_bf(float v, __nv_bfloat16& hi, __nv_bfloat16& lo) {
    hi = __float2bfloat16(v);
    lo = __float2bfloat16(v - __bfloat162float(hi));
}
__device__ __forceinline__ void ldmx4(uint32_t* r, uint32_t addr) {
    asm volatile("ldmatrix.sync.aligned.m8n8.x4.shared.b16 {%0,%1,%2,%3}, [%4];"
        : "=r"(r[0]), "=r"(r[1]), "=r"(r[2]), "=r"(r[3]) : "r"(addr));
}
__device__ __forceinline__ void mma_bf(float* c, const uint32_t* a, uint32_t b0, uint32_t b1) {
    asm volatile("mma.sync.aligned.m16n8k16.row.col.f32.bf16.bf16.f32 "
        "{%0,%1,%2,%3}, {%4,%5,%6,%7}, {%8,%9}, {%0,%1,%2,%3};"
        : "+f"(c[0]), "+f"(c[1]), "+f"(c[2]), "+f"(c[3])
        : "r"(a[0]), "r"(a[1]), "r"(a[2]), "r"(a[3]), "r"(b0), "r"(b1));
}
__device__ __forceinline__ void store_a128(__nv_bfloat16* base, int r, int c, float v) {
    __nv_bfloat16 hi, lo; split_bf(v, hi, lo);
    __nv_bfloat16* o = base + (size_t)r * 384;
    o[c] = hi; o[128 + c] = lo; o[256 + c] = hi;
}
__device__ __forceinline__ void store_w(__nv_bfloat16* base, int r, int c, int K, float v) {
    __nv_bfloat16 hi, lo; split_bf(v, hi, lo);
    __nv_bfloat16* o = base + (size_t)(3*r) * K;
    o[c] = hi; o[K + c] = hi; o[2*K + c] = lo;
}

// ---------------- CSR build ----------------
__global__ void k_zero() {
    int i = blockIdx.x * blockDim.x + threadIdx.x;
    if (i < NT) g_deg[i] = 0;
    if (i < 3*2*CC) g_sums[i] = 0.f;
}
__global__ void k_deg(const int* __restrict__ dst) {
    int i = blockIdx.x * blockDim.x + threadIdx.x;
    if (i < EE) atomicAdd(&g_deg[dst[i]], 1);
}
__global__ void k_scan() {
    __shared__ int ssum[1024];
    int t = threadIdx.x;
    int base = t * 32;
    int s = 0;
    #pragma unroll
    for (int i = 0; i < 32; i++) s += g_deg[base + i];
    ssum[t] = s;
    __syncthreads();
    for (int off = 1; off < 1024; off <<= 1) {
        int tmp = (t >= off) ? ssum[t - off] : 0;
        __syncthreads();
        ssum[t] += tmp;
        __syncthreads();
    }
    int run = ssum[t] - s;
    #pragma unroll
    for (int i = 0; i < 32; i++) {
        g_off[base + i] = run;
        g_cur[base + i] = run;
        run += g_deg[base + i];
    }
    if (t == 1023) g_off[NT] = run;
}
__global__ void k_fill(const int* __restrict__ src, const int* __restrict__ dst) {
    int i = blockIdx.x * blockDim.x + threadIdx.x;
    if (i < EE) {
        int p = atomicAdd(&g_cur[dst[i]], 1);
        g_nbr[p] = src[i];
    }
}

// ---------------- weights-only prep (side stream) ----------------
// index space: Wc(16384) | ipw(49152) | opw(16384) | Wm1(32768) | Wm2(32768) = 147456
__global__ void k_prep_w(const float* __restrict__ Wc, const float* __restrict__ ipw,
                         const float* __restrict__ opw, const float* __restrict__ Wm1,
                         const float* __restrict__ Wm2) {
    int i = blockIdx.x * 256 + threadIdx.x;
    if (i < 16384) { store_w(g_Wcs, i >> 7, i & 127, 128, Wc[i]); return; }
    i -= 16384;
    if (i < 49152) { store_w(g_ipws, i >> 7, i & 127, 128, ipw[i]); return; }
    i -= 49152;
    if (i < 16384) { store_w(g_opws, i >> 7, i & 127, 128, opw[i]); return; }
    i -= 16384;
    if (i < 32768) { store_w(g_Wm1s, i >> 7, i & 127, 128, Wm1[i]); return; }
    i -= 32768;
    store_w(g_Wm2s, i >> 8, i & 255, 256, Wm2[i]);
}

// ---------------- mean aggregation ----------------
__global__ void k_agg(const float* __restrict__ x) {
    __shared__ int snbr[128];
    int n = blockIdx.x, c = threadIdx.x;
    int s0 = g_off[n], s1 = g_off[n+1];
    float acc = 0.f;
    for (int j0 = s0; j0 < s1; j0 += 128) {
        int m = min(128, s1 - j0);
        __syncthreads();
        if (c < m) snbr[c] = g_nbr[j0 + c];
        __syncthreads();
        for (int jj = 0; jj < m; jj++) acc += x[snbr[jj]*CC + c];
    }
    float d = (float)(s1 - s0);
    store_a128(g_aggs, n, c, acc / fmaxf(d, 1.f));
}

// ---------------- GEMM mainloop ----------------
#define MG_SMEM (2*32768)

__device__ __forceinline__ void mg_mainloop(
    const __nv_bfloat16* __restrict__ Ap, const __nv_bfloat16* __restrict__ Wp,
    int Kp, char* smem, uint32_t sbase, int t, int lane, int mrow, int ncol,
    float acc[4][4][4])
{
    const int nch = Kp >> 6;
    auto load_chunk = [&](int ck, int buf) {
        int kc = ck * 64;
        #pragma unroll
        for (int i = 0; i < 8; i++) {
            int u = t + 256*i;
            int row_all = u >> 3, seg = u & 7;
            int isB = row_all >> 7;
            int row = row_all & 127;
            const __nv_bfloat16* src = (isB ? Wp : Ap) + (size_t)row * Kp + kc + seg*8;
            uint32_t dst = sbase + buf*32768 + isB*16384 + row*128 + ((seg ^ (row & 7)) * 16);
            asm volatile("cp.async.cg.shared.global [%0], [%1], 16;" :: "r"(dst), "l"(src));
        }
        asm volatile("cp.async.commit_group;" ::: "memory");
    };
    load_chunk(0, 0);
    for (int ck = 0; ck < nch; ck++) {
        if (ck + 1 < nch) {
            load_chunk(ck + 1, (ck + 1) & 1);
            asm volatile("cp.async.wait_group 1;" ::: "memory");
        } else {
            asm volatile("cp.async.wait_group 0;" ::: "memory");
        }
        __syncthreads();
        uint32_t Ab = sbase + (ck & 1)*32768;
        uint32_t Bb = Ab + 16384;
        #pragma unroll
        for (int s = 0; s < 4; s++) {
            int segsw = ((s*2 + (lane >> 4)) ^ (lane & 7)) * 16;
            uint32_t af[4][4];
            #pragma unroll
            for (int mt = 0; mt < 4; mt++)
                ldmx4(af[mt], Ab + (mrow + mt*16 + (lane & 15))*128 + segsw);
            uint32_t bf[4][2];
            #pragma unroll
            for (int half = 0; half < 2; half++) {
                uint32_t r4[4];
                ldmx4(r4, Bb + (ncol + half*16 + (lane & 15))*128 + segsw);
                bf[half*2+0][0] = r4[0]; bf[half*2+0][1] = r4[2];
                bf[half*2+1][0] = r4[1]; bf[half*2+1][1] = r4[3];
            }
            #pragma unroll
            for (int mt = 0; mt < 4; mt++)
                #pragma unroll
                for (int nt = 0; nt < 4; nt++)
                    mma_bf(acc[mt][nt], af[mt], bf[nt][0], bf[nt][1]);
        }
        __syncthreads();
    }
}

__device__ __forceinline__ void mg_stats_flush(char* smem, int t, int lane, int ncol,
                                               const float* csum, const float* csq, int which) {
    float* ssum = (float*)smem;
    float* ssq  = ssum + 128;
    if (t < 256) { ((float*)smem)[t] = 0.f; }
    __syncthreads();
    #pragma unroll
    for (int nt = 0; nt < 4; nt++) {
        int c0 = ncol + nt*8 + 2*(lane & 3);
        atomicAdd(&ssum[c0],   csum[nt*2+0]);
        atomicAdd(&ssum[c0+1], csum[nt*2+1]);
        atomicAdd(&ssq[c0],    csq[nt*2+0]);
        atomicAdd(&ssq[c0+1],  csq[nt*2+1]);
    }
    __syncthreads();
    if (t < 128) {
        atomicAdd(&g_sums[which*256 + t],       ssum[t]);
        atomicAdd(&g_sums[which*256 + 128 + t], ssq[t]);
    }
}

// EPI: 1 = +bias+resid -> fp32 out (+stats WHICH>=0) ; 2 = relu -> hiddens
template<int EPI, int WHICH>
__global__ __launch_bounds__(256, 2) void k_mgemm(
    const __nv_bfloat16* __restrict__ A, const __nv_bfloat16* __restrict__ W,
    const float* __restrict__ bias, const float* __restrict__ resid,
    float* __restrict__ out, int Kp, int Nout)
{
    extern __shared__ char smem[];
    const int t = threadIdx.x, lane = t & 31, w = t >> 5;
    const int bm = blockIdx.x, bn = blockIdx.y;
    const uint32_t sbase = smem_u32(smem);
    const int mrow = (w >> 2) * 64;
    const int ncol = (w & 3) * 32;
    const __nv_bfloat16* Ap = A + (size_t)bm * 128 * Kp;
    const __nv_bfloat16* Wp = W + (size_t)bn * 128 * Kp;

    float acc[4][4][4];
    #pragma unroll
    for (int a = 0; a < 4; a++)
        #pragma unroll
        for (int b = 0; b < 4; b++)
            #pragma unroll
            for (int c = 0; c < 4; c++) acc[a][b][c] = 0.f;

    mg_mainloop(Ap, Wp, Kp, smem, sbase, t, lane, mrow, ncol, acc);

    float csum[8] = {}, csq[8] = {};
    #pragma unroll
    for (int mt = 0; mt < 4; mt++) {
        int m0 = bm*128 + mrow + mt*16 + (lane >> 2);
        #pragma unroll
        for (int nt = 0; nt < 4; nt++) {
            int nl = ncol + nt*8 + 2*(lane & 3);
            int ng = bn*128 + nl;
            float bv0 = bias[ng], bv1 = bias[ng+1];
            #pragma unroll
            for (int hh = 0; hh < 2; hh++) {
                int m = m0 + hh*8;
                float v0 = acc[mt][nt][hh*2+0] + bv0;
                float v1 = acc[mt][nt][hh*2+1] + bv1;
                if (EPI == 2) {
                    v0 = fmaxf(v0, 0.f); v1 = fmaxf(v1, 0.f);
                    __nv_bfloat16 h0, l0, h1, l1;
                    split_bf(v0, h0, l0); split_bf(v1, h1, l1);
                    __nv_bfloat16* dst = g_hiddens + (size_t)m*768 + ng;
                    *(uint32_t*)(dst)       = pack_bf2(h0, h1);
                    *(uint32_t*)(dst + 256) = pack_bf2(l0, l1);
                    *(uint32_t*)(dst + 512) = pack_bf2(h0, h1);
                } else {
                    const float2 rv = *(const float2*)(resid + (size_t)m*Nout + ng);
                    v0 += rv.x; v1 += rv.y;
                    *(float2*)(out + (size_t)m*Nout + ng) = make_float2(v0, v1);
                    if (WHICH >= 0) {
                        csum[nt*2+0] += v0; csq[nt*2+0] += v0*v0;
                        csum[nt*2+1] += v1; csq[nt*2+1] += v1*v1;
                    }
                }
            }
        }
    }
    if (EPI == 1 && WHICH >= 0) {
        __syncthreads();
        mg_stats_flush(smem, t, lane, ncol, csum, csq, WHICH);
    }
}

// ---------------- QKV GEMM with inline x fp32 -> split-bf16 conversion ----------------
// grid (NT/128, 3). A derived from x [128 rows x 128 fp32], split-3 along virtual K=384.
__global__ __launch_bounds__(256, 2) void k_qkv(const float* __restrict__ x,
                                                const float* __restrict__ ipb) {
    extern __shared__ char smem[];
    const int t = threadIdx.x, lane = t & 31, w = t >> 5;
    const int bm = blockIdx.x, bn = blockIdx.y;
    const uint32_t sbase = smem_u32(smem);
    const int mrow = (w >> 2) * 64;
    const int ncol = (w & 3) * 32;
    const float* Xp = x + (size_t)bm * 128 * 128;
    const __nv_bfloat16* Wp = g_ipws + (size_t)bn * 128 * 384;

    float acc[4][4][4];
    #pragma unroll
    for (int a = 0; a < 4; a++)
        #pragma unroll
        for (int b = 0; b < 4; b++)
            #pragma unroll
            for (int c = 0; c < 4; c++) acc[a][b][c] = 0.f;

    auto load_chunk = [&](int ck, int buf) {
        int kc = ck * 64;
        int v = kc >> 7;        // 0,0,1,1,2,2 -> hi,hi,lo,lo,hi,hi
        int c0 = kc & 127;      // source x column base
        // A: manual fp32 load + convert + sts
        #pragma unroll
        for (int i = 0; i < 4; i++) {
            int u = t + 256*i;
            int r = u >> 3, s = u & 7;
            const float* srcx = Xp + (size_t)r*128 + c0 + s*8;
            float4 f0 = *(const float4*)(srcx);
            float4 f1 = *(const float4*)(srcx + 4);
            float vals[8] = {f0.x,f0.y,f0.z,f0.w,f1.x,f1.y,f1.z,f1.w};
            uint32_t pk[4];
            if (v == 1) {
                #pragma unroll
                for (int k2 = 0; k2 < 4; k2++) {
                    __nv_bfloat16 h0 = __float2bfloat16(vals[k2*2]);
                    __nv_bfloat16 h1 = __float2bfloat16(vals[k2*2+1]);
                    __nv_bfloat16 l0 = __float2bfloat16(vals[k2*2]   - __bfloat162float(h0));
                    __nv_bfloat16 l1 = __float2bfloat16(vals[k2*2+1] - __bfloat162float(h1));
                    pk[k2] = pack_bf2(l0, l1);
                }
            } else {
                #pragma unroll
                for (int k2 = 0; k2 < 4; k2++)
                    pk[k2] = pack_bf2(__float2bfloat16(vals[k2*2]), __float2bfloat16(vals[k2*2+1]));
            }
            *(uint4*)(smem + buf*32768 + r*128 + ((s ^ (r & 7)) * 16)) = make_uint4(pk[0],pk[1],pk[2],pk[3]);
        }
        // B: cp.async
        #pragma unroll
        for (int i = 0; i < 4; i++) {
            int u = t + 256*i;
            int r = u >> 3, s = u & 7;
            const __nv_bfloat16* src = Wp + (size_t)r * 384 + kc + s*8;
            uint32_t dst = sbase + buf*32768 + 16384 + r*128 + ((s ^ (r & 7)) * 16);
            asm volatile("cp.async.cg.shared.global [%0], [%1], 16;" :: "r"(dst), "l"(src));
        }
        asm volatile("cp.async.commit_group;" ::: "memory");
    };

    load_chunk(0, 0);
    for (int ck = 0; ck < 6; ck++) {
        if (ck + 1 < 6) {
            load_chunk(ck + 1, (ck + 1) & 1);
            asm volatile("cp.async.wait_group 1;" ::: "memory");
        } else {
            asm volatile("cp.async.wait_group 0;" ::: "memory");
        }
        __syncthreads();
        uint32_t Ab = sbase + (ck & 1)*32768;
        uint32_t Bb = Ab + 16384;
        #pragma unroll
        for (int s = 0; s < 4; s++) {
            int segsw = ((s*2 + (lane >> 4)) ^ (lane & 7)) * 16;
            uint32_t af[4][4];
            #pragma unroll
            for (int mt = 0; mt < 4; mt++)
                ldmx4(af[mt], Ab + (mrow + mt*16 + (lane & 15))*128 + segsw);
            uint32_t bf[4][2];
            #pragma unroll
            for (int half = 0; half < 2; half++) {
                uint32_t r4[4];
                ldmx4(r4, Bb + (ncol + half*16 + (lane & 15))*128 + segsw);
                bf[half*2+0][0] = r4[0]; bf[half*2+0][1] = r4[2];
                bf[half*2+1][0] = r4[1]; bf[half*2+1][1] = r4[3];
            }
            #pragma unroll
            for (int mt = 0; mt < 4; mt++)
                #pragma unroll
                for (int nt = 0; nt < 4; nt++)
                    mma_bf(acc[mt][nt], af[mt], bf[nt][0], bf[nt][1]);
        }
        __syncthreads();
    }

    // epilogue: +bias -> Q/K/V bf16 split scatter
    #pragma unroll
    for (int mt = 0; mt < 4; mt++) {
        int m0 = bm*128 + mrow + mt*16 + (lane >> 2);
        #pragma unroll
        for (int nt = 0; nt < 4; nt++) {
            int nl = ncol + nt*8 + 2*(lane & 3);
            float bv0 = ipb[bn*128 + nl], bv1 = ipb[bn*128 + nl + 1];
            #pragma unroll
            for (int hh = 0; hh < 2; hh++) {
                int m = m0 + hh*8;
                float v0 = acc[mt][nt][hh*2+0] + bv0;
                float v1 = acc[mt][nt][hh*2+1] + bv1;
                int h = nl >> 5, d = nl & 31;
                __nv_bfloat16* dp = (bn == 0) ? g_qs : (bn == 1) ? g_ks : g_vs;
                int bh = (m >> 9)*HH + h;
                __nv_bfloat16 h0, l0, h1, l1;
                split_bf(v0, h0, l0); split_bf(v1, h1, l1);
                __nv_bfloat16* dst = dp + ((size_t)bh*NNODE + (m & 511))*64 + d;
                *(uint32_t*)(dst)      = pack_bf2(h0, h1);
                *(uint32_t*)(dst + 32) = pack_bf2(l0, l1);
            }
        }
    }
}

// ---------------- flash attention ----------------
#define FA_SMEM (3*65536)
__global__ __launch_bounds__(256, 1) void k_fattn() {
    extern __shared__ char sm2[];
    const uint32_t sb = smem_u32(sm2);
    const uint32_t Qb = sb, Kb = sb + 65536, Vb = sb + 131072;
    const int bh = blockIdx.x, t = threadIdx.x, lane = t & 31, w = t >> 5;
    const __nv_bfloat16* qg = g_qs + (size_t)bh * NNODE * 64;
    const __nv_bfloat16* kg = g_ks + (size_t)bh * NNODE * 64;
    const __nv_bfloat16* vg = g_vs + (size_t)bh * NNODE * 64;

    for (int i = t; i < 4096; i += 256) {
        int r = i >> 3, s = i & 7;
        uint32_t off = (uint32_t)(r*128 + ((s ^ (r & 7)) * 16));
        *(float4*)(sm2 + off)          = *(const float4*)(qg + r*64 + s*8);
        *(float4*)(sm2 + 65536 + off)  = *(const float4*)(kg + r*64 + s*8);
    }
    for (int i = t; i < 4096; i += 256) {
        int j = i & 511, s = i >> 9;
        float4 v4 = *(const float4*)(vg + j*64 + s*8);
        const __nv_bfloat16* pv = (const __nv_bfloat16*)&v4;
        #pragma unroll
        for (int k = 0; k < 8; k++) {
            int d = s*8 + k;
            *(__nv_bfloat16*)(sm2 + 131072 + d*1024 + (((j >> 3) ^ (d & 7)) * 16) + (j & 7)*2) = pv[k];
        }
    }
    __syncthreads();

    const int q0 = w * 64;
    uint32_t aqh[4][2][4];
    #pragma unroll
    for (int mt = 0; mt < 4; mt++)
        #pragma unroll
        for (int kc = 0; kc < 2; kc++) {
            int row = q0 + mt*16 + (lane & 15);
            ldmx4(aqh[mt][kc], Qb + row*128 + (((kc*2 + (lane >> 4)) ^ (row & 7)) * 16));
        }

    float of[4][4][4];
    #pragma unroll
    for (int a = 0; a < 4; a++)
        #pragma unroll
        for (int b = 0; b < 4; b++)
            #pragma unroll
            for (int c = 0; c < 4; c++) of[a][b][c] = 0.f;
    float mrow[4][2], lrow[4][2];
    #pragma unroll
    for (int a = 0; a < 4; a++) { mrow[a][0] = -1e30f; mrow[a][1] = -1e30f; lrow[a][0] = 0.f; lrow[a][1] = 0.f; }

    const float sc = 0.17677669529663687f;

    for (int jb = 0; jb < 32; jb++) {
        const int j0 = jb * 16;
        uint32_t bk[4][2][2];
        #pragma unroll
        for (int kc = 0; kc < 4; kc++) {
            int row = j0 + (lane & 15);
            uint32_t r4[4];
            ldmx4(r4, Kb + row*128 + (((kc*2 + (lane >> 4)) ^ (row & 7)) * 16));
            bk[kc][0][0] = r4[0]; bk[kc][0][1] = r4[2];
            bk[kc][1][0] = r4[1]; bk[kc][1][1] = r4[3];
        }
        float c[4][2][4];
        #pragma unroll
        for (int a = 0; a < 4; a++)
            #pragma unroll
            for (int b = 0; b < 2; b++)
                #pragma unroll
                for (int e = 0; e < 4; e++) c[a][b][e] = 0.f;
        #pragma unroll
        for (int mt = 0; mt < 4; mt++) {
            uint32_t aql[2][4];
            #pragma unroll
            for (int kc = 0; kc < 2; kc++) {
                int row = q0 + mt*16 + (lane & 15);
                ldmx4(aql[kc], Qb + row*128 + ((((kc + 2)*2 + (lane >> 4)) ^ (row & 7)) * 16));
            }
            #pragma unroll
            for (int nt = 0; nt < 2; nt++) {
                mma_bf(c[mt][nt], aqh[mt][0], bk[0][nt][0], bk[0][nt][1]);
                mma_bf(c[mt][nt], aqh[mt][1], bk[1][nt][0], bk[1][nt][1]);
                mma_bf(c[mt][nt], aql[0],     bk[0][nt][0], bk[0][nt][1]);
                mma_bf(c[mt][nt], aql[1],     bk[1][nt][0], bk[1][nt][1]);
                mma_bf(c[mt][nt], aqh[mt][0], bk[2][nt][0], bk[2][nt][1]);
                mma_bf(c[mt][nt], aqh[mt][1], bk[3][nt][0], bk[3][nt][1]);
            }
        }
        #pragma unroll
        for (int mt = 0; mt < 4; mt++)
            #pragma unroll
            for (int h = 0; h < 2; h++) {
                float s0 = c[mt][0][h*2]*sc, s1 = c[mt][0][h*2+1]*sc;
                float s2 = c[mt][1][h*2]*sc, s3 = c[mt][1][h*2+1]*sc;
                float mx = fmaxf(fmaxf(s0, s1), fmaxf(s2, s3));
                mx = fmaxf(mx, __shfl_xor_sync(0xffffffffu, mx, 1));
                mx = fmaxf(mx, __shfl_xor_sync(0xffffffffu, mx, 2));
                float mnew = fmaxf(mrow[mt][h], mx);
                float fac = __expf(mrow[mt][h] - mnew);
                mrow[mt][h] = mnew;
                float p0 = __expf(s0 - mnew), p1 = __expf(s1 - mnew);
                float p2 = __expf(s2 - mnew), p3 = __expf(s3 - mnew);
                c[mt][0][h*2] = p0; c[mt][0][h*2+1] = p1;
                c[mt][1][h*2] = p2; c[mt][1][h*2+1] = p3;
                float rs = p0 + p1 + p2 + p3;
                rs += __shfl_xor_sync(0xffffffffu, rs, 1);
                rs += __shfl_xor_sync(0xffffffffu, rs, 2);
                lrow[mt][h] = lrow[mt][h]*fac + rs;
                #pragma unroll
                for (int nt = 0; nt < 4; nt++) { of[mt][nt][h*2] *= fac; of[mt][nt][h*2+1] *= fac; }
            }
        uint32_t pah[4][4], pal[4][4];
        #pragma unroll
        for (int mt = 0; mt < 4; mt++) {
            __nv_bfloat16 hx, lx, hy, ly;
            split_bf(c[mt][0][0], hx, lx); split_bf(c[mt][0][1], hy, ly);
            pah[mt][0] = pack_bf2(hx, hy); pal[mt][0] = pack_bf2(lx, ly);
            split_bf(c[mt][0][2], hx, lx); split_bf(c[mt][0][3], hy, ly);
            pah[mt][1] = pack_bf2(hx, hy); pal[mt][1] = pack_bf2(lx, ly);
            split_bf(c[mt][1][0], hx, lx); split_bf(c[mt][1][1], hy, ly);
            pah[mt][2] = pack_bf2(hx, hy); pal[mt][2] = pack_bf2(lx, ly);
            split_bf(c[mt][1][2], hx, lx); split_bf(c[mt][1][3], hy, ly);
            pah[mt][3] = pack_bf2(hx, hy); pal[mt][3] = pack_bf2(lx, ly);
        }
        uint32_t bvh[4][2], bvl[4][2];
        #pragma unroll
        for (int dh = 0; dh < 2; dh++) {
            int rowh = dh*16 + (lane & 15);
            uint32_t r4[4];
            ldmx4(r4, Vb + rowh*1024 + (((((j0 >> 3) + (lane >> 4)) ^ (rowh & 7))) * 16));
            bvh[dh*2+0][0] = r4[0]; bvh[dh*2+0][1] = r4[2];
            bvh[dh*2+1][0] = r4[1]; bvh[dh*2+1][1] = r4[3];
            int rowl = rowh + 32;
            ldmx4(r4, Vb + rowl*1024 + (((((j0 >> 3) + (lane >> 4)) ^ (rowl & 7))) * 16));
            bvl[dh*2+0][0] = r4[0]; bvl[dh*2+0][1] = r4[2];
            bvl[dh*2+1][0] = r4[1]; bvl[dh*2+1][1] = r4[3];
        }
        #pragma unroll
        for (int mt = 0; mt < 4; mt++)
            #pragma unroll
            for (int nt = 0; nt < 4; nt++) {
                mma_bf(of[mt][nt], pah[mt], bvh[nt][0], bvh[nt][1]);
                mma_bf(of[mt][nt], pal[mt], bvh[nt][0], bvh[nt][1]);
                mma_bf(of[mt][nt], pah[mt], bvl[nt][0], bvl[nt][1]);
            }
    }

    const int b = bh >> 2, h4 = bh & 3;
    #pragma unroll
    for (int mt = 0; mt < 4; mt++)
        #pragma unroll
        for (int h = 0; h < 2; h++) {
            float inv = 1.f / lrow[mt][h];
            int q = q0 + mt*16 + (lane >> 2) + h*8;
            __nv_bfloat16* base = g_obufs + ((size_t)(b*NNODE + q))*384 + h4*DHD;
            #pragma unroll
            for (int nt = 0; nt < 4; nt++) {
                int d = nt*8 + 2*(lane & 3);
                float v0 = of[mt][nt][h*2]   * inv;
                float v1 = of[mt][nt][h*2+1] * inv;
                __nv_bfloat16 h0, l0, h1, l1;
                split_bf(v0, h0, l0); split_bf(v1, h1, l1);
                *(uint32_t*)(base + d)       = pack_bf2(h0, h1);
                *(uint32_t*)(base + 128 + d) = pack_bf2(l0, l1);
                *(uint32_t*)(base + 256 + d) = pack_bf2(h0, h1);
            }
        }
}

// ---------------- finalize / combine / final ----------------
__global__ void k_fin12(const float* __restrict__ gn1, const float* __restrict__ bn1,
                        const float* __restrict__ gn2, const float* __restrict__ bn2) {
    int t = threadIdx.x;
    int which = t >> 7, c = t & 127;
    const float* g = which ? gn2 : gn1;
    const float* b = which ? bn2 : bn1;
    float s  = g_sums[which*256 + c];
    float s2 = g_sums[which*256 + 128 + c];
    float m  = s / (float)NT;
    float v  = s2 / (float)NT - m*m;
    float scale = g[c] * rsqrtf(v + 1e-5f);
    g_scale[which*128 + c] = scale;
    g_shift[which*128 + c] = b[c] - m*scale;
}
__global__ void k_fin3(const float* __restrict__ g, const float* __restrict__ b) {
    int c = threadIdx.x;
    float s  = g_sums[2*256 + c];
    float s2 = g_sums[2*256 + 128 + c];
    float m  = s / (float)NT;
    float v  = s2 / (float)NT - m*m;
    float scale = g[c] * rsqrtf(v + 1e-5f);
    g_scale[2*128 + c] = scale;
    g_shift[2*128 + c] = b[c] - m*scale;
}

__global__ void k_combine() {
    int i = blockIdx.x * blockDim.x + threadIdx.x;
    int c = (i*4) & 127;
    int r = (i*4) >> 7;
    float4 a  = *(const float4*)(g_hlocal + (size_t)i*4);
    float4 bb = *(const float4*)(g_hattn + (size_t)i*4);
    float4 s1 = *(const float4*)(g_scale + c);
    float4 h1 = *(const float4*)(g_shift + c);
    float4 s2 = *(const float4*)(g_scale + 128 + c);
    float4 h2 = *(const float4*)(g_shift + 128 + c);
    float4 o;
    o.x = a.x*s1.x + h1.x + bb.x*s2.x + h2.x;
    o.y = a.y*s1.y + h1.y + bb.y*s2.y + h2.y;
    o.z = a.z*s1.z + h1.z + bb.z*s2.z + h2.z;
    o.w = a.w*s1.w + h1.w + bb.w*s2.w + h2.w;
    *(float4*)(g_comb + (size_t)i*4) = o;
    float vv[4] = {o.x, o.y, o.z, o.w};
    __nv_bfloat16 hi[4], lo[4];
    #pragma unroll
    for (int k = 0; k < 4; k++) split_bf(vv[k], hi[k], lo[k]);
    __nv_bfloat16* dst = g_combs + (size_t)r*384 + c;
    *(uint32_t*)(dst)       = pack_bf2(hi[0], hi[1]);
    *(uint32_t*)(dst + 2)   = pack_bf2(hi[2], hi[3]);
    *(uint32_t*)(dst + 128) = pack_bf2(lo[0], lo[1]);
    *(uint32_t*)(dst + 130) = pack_bf2(lo[2], lo[3]);
    *(uint32_t*)(dst + 256) = pack_bf2(hi[0], hi[1]);
    *(uint32_t*)(dst + 258) = pack_bf2(hi[2], hi[3]);
}

__global__ void k_final(float* __restrict__ out) {
    int i = blockIdx.x * blockDim.x + threadIdx.x;
    int c = (i*4) & 127;
    float4 a  = *(const float4*)(g_out2 + (size_t)i*4);
    float4 s3 = *(const float4*)(g_scale + 256 + c);
    float4 h3 = *(const float4*)(g_shift + 256 + c);
    float4 o;
    o.x = a.x*s3.x + h3.x;
    o.y = a.y*s3.y + h3.y;
    o.z = a.z*s3.z + h3.z;
    o.w = a.w*s3.w + h3.w;
    *(float4*)(out + (size_t)i*4) = o;
}

// ---------------- launch ----------------
extern "C" void kernel_launch(void* const* d_in, const int* in_sizes, int n_in,
                              void* d_out, int out_size) {
    const float* x   = (const float*)d_in[0];
    const int*   ei  = (const int*)  d_in[1];
    const float* Wc  = (const float*)d_in[2];
    const float* bc  = (const float*)d_in[3];
    const float* ipw = (const float*)d_in[4];
    const float* ipb = (const float*)d_in[5];
    const float* opw = (const float*)d_in[6];
    const float* opb = (const float*)d_in[7];
    const float* gn1 = (const float*)d_in[8];
    const float* bn1 = (const float*)d_in[9];
    const float* gn2 = (const float*)d_in[10];
    const float* bn2 = (const float*)d_in[11];
    const float* gn3 = (const float*)d_in[12];
    const float* bn3 = (const float*)d_in[13];
    const float* Wm1 = (const float*)d_in[14];
    const float* bm1 = (const float*)d_in[15];
    const float* Wm2 = (const float*)d_in[16];
    const float* bm2 = (const float*)d_in[17];
    const int* src = ei;
    const int* dst = ei + EE;

    void *p_hlocal, *p_hattn, *p_comb, *p_out2, *p_aggs, *p_obufs, *p_combs, *p_hiddens;
    void *p_Wcs, *p_opws, *p_Wm1s, *p_Wm2s;
    cudaGetSymbolAddress(&p_hlocal, g_hlocal);
    cudaGetSymbolAddress(&p_hattn,  g_hattn);
    cudaGetSymbolAddress(&p_comb,   g_comb);
    cudaGetSymbolAddress(&p_out2,   g_out2);
    cudaGetSymbolAddress(&p_aggs,   g_aggs);
    cudaGetSymbolAddress(&p_obufs,  g_obufs);
    cudaGetSymbolAddress(&p_combs,  g_combs);
    cudaGetSymbolAddress(&p_hiddens,g_hiddens);
    cudaGetSymbolAddress(&p_Wcs,    g_Wcs);
    cudaGetSymbolAddress(&p_opws,   g_opws);
    cudaGetSymbolAddress(&p_Wm1s,   g_Wm1s);
    cudaGetSymbolAddress(&p_Wm2s,   g_Wm2s);

    cudaFuncSetAttribute(k_fattn, cudaFuncAttributeMaxDynamicSharedMemorySize, FA_SMEM);
    cudaFuncSetAttribute(k_qkv,         cudaFuncAttributeMaxDynamicSharedMemorySize, MG_SMEM);
    cudaFuncSetAttribute(k_mgemm<1,0>,  cudaFuncAttributeMaxDynamicSharedMemorySize, MG_SMEM);
    cudaFuncSetAttribute(k_mgemm<1,1>,  cudaFuncAttributeMaxDynamicSharedMemorySize, MG_SMEM);
    cudaFuncSetAttribute(k_mgemm<2,-1>, cudaFuncAttributeMaxDynamicSharedMemorySize, MG_SMEM);
    cudaFuncSetAttribute(k_mgemm<1,2>,  cudaFuncAttributeMaxDynamicSharedMemorySize, MG_SMEM);

    static cudaStream_t s2 = nullptr;
    static cudaEvent_t e_fork = nullptr, e0 = nullptr, e_prepw = nullptr, e_loc = nullptr;
    if (s2 == nullptr) {
        cudaStreamCreateWithFlags(&s2, cudaStreamNonBlocking);
        cudaEventCreateWithFlags(&e_fork, cudaEventDisableTiming);
        cudaEventCreateWithFlags(&e0,     cudaEventDisableTiming);
        cudaEventCreateWithFlags(&e_prepw,cudaEventDisableTiming);
        cudaEventCreateWithFlags(&e_loc,  cudaEventDisableTiming);
    }

    // ---- fork immediately ----
    cudaEventRecord(e_fork, 0);
    cudaStreamWaitEvent(s2, e_fork, 0);

    // ---- side stream: weight splits first (QKV + local depend on them) ----
    k_prep_w<<<576, 256, 0, s2>>>(Wc, ipw, opw, Wm1, Wm2);
    cudaEventRecord(e_prepw, s2);

    // ---- main: zero ----
    k_zero<<<NT/256, 256>>>();
    cudaEventRecord(e0, 0);

    // ---- side: CSR chain + agg + local GEMM ----
    cudaStreamWaitEvent(s2, e0, 0);
    k_deg<<<EE/256, 256, 0, s2>>>(dst);
    k_scan<<<1, 1024, 0, s2>>>();
    k_fill<<<EE/256, 256, 0, s2>>>(src, dst);
    k_agg<<<NT, 128, 0, s2>>>(x);
    k_mgemm<1,0><<<dim3(NT/128, 1), 256, MG_SMEM, s2>>>(
        (const __nv_bfloat16*)p_aggs, (const __nv_bfloat16*)p_Wcs, bc, x, (float*)p_hlocal, 384, 128);
    cudaEventRecord(e_loc, s2);

    // ---- main: QKV (inline x convert; waits on weight splits) ----
    cudaStreamWaitEvent(0, e_prepw, 0);
    k_qkv<<<dim3(NT/128, 3), 256, MG_SMEM>>>(x, ipb);

    k_fattn<<<BB*HH, 256, FA_SMEM>>>();

    k_mgemm<1,1><<<dim3(NT/128, 1), 256, MG_SMEM>>>(
        (const __nv_bfloat16*)p_obufs, (const __nv_bfloat16*)p_opws, opb, x, (float*)p_hattn, 384, 128);

    // ---- join, finish ----
    cudaStreamWaitEvent(0, e_loc, 0);
    k_fin12<<<1, 256>>>(gn1, bn1, gn2, bn2);
    k_combine<<<NT*CC/4/256, 256>>>();

    k_mgemm<2,-1><<<dim3(NT/128, 2), 256, MG_SMEM>>>(
        (const __nv_bfloat16*)p_combs, (const __nv_bfloat16*)p_Wm1s, bm1, nullptr, nullptr, 384, 256);

    k_mgemm<1,2><<<dim3(NT/128, 1), 256, MG_SMEM>>>(
        (const __nv_bfloat16*)p_hiddens, (const __nv_bfloat16*)p_Wm2s, bm2, (const float*)p_comb, (float*)p_out2, 768, 128);

    k_fin3<<<1, 128>>>(gn3, bn3);
    k_final<<<NT*CC/4/256, 256>>>((float*)d_out);
}

// round 9
// speedup vs baseline: 1.3945x; 1.0514x over previous
#include <cuda_runtime.h>
#include <cuda_bf16.h>
#include <math.h>
#include <stdint.h>

#define NT  32768
#define CC  128
#define BB  64
#define NNODE 512
#define HH  4
#define DHD 32
#define EE  524288

// ---------------- scratch ----------------
__device__ int   g_deg[NT];
__device__ int   g_off[NT+1];
__device__ int   g_cur[NT];
__device__ int   g_nbr[EE];
__device__ float g_hlocal[NT*CC];
__device__ float g_hattn[NT*CC];
__device__ float g_comb[NT*CC];
__device__ float g_out2[NT*CC];
__device__ float g_sums[3*2*CC];
__device__ float g_scale[3*CC];
__device__ float g_shift[3*CC];

__device__ __nv_bfloat16 g_aggs[NT*384];     // [hi|lo|hi]
__device__ __nv_bfloat16 g_obufs[NT*384];
__device__ __nv_bfloat16 g_combs[NT*384];
__device__ __nv_bfloat16 g_hiddens[NT*768];
__device__ __nv_bfloat16 g_Wcs[128*384];     // [hi|hi|lo]
__device__ __nv_bfloat16 g_ipws[384*384];
__device__ __nv_bfloat16 g_opws[128*384];
__device__ __nv_bfloat16 g_Wm1s[256*384];
__device__ __nv_bfloat16 g_Wm2s[128*768];
__device__ __nv_bfloat16 g_qs[BB*HH*NNODE*64];
__device__ __nv_bfloat16 g_ks[BB*HH*NNODE*64];
__device__ __nv_bfloat16 g_vs[BB*HH*NNODE*64];

// ---------------- helpers ----------------
__device__ __forceinline__ uint32_t smem_u32(const void* p) {
    uint32_t a;
    asm("{ .reg .u64 t; cvta.to.shared.u64 t, %1; cvt.u32.u64 %0, t; }" : "=r"(a) : "l"(p));
    return a;
}
__device__ __forceinline__ uint32_t pack_bf2(__nv_bfloat16 a, __nv_bfloat16 b) {
    return (uint32_t)__bfloat16_as_ushort(a) | ((uint32_t)__bfloat16_as_ushort(b) << 16);
}
__device__ __forceinline__ void split_bf(float v, __nv_bfloat16& hi, __nv_bfloat16& lo) {
    hi = __float2bfloat16(v);
    lo = __float2bfloat16(v - __bfloat162float(hi));
}
__device__ __forceinline__ void ldmx4(uint32_t* r, uint32_t addr) {
    asm volatile("ldmatrix.sync.aligned.m8n8.x4.shared.b16 {%0,%1,%2,%3}, [%4];"
        : "=r"(r[0]), "=r"(r[1]), "=r"(r[2]), "=r"(r[3]) : "r"(addr));
}
__device__ __forceinline__ void mma_bf(float* c, const uint32_t* a, uint32_t b0, uint32_t b1) {
    asm volatile("mma.sync.aligned.m16n8k16.row.col.f32.bf16.bf16.f32 "
        "{%0,%1,%2,%3}, {%4,%5,%6,%7}, {%8,%9}, {%0,%1,%2,%3};"
        : "+f"(c[0]), "+f"(c[1]), "+f"(c[2]), "+f"(c[3])
        : "r"(a[0]), "r"(a[1]), "r"(a[2]), "r"(a[3]), "r"(b0), "r"(b1));
}
__device__ __forceinline__ void store_a128(__nv_bfloat16* base, int r, int c, float v) {
    __nv_bfloat16 hi, lo; split_bf(v, hi, lo);
    __nv_bfloat16* o = base + (size_t)r * 384;
    o[c] = hi; o[128 + c] = lo; o[256 + c] = hi;
}
__device__ __forceinline__ void store_w(__nv_bfloat16* base, int r, int c, int K, float v) {
    __nv_bfloat16 hi, lo; split_bf(v, hi, lo);
    __nv_bfloat16* o = base + (size_t)(3*r) * K;
    o[c] = hi; o[K + c] = hi; o[2*K + c] = lo;
}

// ---------------- CSR build ----------------
__global__ void k_zero() {
    int i = blockIdx.x * blockDim.x + threadIdx.x;
    if (i < NT) g_deg[i] = 0;
    if (i < 3*2*CC) g_sums[i] = 0.f;
}
__global__ void k_deg(const int* __restrict__ dst) {
    int i = blockIdx.x * blockDim.x + threadIdx.x;
    if (i < EE) atomicAdd(&g_deg[dst[i]], 1);
}
// hierarchical scan: int4 loads, warp shfl-scan, 2 barriers
__global__ void k_scan() {
    __shared__ int wsum[32];
    int t = threadIdx.x, lane = t & 31, wp = t >> 5;
    int4 v[8];
    const int4* dp = (const int4*)g_deg + t*8;
    int s = 0;
    #pragma unroll
    for (int i = 0; i < 8; i++) {
        v[i] = dp[i];
        s += v[i].x + v[i].y + v[i].z + v[i].w;
    }
    int incl = s;
    #pragma unroll
    for (int o = 1; o < 32; o <<= 1) {
        int n = __shfl_up_sync(0xffffffffu, incl, o);
        if (lane >= o) incl += n;
    }
    if (lane == 31) wsum[wp] = incl;
    __syncthreads();
    if (wp == 0) {
        int ws = wsum[lane];
        int wi = ws;
        #pragma unroll
        for (int o = 1; o < 32; o <<= 1) {
            int n = __shfl_up_sync(0xffffffffu, wi, o);
            if (lane >= o) wi += n;
        }
        wsum[lane] = wi - ws;  // exclusive
    }
    __syncthreads();
    int run = wsum[wp] + (incl - s);
    int4* op = (int4*)g_off + t*8;
    int4* cp = (int4*)g_cur + t*8;
    #pragma unroll
    for (int i = 0; i < 8; i++) {
        int4 o4;
        o4.x = run; run += v[i].x;
        o4.y = run; run += v[i].y;
        o4.z = run; run += v[i].z;
        o4.w = run; run += v[i].w;
        op[i] = o4; cp[i] = o4;
    }
    if (t == 1023) g_off[NT] = run;
}
__global__ void k_fill(const int* __restrict__ src, const int* __restrict__ dst) {
    int i = blockIdx.x * blockDim.x + threadIdx.x;
    if (i < EE) {
        int p = atomicAdd(&g_cur[dst[i]], 1);
        g_nbr[p] = src[i];
    }
}

// ---------------- weights-only prep (side stream) ----------------
__global__ void k_prep_w(const float* __restrict__ Wc, const float* __restrict__ ipw,
                         const float* __restrict__ opw, const float* __restrict__ Wm1,
                         const float* __restrict__ Wm2) {
    int i = blockIdx.x * 256 + threadIdx.x;
    if (i < 16384) { store_w(g_Wcs, i >> 7, i & 127, 128, Wc[i]); return; }
    i -= 16384;
    if (i < 49152) { store_w(g_ipws, i >> 7, i & 127, 128, ipw[i]); return; }
    i -= 49152;
    if (i < 16384) { store_w(g_opws, i >> 7, i & 127, 128, opw[i]); return; }
    i -= 16384;
    if (i < 32768) { store_w(g_Wm1s, i >> 7, i & 127, 128, Wm1[i]); return; }
    i -= 32768;
    store_w(g_Wm2s, i >> 8, i & 255, 256, Wm2[i]);
}

// ---------------- mean aggregation ----------------
__global__ void k_agg(const float* __restrict__ x) {
    __shared__ int snbr[128];
    int n = blockIdx.x, c = threadIdx.x;
    int s0 = g_off[n], s1 = g_off[n+1];
    float acc = 0.f;
    for (int j0 = s0; j0 < s1; j0 += 128) {
        int m = min(128, s1 - j0);
        __syncthreads();
        if (c < m) snbr[c] = g_nbr[j0 + c];
        __syncthreads();
        for (int jj = 0; jj < m; jj++) acc += x[snbr[jj]*CC + c];
    }
    float d = (float)(s1 - s0);
    store_a128(g_aggs, n, c, acc / fmaxf(d, 1.f));
}

// ---------------- GEMM mainloop ----------------
#define MG_SMEM (2*32768)

__device__ __forceinline__ void mg_mainloop(
    const __nv_bfloat16* __restrict__ Ap, const __nv_bfloat16* __restrict__ Wp,
    int Kp, char* smem, uint32_t sbase, int t, int lane, int mrow, int ncol,
    float acc[4][4][4])
{
    const int nch = Kp >> 6;
    auto load_chunk = [&](int ck, int buf) {
        int kc = ck * 64;
        #pragma unroll
        for (int i = 0; i < 8; i++) {
            int u = t + 256*i;
            int row_all = u >> 3, seg = u & 7;
            int isB = row_all >> 7;
            int row = row_all & 127;
            const __nv_bfloat16* src = (isB ? Wp : Ap) + (size_t)row * Kp + kc + seg*8;
            uint32_t dst = sbase + buf*32768 + isB*16384 + row*128 + ((seg ^ (row & 7)) * 16);
            asm volatile("cp.async.cg.shared.global [%0], [%1], 16;" :: "r"(dst), "l"(src));
        }
        asm volatile("cp.async.commit_group;" ::: "memory");
    };
    load_chunk(0, 0);
    for (int ck = 0; ck < nch; ck++) {
        if (ck + 1 < nch) {
            load_chunk(ck + 1, (ck + 1) & 1);
            asm volatile("cp.async.wait_group 1;" ::: "memory");
        } else {
            asm volatile("cp.async.wait_group 0;" ::: "memory");
        }
        __syncthreads();
        uint32_t Ab = sbase + (ck & 1)*32768;
        uint32_t Bb = Ab + 16384;
        #pragma unroll
        for (int s = 0; s < 4; s++) {
            int segsw = ((s*2 + (lane >> 4)) ^ (lane & 7)) * 16;
            uint32_t af[4][4];
            #pragma unroll
            for (int mt = 0; mt < 4; mt++)
                ldmx4(af[mt], Ab + (mrow + mt*16 + (lane & 15))*128 + segsw);
            uint32_t bf[4][2];
            #pragma unroll
            for (int half = 0; half < 2; half++) {
                uint32_t r4[4];
                ldmx4(r4, Bb + (ncol + half*16 + (lane & 15))*128 + segsw);
                bf[half*2+0][0] = r4[0]; bf[half*2+0][1] = r4[2];
                bf[half*2+1][0] = r4[1]; bf[half*2+1][1] = r4[3];
            }
            #pragma unroll
            for (int mt = 0; mt < 4; mt++)
                #pragma unroll
                for (int nt = 0; nt < 4; nt++)
                    mma_bf(acc[mt][nt], af[mt], bf[nt][0], bf[nt][1]);
        }
        __syncthreads();
    }
}

__device__ __forceinline__ void mg_stats_flush(char* smem, int t, int lane, int ncol,
                                               const float* csum, const float* csq, int which) {
    float* ssum = (float*)smem;
    float* ssq  = ssum + 128;
    if (t < 256) { ((float*)smem)[t] = 0.f; }
    __syncthreads();
    #pragma unroll
    for (int nt = 0; nt < 4; nt++) {
        int c0 = ncol + nt*8 + 2*(lane & 3);
        atomicAdd(&ssum[c0],   csum[nt*2+0]);
        atomicAdd(&ssum[c0+1], csum[nt*2+1]);
        atomicAdd(&ssq[c0],    csq[nt*2+0]);
        atomicAdd(&ssq[c0+1],  csq[nt*2+1]);
    }
    __syncthreads();
    if (t < 128) {
        atomicAdd(&g_sums[which*256 + t],       ssum[t]);
        atomicAdd(&g_sums[which*256 + 128 + t], ssq[t]);
    }
}

// EPI: 1 = +bias+resid -> fp32 out (+stats WHICH>=0) ; 2 = relu -> hiddens
template<int EPI, int WHICH>
__global__ __launch_bounds__(256, 2) void k_mgemm(
    const __nv_bfloat16* __restrict__ A, const __nv_bfloat16* __restrict__ W,
    const float* __restrict__ bias, const float* __restrict__ resid,
    float* __restrict__ out, int Kp, int Nout)
{
    extern __shared__ char smem[];
    const int t = threadIdx.x, lane = t & 31, w = t >> 5;
    const int bm = blockIdx.x, bn = blockIdx.y;
    const uint32_t sbase = smem_u32(smem);
    const int mrow = (w >> 2) * 64;
    const int ncol = (w & 3) * 32;
    const __nv_bfloat16* Ap = A + (size_t)bm * 128 * Kp;
    const __nv_bfloat16* Wp = W + (size_t)bn * 128 * Kp;

    float acc[4][4][4];
    #pragma unroll
    for (int a = 0; a < 4; a++)
        #pragma unroll
        for (int b = 0; b < 4; b++)
            #pragma unroll
            for (int c = 0; c < 4; c++) acc[a][b][c] = 0.f;

    mg_mainloop(Ap, Wp, Kp, smem, sbase, t, lane, mrow, ncol, acc);

    float csum[8] = {}, csq[8] = {};
    #pragma unroll
    for (int mt = 0; mt < 4; mt++) {
        int m0 = bm*128 + mrow + mt*16 + (lane >> 2);
        #pragma unroll
        for (int nt = 0; nt < 4; nt++) {
            int nl = ncol + nt*8 + 2*(lane & 3);
            int ng = bn*128 + nl;
            float bv0 = bias[ng], bv1 = bias[ng+1];
            #pragma unroll
            for (int hh = 0; hh < 2; hh++) {
                int m = m0 + hh*8;
                float v0 = acc[mt][nt][hh*2+0] + bv0;
                float v1 = acc[mt][nt][hh*2+1] + bv1;
                if (EPI == 2) {
                    v0 = fmaxf(v0, 0.f); v1 = fmaxf(v1, 0.f);
                    __nv_bfloat16 h0, l0, h1, l1;
                    split_bf(v0, h0, l0); split_bf(v1, h1, l1);
                    __nv_bfloat16* dst = g_hiddens + (size_t)m*768 + ng;
                    *(uint32_t*)(dst)       = pack_bf2(h0, h1);
                    *(uint32_t*)(dst + 256) = pack_bf2(l0, l1);
                    *(uint32_t*)(dst + 512) = pack_bf2(h0, h1);
                } else {
                    const float2 rv = *(const float2*)(resid + (size_t)m*Nout + ng);
                    v0 += rv.x; v1 += rv.y;
                    *(float2*)(out + (size_t)m*Nout + ng) = make_float2(v0, v1);
                    if (WHICH >= 0) {
                        csum[nt*2+0] += v0; csq[nt*2+0] += v0*v0;
                        csum[nt*2+1] += v1; csq[nt*2+1] += v1*v1;
                    }
                }
            }
        }
    }
    if (EPI == 1 && WHICH >= 0) {
        __syncthreads();
        mg_stats_flush(smem, t, lane, ncol, csum, csq, WHICH);
    }
}

// ---------------- QKV GEMM with inline x fp32 -> split-bf16 conversion ----------------
__global__ __launch_bounds__(256, 2) void k_qkv(const float* __restrict__ x,
                                                const float* __restrict__ ipb) {
    extern __shared__ char smem[];
    const int t = threadIdx.x, lane = t & 31, w = t >> 5;
    const int bm = blockIdx.x, bn = blockIdx.y;
    const uint32_t sbase = smem_u32(smem);
    const int mrow = (w >> 2) * 64;
    const int ncol = (w & 3) * 32;
    const float* Xp = x + (size_t)bm * 128 * 128;
    const __nv_bfloat16* Wp = g_ipws + (size_t)bn * 128 * 384;

    float acc[4][4][4];
    #pragma unroll
    for (int a = 0; a < 4; a++)
        #pragma unroll
        for (int b = 0; b < 4; b++)
            #pragma unroll
            for (int c = 0; c < 4; c++) acc[a][b][c] = 0.f;

    auto load_chunk = [&](int ck, int buf) {
        int kc = ck * 64;
        int v = kc >> 7;
        int c0 = kc & 127;
        #pragma unroll
        for (int i = 0; i < 4; i++) {
            int u = t + 256*i;
            int r = u >> 3, s = u & 7;
            const float* srcx = Xp + (size_t)r*128 + c0 + s*8;
            float4 f0 = *(const float4*)(srcx);
            float4 f1 = *(const float4*)(srcx + 4);
            float vals[8] = {f0.x,f0.y,f0.z,f0.w,f1.x,f1.y,f1.z,f1.w};
            uint32_t pk[4];
            if (v == 1) {
                #pragma unroll
                for (int k2 = 0; k2 < 4; k2++) {
                    __nv_bfloat16 h0 = __float2bfloat16(vals[k2*2]);
                    __nv_bfloat16 h1 = __float2bfloat16(vals[k2*2+1]);
                    __nv_bfloat16 l0 = __float2bfloat16(vals[k2*2]   - __bfloat162float(h0));
                    __nv_bfloat16 l1 = __float2bfloat16(vals[k2*2+1] - __bfloat162float(h1));
                    pk[k2] = pack_bf2(l0, l1);
                }
            } else {
                #pragma unroll
                for (int k2 = 0; k2 < 4; k2++)
                    pk[k2] = pack_bf2(__float2bfloat16(vals[k2*2]), __float2bfloat16(vals[k2*2+1]));
            }
            *(uint4*)(smem + buf*32768 + r*128 + ((s ^ (r & 7)) * 16)) = make_uint4(pk[0],pk[1],pk[2],pk[3]);
        }
        #pragma unroll
        for (int i = 0; i < 4; i++) {
            int u = t + 256*i;
            int r = u >> 3, s = u & 7;
            const __nv_bfloat16* src = Wp + (size_t)r * 384 + kc + s*8;
            uint32_t dst = sbase + buf*32768 + 16384 + r*128 + ((s ^ (r & 7)) * 16);
            asm volatile("cp.async.cg.shared.global [%0], [%1], 16;" :: "r"(dst), "l"(src));
        }
        asm volatile("cp.async.commit_group;" ::: "memory");
    };

    load_chunk(0, 0);
    for (int ck = 0; ck < 6; ck++) {
        if (ck + 1 < 6) {
            load_chunk(ck + 1, (ck + 1) & 1);
            asm volatile("cp.async.wait_group 1;" ::: "memory");
        } else {
            asm volatile("cp.async.wait_group 0;" ::: "memory");
        }
        __syncthreads();
        uint32_t Ab = sbase + (ck & 1)*32768;
        uint32_t Bb = Ab + 16384;
        #pragma unroll
        for (int s = 0; s < 4; s++) {
            int segsw = ((s*2 + (lane >> 4)) ^ (lane & 7)) * 16;
            uint32_t af[4][4];
            #pragma unroll
            for (int mt = 0; mt < 4; mt++)
                ldmx4(af[mt], Ab + (mrow + mt*16 + (lane & 15))*128 + segsw);
            uint32_t bf[4][2];
            #pragma unroll
            for (int half = 0; half < 2; half++) {
                uint32_t r4[4];
                ldmx4(r4, Bb + (ncol + half*16 + (lane & 15))*128 + segsw);
                bf[half*2+0][0] = r4[0]; bf[half*2+0][1] = r4[2];
                bf[half*2+1][0] = r4[1]; bf[half*2+1][1] = r4[3];
            }
            #pragma unroll
            for (int mt = 0; mt < 4; mt++)
                #pragma unroll
                for (int nt = 0; nt < 4; nt++)
                    mma_bf(acc[mt][nt], af[mt], bf[nt][0], bf[nt][1]);
        }
        __syncthreads();
    }

    #pragma unroll
    for (int mt = 0; mt < 4; mt++) {
        int m0 = bm*128 + mrow + mt*16 + (lane >> 2);
        #pragma unroll
        for (int nt = 0; nt < 4; nt++) {
            int nl = ncol + nt*8 + 2*(lane & 3);
            float bv0 = ipb[bn*128 + nl], bv1 = ipb[bn*128 + nl + 1];
            #pragma unroll
            for (int hh = 0; hh < 2; hh++) {
                int m = m0 + hh*8;
                float v0 = acc[mt][nt][hh*2+0] + bv0;
                float v1 = acc[mt][nt][hh*2+1] + bv1;
                int h = nl >> 5, d = nl & 31;
                __nv_bfloat16* dp = (bn == 0) ? g_qs : (bn == 1) ? g_ks : g_vs;
                int bh = (m >> 9)*HH + h;
                __nv_bfloat16 h0, l0, h1, l1;
                split_bf(v0, h0, l0); split_bf(v1, h1, l1);
                __nv_bfloat16* dst = dp + ((size_t)bh*NNODE + (m & 511))*64 + d;
                *(uint32_t*)(dst)      = pack_bf2(h0, h1);
                *(uint32_t*)(dst + 32) = pack_bf2(l0, l1);
            }
        }
    }
}

// ---------------- flash attention ----------------
#define FA_SMEM (3*65536)
__global__ __launch_bounds__(256, 1) void k_fattn() {
    extern __shared__ char sm2[];
    const uint32_t sb = smem_u32(sm2);
    const uint32_t Qb = sb, Kb = sb + 65536, Vb = sb + 131072;
    const int bh = blockIdx.x, t = threadIdx.x, lane = t & 31, w = t >> 5;
    const __nv_bfloat16* qg = g_qs + (size_t)bh * NNODE * 64;
    const __nv_bfloat16* kg = g_ks + (size_t)bh * NNODE * 64;
    const __nv_bfloat16* vg = g_vs + (size_t)bh * NNODE * 64;

    for (int i = t; i < 4096; i += 256) {
        int r = i >> 3, s = i & 7;
        uint32_t off = (uint32_t)(r*128 + ((s ^ (r & 7)) * 16));
        *(float4*)(sm2 + off)          = *(const float4*)(qg + r*64 + s*8);
        *(float4*)(sm2 + 65536 + off)  = *(const float4*)(kg + r*64 + s*8);
    }
    for (int i = t; i < 4096; i += 256) {
        int j = i & 511, s = i >> 9;
        float4 v4 = *(const float4*)(vg + j*64 + s*8);
        const __nv_bfloat16* pv = (const __nv_bfloat16*)&v4;
        #pragma unroll
        for (int k = 0; k < 8; k++) {
            int d = s*8 + k;
            *(__nv_bfloat16*)(sm2 + 131072 + d*1024 + (((j >> 3) ^ (d & 7)) * 16) + (j & 7)*2) = pv[k];
        }
    }
    __syncthreads();

    const int q0 = w * 64;
    uint32_t aqh[4][2][4];
    #pragma unroll
    for (int mt = 0; mt < 4; mt++)
        #pragma unroll
        for (int kc = 0; kc < 2; kc++) {
            int row = q0 + mt*16 + (lane & 15);
            ldmx4(aqh[mt][kc], Qb + row*128 + (((kc*2 + (lane >> 4)) ^ (row & 7)) * 16));
        }

    float of[4][4][4];
    #pragma unroll
    for (int a = 0; a < 4; a++)
        #pragma unroll
        for (int b = 0; b < 4; b++)
            #pragma unroll
            for (int c = 0; c < 4; c++) of[a][b][c] = 0.f;
    float mrow[4][2], lrow[4][2];
    #pragma unroll
    for (int a = 0; a < 4; a++) { mrow[a][0] = -1e30f; mrow[a][1] = -1e30f; lrow[a][0] = 0.f; lrow[a][1] = 0.f; }

    const float sc = 0.17677669529663687f;

    for (int jb = 0; jb < 32; jb++) {
        const int j0 = jb * 16;
        uint32_t bk[4][2][2];
        #pragma unroll
        for (int kc = 0; kc < 4; kc++) {
            int row = j0 + (lane & 15);
            uint32_t r4[4];
            ldmx4(r4, Kb + row*128 + (((kc*2 + (lane >> 4)) ^ (row & 7)) * 16));
            bk[kc][0][0] = r4[0]; bk[kc][0][1] = r4[2];
            bk[kc][1][0] = r4[1]; bk[kc][1][1] = r4[3];
        }
        float c[4][2][4];
        #pragma unroll
        for (int a = 0; a < 4; a++)
            #pragma unroll
            for (int b = 0; b < 2; b++)
                #pragma unroll
                for (int e = 0; e < 4; e++) c[a][b][e] = 0.f;
        #pragma unroll
        for (int mt = 0; mt < 4; mt++) {
            uint32_t aql[2][4];
            #pragma unroll
            for (int kc = 0; kc < 2; kc++) {
                int row = q0 + mt*16 + (lane & 15);
                ldmx4(aql[kc], Qb + row*128 + ((((kc + 2)*2 + (lane >> 4)) ^ (row & 7)) * 16));
            }
            #pragma unroll
            for (int nt = 0; nt < 2; nt++) {
                mma_bf(c[mt][nt], aqh[mt][0], bk[0][nt][0], bk[0][nt][1]);
                mma_bf(c[mt][nt], aqh[mt][1], bk[1][nt][0], bk[1][nt][1]);
                mma_bf(c[mt][nt], aql[0],     bk[0][nt][0], bk[0][nt][1]);
                mma_bf(c[mt][nt], aql[1],     bk[1][nt][0], bk[1][nt][1]);
                mma_bf(c[mt][nt], aqh[mt][0], bk[2][nt][0], bk[2][nt][1]);
                mma_bf(c[mt][nt], aqh[mt][1], bk[3][nt][0], bk[3][nt][1]);
            }
        }
        #pragma unroll
        for (int mt = 0; mt < 4; mt++)
            #pragma unroll
            for (int h = 0; h < 2; h++) {
                float s0 = c[mt][0][h*2]*sc, s1 = c[mt][0][h*2+1]*sc;
                float s2 = c[mt][1][h*2]*sc, s3 = c[mt][1][h*2+1]*sc;
                float mx = fmaxf(fmaxf(s0, s1), fmaxf(s2, s3));
                mx = fmaxf(mx, __shfl_xor_sync(0xffffffffu, mx, 1));
                mx = fmaxf(mx, __shfl_xor_sync(0xffffffffu, mx, 2));
                float mnew = fmaxf(mrow[mt][h], mx);
                float fac = __expf(mrow[mt][h] - mnew);
                mrow[mt][h] = mnew;
                float p0 = __expf(s0 - mnew), p1 = __expf(s1 - mnew);
                float p2 = __expf(s2 - mnew), p3 = __expf(s3 - mnew);
                c[mt][0][h*2] = p0; c[mt][0][h*2+1] = p1;
                c[mt][1][h*2] = p2; c[mt][1][h*2+1] = p3;
                float rs = p0 + p1 + p2 + p3;
                rs += __shfl_xor_sync(0xffffffffu, rs, 1);
                rs += __shfl_xor_sync(0xffffffffu, rs, 2);
                lrow[mt][h] = lrow[mt][h]*fac + rs;
                #pragma unroll
                for (int nt = 0; nt < 4; nt++) { of[mt][nt][h*2] *= fac; of[mt][nt][h*2+1] *= fac; }
            }
        uint32_t pah[4][4], pal[4][4];
        #pragma unroll
        for (int mt = 0; mt < 4; mt++) {
            __nv_bfloat16 hx, lx, hy, ly;
            split_bf(c[mt][0][0], hx, lx); split_bf(c[mt][0][1], hy, ly);
            pah[mt][0] = pack_bf2(hx, hy); pal[mt][0] = pack_bf2(lx, ly);
            split_bf(c[mt][0][2], hx, lx); split_bf(c[mt][0][3], hy, ly);
            pah[mt][1] = pack_bf2(hx, hy); pal[mt][1] = pack_bf2(lx, ly);
            split_bf(c[mt][1][0], hx, lx); split_bf(c[mt][1][1], hy, ly);
            pah[mt][2] = pack_bf2(hx, hy); pal[mt][2] = pack_bf2(lx, ly);
            split_bf(c[mt][1][2], hx, lx); split_bf(c[mt][1][3], hy, ly);
            pah[mt][3] = pack_bf2(hx, hy); pal[mt][3] = pack_bf2(lx, ly);
        }
        uint32_t bvh[4][2], bvl[4][2];
        #pragma unroll
        for (int dh = 0; dh < 2; dh++) {
            int rowh = dh*16 + (lane & 15);
            uint32_t r4[4];
            ldmx4(r4, Vb + rowh*1024 + (((((j0 >> 3) + (lane >> 4)) ^ (rowh & 7))) * 16));
            bvh[dh*2+0][0] = r4[0]; bvh[dh*2+0][1] = r4[2];
            bvh[dh*2+1][0] = r4[1]; bvh[dh*2+1][1] = r4[3];
            int rowl = rowh + 32;
            ldmx4(r4, Vb + rowl*1024 + (((((j0 >> 3) + (lane >> 4)) ^ (rowl & 7))) * 16));
            bvl[dh*2+0][0] = r4[0]; bvl[dh*2+0][1] = r4[2];
            bvl[dh*2+1][0] = r4[1]; bvl[dh*2+1][1] = r4[3];
        }
        #pragma unroll
        for (int mt = 0; mt < 4; mt++)
            #pragma unroll
            for (int nt = 0; nt < 4; nt++) {
                mma_bf(of[mt][nt], pah[mt], bvh[nt][0], bvh[nt][1]);
                mma_bf(of[mt][nt], pal[mt], bvh[nt][0], bvh[nt][1]);
                mma_bf(of[mt][nt], pah[mt], bvl[nt][0], bvl[nt][1]);
            }
    }

    const int b = bh >> 2, h4 = bh & 3;
    #pragma unroll
    for (int mt = 0; mt < 4; mt++)
        #pragma unroll
        for (int h = 0; h < 2; h++) {
            float inv = 1.f / lrow[mt][h];
            int q = q0 + mt*16 + (lane >> 2) + h*8;
            __nv_bfloat16* base = g_obufs + ((size_t)(b*NNODE + q))*384 + h4*DHD;
            #pragma unroll
            for (int nt = 0; nt < 4; nt++) {
                int d = nt*8 + 2*(lane & 3);
                float v0 = of[mt][nt][h*2]   * inv;
                float v1 = of[mt][nt][h*2+1] * inv;
                __nv_bfloat16 h0, l0, h1, l1;
                split_bf(v0, h0, l0); split_bf(v1, h1, l1);
                *(uint32_t*)(base + d)       = pack_bf2(h0, h1);
                *(uint32_t*)(base + 128 + d) = pack_bf2(l0, l1);
                *(uint32_t*)(base + 256 + d) = pack_bf2(h0, h1);
            }
        }
}

// ---------------- finalize / combine / final ----------------
__global__ void k_fin12(const float* __restrict__ gn1, const float* __restrict__ bn1,
                        const float* __restrict__ gn2, const float* __restrict__ bn2) {
    int t = threadIdx.x;
    int which = t >> 7, c = t & 127;
    const float* g = which ? gn2 : gn1;
    const float* b = which ? bn2 : bn1;
    float s  = g_sums[which*256 + c];
    float s2 = g_sums[which*256 + 128 + c];
    float m  = s / (float)NT;
    float v  = s2 / (float)NT - m*m;
    float scale = g[c] * rsqrtf(v + 1e-5f);
    g_scale[which*128 + c] = scale;
    g_shift[which*128 + c] = b[c] - m*scale;
}
__global__ void k_fin3(const float* __restrict__ g, const float* __restrict__ b) {
    int c = threadIdx.x;
    float s  = g_sums[2*256 + c];
    float s2 = g_sums[2*256 + 128 + c];
    float m  = s / (float)NT;
    float v  = s2 / (float)NT - m*m;
    float scale = g[c] * rsqrtf(v + 1e-5f);
    g_scale[2*128 + c] = scale;
    g_shift[2*128 + c] = b[c] - m*scale;
}

__global__ void k_combine() {
    int i = blockIdx.x * blockDim.x + threadIdx.x;
    int c = (i*4) & 127;
    int r = (i*4) >> 7;
    float4 a  = *(const float4*)(g_hlocal + (size_t)i*4);
    float4 bb = *(const float4*)(g_hattn + (size_t)i*4);
    float4 s1 = *(const float4*)(g_scale + c);
    float4 h1 = *(const float4*)(g_shift + c);
    float4 s2 = *(const float4*)(g_scale + 128 + c);
    float4 h2 = *(const float4*)(g_shift + 128 + c);
    float4 o;
    o.x = a.x*s1.x + h1.x + bb.x*s2.x + h2.x;
    o.y = a.y*s1.y + h1.y + bb.y*s2.y + h2.y;
    o.z = a.z*s1.z + h1.z + bb.z*s2.z + h2.z;
    o.w = a.w*s1.w + h1.w + bb.w*s2.w + h2.w;
    *(float4*)(g_comb + (size_t)i*4) = o;
    float vv[4] = {o.x, o.y, o.z, o.w};
    __nv_bfloat16 hi[4], lo[4];
    #pragma unroll
    for (int k = 0; k < 4; k++) split_bf(vv[k], hi[k], lo[k]);
    __nv_bfloat16* dst = g_combs + (size_t)r*384 + c;
    *(uint32_t*)(dst)       = pack_bf2(hi[0], hi[1]);
    *(uint32_t*)(dst + 2)   = pack_bf2(hi[2], hi[3]);
    *(uint32_t*)(dst + 128) = pack_bf2(lo[0], lo[1]);
    *(uint32_t*)(dst + 130) = pack_bf2(lo[2], lo[3]);
    *(uint32_t*)(dst + 256) = pack_bf2(hi[0], hi[1]);
    *(uint32_t*)(dst + 258) = pack_bf2(hi[2], hi[3]);
}

__global__ void k_final(float* __restrict__ out) {
    int i = blockIdx.x * blockDim.x + threadIdx.x;
    int c = (i*4) & 127;
    float4 a  = *(const float4*)(g_out2 + (size_t)i*4);
    float4 s3 = *(const float4*)(g_scale + 256 + c);
    float4 h3 = *(const float4*)(g_shift + 256 + c);
    float4 o;
    o.x = a.x*s3.x + h3.x;
    o.y = a.y*s3.y + h3.y;
    o.z = a.z*s3.z + h3.z;
    o.w = a.w*s3.w + h3.w;
    *(float4*)(out + (size_t)i*4) = o;
}

// ---------------- launch ----------------
extern "C" void kernel_launch(void* const* d_in, const int* in_sizes, int n_in,
                              void* d_out, int out_size) {
    const float* x   = (const float*)d_in[0];
    const int*   ei  = (const int*)  d_in[1];
    const float* Wc  = (const float*)d_in[2];
    const float* bc  = (const float*)d_in[3];
    const float* ipw = (const float*)d_in[4];
    const float* ipb = (const float*)d_in[5];
    const float* opw = (const float*)d_in[6];
    const float* opb = (const float*)d_in[7];
    const float* gn1 = (const float*)d_in[8];
    const float* bn1 = (const float*)d_in[9];
    const float* gn2 = (const float*)d_in[10];
    const float* bn2 = (const float*)d_in[11];
    const float* gn3 = (const float*)d_in[12];
    const float* bn3 = (const float*)d_in[13];
    const float* Wm1 = (const float*)d_in[14];
    const float* bm1 = (const float*)d_in[15];
    const float* Wm2 = (const float*)d_in[16];
    const float* bm2 = (const float*)d_in[17];
    const int* src = ei;
    const int* dst = ei + EE;

    void *p_hlocal, *p_hattn, *p_comb, *p_out2, *p_aggs, *p_obufs, *p_combs, *p_hiddens;
    void *p_Wcs, *p_opws, *p_Wm1s, *p_Wm2s;
    cudaGetSymbolAddress(&p_hlocal, g_hlocal);
    cudaGetSymbolAddress(&p_hattn,  g_hattn);
    cudaGetSymbolAddress(&p_comb,   g_comb);
    cudaGetSymbolAddress(&p_out2,   g_out2);
    cudaGetSymbolAddress(&p_aggs,   g_aggs);
    cudaGetSymbolAddress(&p_obufs,  g_obufs);
    cudaGetSymbolAddress(&p_combs,  g_combs);
    cudaGetSymbolAddress(&p_hiddens,g_hiddens);
    cudaGetSymbolAddress(&p_Wcs,    g_Wcs);
    cudaGetSymbolAddress(&p_opws,   g_opws);
    cudaGetSymbolAddress(&p_Wm1s,   g_Wm1s);
    cudaGetSymbolAddress(&p_Wm2s,   g_Wm2s);

    cudaFuncSetAttribute(k_fattn, cudaFuncAttributeMaxDynamicSharedMemorySize, FA_SMEM);
    cudaFuncSetAttribute(k_qkv,         cudaFuncAttributeMaxDynamicSharedMemorySize, MG_SMEM);
    cudaFuncSetAttribute(k_mgemm<1,0>,  cudaFuncAttributeMaxDynamicSharedMemorySize, MG_SMEM);
    cudaFuncSetAttribute(k_mgemm<1,1>,  cudaFuncAttributeMaxDynamicSharedMemorySize, MG_SMEM);
    cudaFuncSetAttribute(k_mgemm<2,-1>, cudaFuncAttributeMaxDynamicSharedMemorySize, MG_SMEM);
    cudaFuncSetAttribute(k_mgemm<1,2>,  cudaFuncAttributeMaxDynamicSharedMemorySize, MG_SMEM);

    static cudaStream_t s2 = nullptr;
    static cudaEvent_t e_fork = nullptr, e0 = nullptr, e_prepw = nullptr, e_loc = nullptr;
    if (s2 == nullptr) {
        cudaStreamCreateWithFlags(&s2, cudaStreamNonBlocking);
        cudaEventCreateWithFlags(&e_fork, cudaEventDisableTiming);
        cudaEventCreateWithFlags(&e0,     cudaEventDisableTiming);
        cudaEventCreateWithFlags(&e_prepw,cudaEventDisableTiming);
        cudaEventCreateWithFlags(&e_loc,  cudaEventDisableTiming);
    }

    // ---- fork immediately ----
    cudaEventRecord(e_fork, 0);
    cudaStreamWaitEvent(s2, e_fork, 0);

    // ---- side stream: weight splits first (QKV + local depend on them) ----
    k_prep_w<<<576, 256, 0, s2>>>(Wc, ipw, opw, Wm1, Wm2);
    cudaEventRecord(e_prepw, s2);

    // ---- main: zero ----
    k_zero<<<NT/256, 256>>>();
    cudaEventRecord(e0, 0);

    // ---- side: CSR chain + agg + local GEMM ----
    cudaStreamWaitEvent(s2, e0, 0);
    k_deg<<<EE/256, 256, 0, s2>>>(dst);
    k_scan<<<1, 1024, 0, s2>>>();
    k_fill<<<EE/256, 256, 0, s2>>>(src, dst);
    k_agg<<<NT, 128, 0, s2>>>(x);
    k_mgemm<1,0><<<dim3(NT/128, 1), 256, MG_SMEM, s2>>>(
        (const __nv_bfloat16*)p_aggs, (const __nv_bfloat16*)p_Wcs, bc, x, (float*)p_hlocal, 384, 128);
    cudaEventRecord(e_loc, s2);

    // ---- main: QKV (inline x convert; waits on weight splits) ----
    cudaStreamWaitEvent(0, e_prepw, 0);
    k_qkv<<<dim3(NT/128, 3), 256, MG_SMEM>>>(x, ipb);

    k_fattn<<<BB*HH, 256, FA_SMEM>>>();

    k_mgemm<1,1><<<dim3(NT/128, 1), 256, MG_SMEM>>>(
        (const __nv_bfloat16*)p_obufs, (const __nv_bfloat16*)p_opws, opb, x, (float*)p_hattn, 384, 128);

    // ---- join, finish ----
    cudaStreamWaitEvent(0, e_loc, 0);
    k_fin12<<<1, 256>>>(gn1, bn1, gn2, bn2);
    k_combine<<<NT*CC/4/256, 256>>>();

    k_mgemm<2,-1><<<dim3(NT/128, 2), 256, MG_SMEM>>>(
        (const __nv_bfloat16*)p_combs, (const __nv_bfloat16*)p_Wm1s, bm1, nullptr, nullptr, 384, 256);

    k_mgemm<1,2><<<dim3(NT/128, 1), 256, MG_SMEM>>>(
        (const __nv_bfloat16*)p_hiddens, (const __nv_bfloat16*)p_Wm2s, bm2, (const float*)p_comb, (float*)p_out2, 768, 128);

    k_fin3<<<1, 128>>>(gn3, bn3);
    k_final<<<NT*CC/4/256, 256>>>((float*)d_out);
}

// round 10
// speedup vs baseline: 1.4335x; 1.0280x over previous
#include <cuda_runtime.h>
#include <cuda_bf16.h>
#include <math.h>
#include <stdint.h>

#define NT  32768
#define CC  128
#define BB  64
#define NNODE 512
#define HH  4
#define DHD 32
#define EE  524288

// ---------------- scratch ----------------
__device__ int   g_deg[NT];
__device__ int   g_off[NT+1];
__device__ int   g_cur[NT];
__device__ int   g_nbr[EE];
__device__ float g_hlocal[NT*CC];
__device__ float g_hattn[NT*CC];
__device__ float g_out2[NT*CC];
__device__ float g_sums[3*2*CC];
__device__ float g_scale[3*CC];
__device__ float g_shift[3*CC];

__device__ __nv_bfloat16 g_aggs[NT*384];     // [hi|lo|hi]
__device__ __nv_bfloat16 g_obufs[NT*384];
__device__ __nv_bfloat16 g_combs[NT*384];
__device__ __nv_bfloat16 g_hiddens[NT*768];
__device__ __nv_bfloat16 g_Wcs[128*384];     // [hi|hi|lo]
__device__ __nv_bfloat16 g_ipws[384*384];
__device__ __nv_bfloat16 g_opws[128*384];
__device__ __nv_bfloat16 g_Wm1s[256*384];
__device__ __nv_bfloat16 g_Wm2s[128*768];
__device__ __nv_bfloat16 g_qs[BB*HH*NNODE*64];
__device__ __nv_bfloat16 g_ks[BB*HH*NNODE*64];
__device__ __nv_bfloat16 g_vs[BB*HH*NNODE*64];

// ---------------- helpers ----------------
__device__ __forceinline__ uint32_t smem_u32(const void* p) {
    uint32_t a;
    asm("{ .reg .u64 t; cvta.to.shared.u64 t, %1; cvt.u32.u64 %0, t; }" : "=r"(a) : "l"(p));
    return a;
}
__device__ __forceinline__ uint32_t pack_bf2(__nv_bfloat16 a, __nv_bfloat16 b) {
    return (uint32_t)__bfloat16_as_ushort(a) | ((uint32_t)__bfloat16_as_ushort(b) << 16);
}
__device__ __forceinline__ void split_bf(float v, __nv_bfloat16& hi, __nv_bfloat16& lo) {
    hi = __float2bfloat16(v);
    lo = __float2bfloat16(v - __bfloat162float(hi));
}
__device__ __forceinline__ void ldmx4(uint32_t* r, uint32_t addr) {
    asm volatile("ldmatrix.sync.aligned.m8n8.x4.shared.b16 {%0,%1,%2,%3}, [%4];"
        : "=r"(r[0]), "=r"(r[1]), "=r"(r[2]), "=r"(r[3]) : "r"(addr));
}
__device__ __forceinline__ void mma_bf(float* c, const uint32_t* a, uint32_t b0, uint32_t b1) {
    asm volatile("mma.sync.aligned.m16n8k16.row.col.f32.bf16.bf16.f32 "
        "{%0,%1,%2,%3}, {%4,%5,%6,%7}, {%8,%9}, {%0,%1,%2,%3};"
        : "+f"(c[0]), "+f"(c[1]), "+f"(c[2]), "+f"(c[3])
        : "r"(a[0]), "r"(a[1]), "r"(a[2]), "r"(a[3]), "r"(b0), "r"(b1));
}
__device__ __forceinline__ void store_a128(__nv_bfloat16* base, int r, int c, float v) {
    __nv_bfloat16 hi, lo; split_bf(v, hi, lo);
    __nv_bfloat16* o = base + (size_t)r * 384;
    o[c] = hi; o[128 + c] = lo; o[256 + c] = hi;
}
__device__ __forceinline__ void store_w(__nv_bfloat16* base, int r, int c, int K, float v) {
    __nv_bfloat16 hi, lo; split_bf(v, hi, lo);
    __nv_bfloat16* o = base + (size_t)(3*r) * K;
    o[c] = hi; o[K + c] = hi; o[2*K + c] = lo;
}

// ---------------- CSR build ----------------
__global__ void k_zero() {
    int i = blockIdx.x * blockDim.x + threadIdx.x;
    if (i < NT) g_deg[i] = 0;
    if (i < 3*2*CC) g_sums[i] = 0.f;
}
__global__ void k_deg(const int* __restrict__ dst) {
    int i = blockIdx.x * blockDim.x + threadIdx.x;
    if (i < EE) atomicAdd(&g_deg[dst[i]], 1);
}
__global__ void k_scan() {
    __shared__ int wsum[32];
    int t = threadIdx.x, lane = t & 31, wp = t >> 5;
    int4 v[8];
    const int4* dp = (const int4*)g_deg + t*8;
    int s = 0;
    #pragma unroll
    for (int i = 0; i < 8; i++) {
        v[i] = dp[i];
        s += v[i].x + v[i].y + v[i].z + v[i].w;
    }
    int incl = s;
    #pragma unroll
    for (int o = 1; o < 32; o <<= 1) {
        int n = __shfl_up_sync(0xffffffffu, incl, o);
        if (lane >= o) incl += n;
    }
    if (lane == 31) wsum[wp] = incl;
    __syncthreads();
    if (wp == 0) {
        int ws = wsum[lane];
        int wi = ws;
        #pragma unroll
        for (int o = 1; o < 32; o <<= 1) {
            int n = __shfl_up_sync(0xffffffffu, wi, o);
            if (lane >= o) wi += n;
        }
        wsum[lane] = wi - ws;  // exclusive
    }
    __syncthreads();
    int run = wsum[wp] + (incl - s);
    int4* op = (int4*)g_off + t*8;
    int4* cp = (int4*)g_cur + t*8;
    #pragma unroll
    for (int i = 0; i < 8; i++) {
        int4 o4;
        o4.x = run; run += v[i].x;
        o4.y = run; run += v[i].y;
        o4.z = run; run += v[i].z;
        o4.w = run; run += v[i].w;
        op[i] = o4; cp[i] = o4;
    }
    if (t == 1023) g_off[NT] = run;
}
__global__ void k_fill(const int* __restrict__ src, const int* __restrict__ dst) {
    int i = blockIdx.x * blockDim.x + threadIdx.x;
    if (i < EE) {
        int p = atomicAdd(&g_cur[dst[i]], 1);
        g_nbr[p] = src[i];
    }
}

// ---------------- weights-only prep (side stream) ----------------
__global__ void k_prep_w(const float* __restrict__ Wc, const float* __restrict__ ipw,
                         const float* __restrict__ opw, const float* __restrict__ Wm1,
                         const float* __restrict__ Wm2) {
    int i = blockIdx.x * 256 + threadIdx.x;
    if (i < 16384) { store_w(g_Wcs, i >> 7, i & 127, 128, Wc[i]); return; }
    i -= 16384;
    if (i < 49152) { store_w(g_ipws, i >> 7, i & 127, 128, ipw[i]); return; }
    i -= 49152;
    if (i < 16384) { store_w(g_opws, i >> 7, i & 127, 128, opw[i]); return; }
    i -= 16384;
    if (i < 32768) { store_w(g_Wm1s, i >> 7, i & 127, 128, Wm1[i]); return; }
    i -= 32768;
    store_w(g_Wm2s, i >> 8, i & 255, 256, Wm2[i]);
}

// ---------------- mean aggregation ----------------
__global__ void k_agg(const float* __restrict__ x) {
    __shared__ int snbr[128];
    int n = blockIdx.x, c = threadIdx.x;
    int s0 = g_off[n], s1 = g_off[n+1];
    float acc = 0.f;
    for (int j0 = s0; j0 < s1; j0 += 128) {
        int m = min(128, s1 - j0);
        __syncthreads();
        if (c < m) snbr[c] = g_nbr[j0 + c];
        __syncthreads();
        for (int jj = 0; jj < m; jj++) acc += x[snbr[jj]*CC + c];
    }
    float d = (float)(s1 - s0);
    store_a128(g_aggs, n, c, acc / fmaxf(d, 1.f));
}

// ---------------- GEMM mainloop ----------------
#define MG_SMEM (2*32768)

__device__ __forceinline__ void mg_mainloop(
    const __nv_bfloat16* __restrict__ Ap, const __nv_bfloat16* __restrict__ Wp,
    int Kp, char* smem, uint32_t sbase, int t, int lane, int mrow, int ncol,
    float acc[4][4][4])
{
    const int nch = Kp >> 6;
    auto load_chunk = [&](int ck, int buf) {
        int kc = ck * 64;
        #pragma unroll
        for (int i = 0; i < 8; i++) {
            int u = t + 256*i;
            int row_all = u >> 3, seg = u & 7;
            int isB = row_all >> 7;
            int row = row_all & 127;
            const __nv_bfloat16* src = (isB ? Wp : Ap) + (size_t)row * Kp + kc + seg*8;
            uint32_t dst = sbase + buf*32768 + isB*16384 + row*128 + ((seg ^ (row & 7)) * 16);
            asm volatile("cp.async.cg.shared.global [%0], [%1], 16;" :: "r"(dst), "l"(src));
        }
        asm volatile("cp.async.commit_group;" ::: "memory");
    };
    load_chunk(0, 0);
    for (int ck = 0; ck < nch; ck++) {
        if (ck + 1 < nch) {
            load_chunk(ck + 1, (ck + 1) & 1);
            asm volatile("cp.async.wait_group 1;" ::: "memory");
        } else {
            asm volatile("cp.async.wait_group 0;" ::: "memory");
        }
        __syncthreads();
        uint32_t Ab = sbase + (ck & 1)*32768;
        uint32_t Bb = Ab + 16384;
        #pragma unroll
        for (int s = 0; s < 4; s++) {
            int segsw = ((s*2 + (lane >> 4)) ^ (lane & 7)) * 16;
            uint32_t af[4][4];
            #pragma unroll
            for (int mt = 0; mt < 4; mt++)
                ldmx4(af[mt], Ab + (mrow + mt*16 + (lane & 15))*128 + segsw);
            uint32_t bf[4][2];
            #pragma unroll
            for (int half = 0; half < 2; half++) {
                uint32_t r4[4];
                ldmx4(r4, Bb + (ncol + half*16 + (lane & 15))*128 + segsw);
                bf[half*2+0][0] = r4[0]; bf[half*2+0][1] = r4[2];
                bf[half*2+1][0] = r4[1]; bf[half*2+1][1] = r4[3];
            }
            #pragma unroll
            for (int mt = 0; mt < 4; mt++)
                #pragma unroll
                for (int nt = 0; nt < 4; nt++)
                    mma_bf(acc[mt][nt], af[mt], bf[nt][0], bf[nt][1]);
        }
        __syncthreads();
    }
}

__device__ __forceinline__ void mg_stats_flush(char* smem, int t, int lane, int ncol,
                                               const float* csum, const float* csq, int which) {
    float* ssum = (float*)smem;
    float* ssq  = ssum + 128;
    if (t < 256) { ((float*)smem)[t] = 0.f; }
    __syncthreads();
    #pragma unroll
    for (int nt = 0; nt < 4; nt++) {
        int c0 = ncol + nt*8 + 2*(lane & 3);
        atomicAdd(&ssum[c0],   csum[nt*2+0]);
        atomicAdd(&ssum[c0+1], csum[nt*2+1]);
        atomicAdd(&ssq[c0],    csq[nt*2+0]);
        atomicAdd(&ssq[c0+1],  csq[nt*2+1]);
    }
    __syncthreads();
    if (t < 128) {
        atomicAdd(&g_sums[which*256 + t],       ssum[t]);
        atomicAdd(&g_sums[which*256 + 128 + t], ssq[t]);
    }
}

// EPI: 1 = +bias+resid(fp32) -> out (+stats) ; 2 = relu -> hiddens ; 4 = +bias+resid(from g_combs hi+lo) -> out (+stats)
template<int EPI, int WHICH>
__global__ __launch_bounds__(256, 2) void k_mgemm(
    const __nv_bfloat16* __restrict__ A, const __nv_bfloat16* __restrict__ W,
    const float* __restrict__ bias, const float* __restrict__ resid,
    float* __restrict__ out, int Kp, int Nout)
{
    extern __shared__ char smem[];
    const int t = threadIdx.x, lane = t & 31, w = t >> 5;
    const int bm = blockIdx.x, bn = blockIdx.y;
    const uint32_t sbase = smem_u32(smem);
    const int mrow = (w >> 2) * 64;
    const int ncol = (w & 3) * 32;
    const __nv_bfloat16* Ap = A + (size_t)bm * 128 * Kp;
    const __nv_bfloat16* Wp = W + (size_t)bn * 128 * Kp;

    float acc[4][4][4];
    #pragma unroll
    for (int a = 0; a < 4; a++)
        #pragma unroll
        for (int b = 0; b < 4; b++)
            #pragma unroll
            for (int c = 0; c < 4; c++) acc[a][b][c] = 0.f;

    mg_mainloop(Ap, Wp, Kp, smem, sbase, t, lane, mrow, ncol, acc);

    float csum[8] = {}, csq[8] = {};
    #pragma unroll
    for (int mt = 0; mt < 4; mt++) {
        int m0 = bm*128 + mrow + mt*16 + (lane >> 2);
        #pragma unroll
        for (int nt = 0; nt < 4; nt++) {
            int nl = ncol + nt*8 + 2*(lane & 3);
            int ng = bn*128 + nl;
            float bv0 = bias[ng], bv1 = bias[ng+1];
            #pragma unroll
            for (int hh = 0; hh < 2; hh++) {
                int m = m0 + hh*8;
                float v0 = acc[mt][nt][hh*2+0] + bv0;
                float v1 = acc[mt][nt][hh*2+1] + bv1;
                if (EPI == 2) {
                    v0 = fmaxf(v0, 0.f); v1 = fmaxf(v1, 0.f);
                    __nv_bfloat16 h0, l0, h1, l1;
                    split_bf(v0, h0, l0); split_bf(v1, h1, l1);
                    __nv_bfloat16* dst = g_hiddens + (size_t)m*768 + ng;
                    *(uint32_t*)(dst)       = pack_bf2(h0, h1);
                    *(uint32_t*)(dst + 256) = pack_bf2(l0, l1);
                    *(uint32_t*)(dst + 512) = pack_bf2(h0, h1);
                } else {
                    if (EPI == 4) {
                        uint32_t hv = *(const uint32_t*)(g_combs + (size_t)m*384 + ng);
                        uint32_t lv = *(const uint32_t*)(g_combs + (size_t)m*384 + 128 + ng);
                        v0 += __bfloat162float(__ushort_as_bfloat16((unsigned short)(hv & 0xffff)))
                            + __bfloat162float(__ushort_as_bfloat16((unsigned short)(lv & 0xffff)));
                        v1 += __bfloat162float(__ushort_as_bfloat16((unsigned short)(hv >> 16)))
                            + __bfloat162float(__ushort_as_bfloat16((unsigned short)(lv >> 16)));
                    } else {
                        const float2 rv = *(const float2*)(resid + (size_t)m*Nout + ng);
                        v0 += rv.x; v1 += rv.y;
                    }
                    *(float2*)(out + (size_t)m*Nout + ng) = make_float2(v0, v1);
                    if (WHICH >= 0) {
                        csum[nt*2+0] += v0; csq[nt*2+0] += v0*v0;
                        csum[nt*2+1] += v1; csq[nt*2+1] += v1*v1;
                    }
                }
            }
        }
    }
    if (EPI != 2 && WHICH >= 0) {
        __syncthreads();
        mg_stats_flush(smem, t, lane, ncol, csum, csq, WHICH);
    }
}

// ---------------- QKV GEMM with inline x fp32 -> split-bf16 conversion ----------------
__global__ __launch_bounds__(256, 2) void k_qkv(const float* __restrict__ x,
                                                const float* __restrict__ ipb) {
    extern __shared__ char smem[];
    const int t = threadIdx.x, lane = t & 31, w = t >> 5;
    const int bm = blockIdx.x, bn = blockIdx.y;
    const uint32_t sbase = smem_u32(smem);
    const int mrow = (w >> 2) * 64;
    const int ncol = (w & 3) * 32;
    const float* Xp = x + (size_t)bm * 128 * 128;
    const __nv_bfloat16* Wp = g_ipws + (size_t)bn * 128 * 384;

    float acc[4][4][4];
    #pragma unroll
    for (int a = 0; a < 4; a++)
        #pragma unroll
        for (int b = 0; b < 4; b++)
            #pragma unroll
            for (int c = 0; c < 4; c++) acc[a][b][c] = 0.f;

    auto load_chunk = [&](int ck, int buf) {
        int kc = ck * 64;
        int v = kc >> 7;
        int c0 = kc & 127;
        #pragma unroll
        for (int i = 0; i < 4; i++) {
            int u = t + 256*i;
            int r = u >> 3, s = u & 7;
            const float* srcx = Xp + (size_t)r*128 + c0 + s*8;
            float4 f0 = *(const float4*)(srcx);
            float4 f1 = *(const float4*)(srcx + 4);
            float vals[8] = {f0.x,f0.y,f0.z,f0.w,f1.x,f1.y,f1.z,f1.w};
            uint32_t pk[4];
            if (v == 1) {
                #pragma unroll
                for (int k2 = 0; k2 < 4; k2++) {
                    __nv_bfloat16 h0 = __float2bfloat16(vals[k2*2]);
                    __nv_bfloat16 h1 = __float2bfloat16(vals[k2*2+1]);
                    __nv_bfloat16 l0 = __float2bfloat16(vals[k2*2]   - __bfloat162float(h0));
                    __nv_bfloat16 l1 = __float2bfloat16(vals[k2*2+1] - __bfloat162float(h1));
                    pk[k2] = pack_bf2(l0, l1);
                }
            } else {
                #pragma unroll
                for (int k2 = 0; k2 < 4; k2++)
                    pk[k2] = pack_bf2(__float2bfloat16(vals[k2*2]), __float2bfloat16(vals[k2*2+1]));
            }
            *(uint4*)(smem + buf*32768 + r*128 + ((s ^ (r & 7)) * 16)) = make_uint4(pk[0],pk[1],pk[2],pk[3]);
        }
        #pragma unroll
        for (int i = 0; i < 4; i++) {
            int u = t + 256*i;
            int r = u >> 3, s = u & 7;
            const __nv_bfloat16* src = Wp + (size_t)r * 384 + kc + s*8;
            uint32_t dst = sbase + buf*32768 + 16384 + r*128 + ((s ^ (r & 7)) * 16);
            asm volatile("cp.async.cg.shared.global [%0], [%1], 16;" :: "r"(dst), "l"(src));
        }
        asm volatile("cp.async.commit_group;" ::: "memory");
    };

    load_chunk(0, 0);
    for (int ck = 0; ck < 6; ck++) {
        if (ck + 1 < 6) {
            load_chunk(ck + 1, (ck + 1) & 1);
            asm volatile("cp.async.wait_group 1;" ::: "memory");
        } else {
            asm volatile("cp.async.wait_group 0;" ::: "memory");
        }
        __syncthreads();
        uint32_t Ab = sbase + (ck & 1)*32768;
        uint32_t Bb = Ab + 16384;
        #pragma unroll
        for (int s = 0; s < 4; s++) {
            int segsw = ((s*2 + (lane >> 4)) ^ (lane & 7)) * 16;
            uint32_t af[4][4];
            #pragma unroll
            for (int mt = 0; mt < 4; mt++)
                ldmx4(af[mt], Ab + (mrow + mt*16 + (lane & 15))*128 + segsw);
            uint32_t bf[4][2];
            #pragma unroll
            for (int half = 0; half < 2; half++) {
                uint32_t r4[4];
                ldmx4(r4, Bb + (ncol + half*16 + (lane & 15))*128 + segsw);
                bf[half*2+0][0] = r4[0]; bf[half*2+0][1] = r4[2];
                bf[half*2+1][0] = r4[1]; bf[half*2+1][1] = r4[3];
            }
            #pragma unroll
            for (int mt = 0; mt < 4; mt++)
                #pragma unroll
                for (int nt = 0; nt < 4; nt++)
                    mma_bf(acc[mt][nt], af[mt], bf[nt][0], bf[nt][1]);
        }
        __syncthreads();
    }

    #pragma unroll
    for (int mt = 0; mt < 4; mt++) {
        int m0 = bm*128 + mrow + mt*16 + (lane >> 2);
        #pragma unroll
        for (int nt = 0; nt < 4; nt++) {
            int nl = ncol + nt*8 + 2*(lane & 3);
            float bv0 = ipb[bn*128 + nl], bv1 = ipb[bn*128 + nl + 1];
            #pragma unroll
            for (int hh = 0; hh < 2; hh++) {
                int m = m0 + hh*8;
                float v0 = acc[mt][nt][hh*2+0] + bv0;
                float v1 = acc[mt][nt][hh*2+1] + bv1;
                int h = nl >> 5, d = nl & 31;
                __nv_bfloat16* dp = (bn == 0) ? g_qs : (bn == 1) ? g_ks : g_vs;
                int bh = (m >> 9)*HH + h;
                __nv_bfloat16 h0, l0, h1, l1;
                split_bf(v0, h0, l0); split_bf(v1, h1, l1);
                __nv_bfloat16* dst = dp + ((size_t)bh*NNODE + (m & 511))*64 + d;
                *(uint32_t*)(dst)      = pack_bf2(h0, h1);
                *(uint32_t*)(dst + 32) = pack_bf2(l0, l1);
            }
        }
    }
}

// ---------------- flash attention: 512 threads, warp owns 32 q-rows ----------------
#define FA_SMEM (3*65536)
__global__ __launch_bounds__(512, 1) void k_fattn() {
    extern __shared__ char sm2[];
    const uint32_t sb = smem_u32(sm2);
    const uint32_t Qb = sb, Kb = sb + 65536, Vb = sb + 131072;
    const int bh = blockIdx.x, t = threadIdx.x, lane = t & 31, w = t >> 5;
    const __nv_bfloat16* qg = g_qs + (size_t)bh * NNODE * 64;
    const __nv_bfloat16* kg = g_ks + (size_t)bh * NNODE * 64;
    const __nv_bfloat16* vg = g_vs + (size_t)bh * NNODE * 64;

    for (int i = t; i < 4096; i += 512) {
        int r = i >> 3, s = i & 7;
        uint32_t off = (uint32_t)(r*128 + ((s ^ (r & 7)) * 16));
        *(float4*)(sm2 + off)          = *(const float4*)(qg + r*64 + s*8);
        *(float4*)(sm2 + 65536 + off)  = *(const float4*)(kg + r*64 + s*8);
    }
    for (int i = t; i < 4096; i += 512) {
        int j = i & 511, s = i >> 9;
        float4 v4 = *(const float4*)(vg + j*64 + s*8);
        const __nv_bfloat16* pv = (const __nv_bfloat16*)&v4;
        #pragma unroll
        for (int k = 0; k < 8; k++) {
            int d = s*8 + k;
            *(__nv_bfloat16*)(sm2 + 131072 + d*1024 + (((j >> 3) ^ (d & 7)) * 16) + (j & 7)*2) = pv[k];
        }
    }
    __syncthreads();

    const int q0 = w * 32;
    uint32_t aqh[2][2][4];
    #pragma unroll
    for (int mt = 0; mt < 2; mt++)
        #pragma unroll
        for (int kc = 0; kc < 2; kc++) {
            int row = q0 + mt*16 + (lane & 15);
            ldmx4(aqh[mt][kc], Qb + row*128 + (((kc*2 + (lane >> 4)) ^ (row & 7)) * 16));
        }

    float of[2][4][4];
    #pragma unroll
    for (int a = 0; a < 2; a++)
        #pragma unroll
        for (int b = 0; b < 4; b++)
            #pragma unroll
            for (int c = 0; c < 4; c++) of[a][b][c] = 0.f;
    float mrow[2][2], lrow[2][2];
    #pragma unroll
    for (int a = 0; a < 2; a++) { mrow[a][0] = -1e30f; mrow[a][1] = -1e30f; lrow[a][0] = 0.f; lrow[a][1] = 0.f; }

    const float sc = 0.17677669529663687f;

    for (int jb = 0; jb < 32; jb++) {
        const int j0 = jb * 16;
        uint32_t bk[4][2][2];
        #pragma unroll
        for (int kc = 0; kc < 4; kc++) {
            int row = j0 + (lane & 15);
            uint32_t r4[4];
            ldmx4(r4, Kb + row*128 + (((kc*2 + (lane >> 4)) ^ (row & 7)) * 16));
            bk[kc][0][0] = r4[0]; bk[kc][0][1] = r4[2];
            bk[kc][1][0] = r4[1]; bk[kc][1][1] = r4[3];
        }
        float c[2][2][4];
        #pragma unroll
        for (int a = 0; a < 2; a++)
            #pragma unroll
            for (int b = 0; b < 2; b++)
                #pragma unroll
                for (int e = 0; e < 4; e++) c[a][b][e] = 0.f;
        #pragma unroll
        for (int mt = 0; mt < 2; mt++) {
            uint32_t aql[2][4];
            #pragma unroll
            for (int kc = 0; kc < 2; kc++) {
                int row = q0 + mt*16 + (lane & 15);
                ldmx4(aql[kc], Qb + row*128 + ((((kc + 2)*2 + (lane >> 4)) ^ (row & 7)) * 16));
            }
            #pragma unroll
            for (int nt = 0; nt < 2; nt++) {
                mma_bf(c[mt][nt], aqh[mt][0], bk[0][nt][0], bk[0][nt][1]);
                mma_bf(c[mt][nt], aqh[mt][1], bk[1][nt][0], bk[1][nt][1]);
                mma_bf(c[mt][nt], aql[0],     bk[0][nt][0], bk[0][nt][1]);
                mma_bf(c[mt][nt], aql[1],     bk[1][nt][0], bk[1][nt][1]);
                mma_bf(c[mt][nt], aqh[mt][0], bk[2][nt][0], bk[2][nt][1]);
                mma_bf(c[mt][nt], aqh[mt][1], bk[3][nt][0], bk[3][nt][1]);
            }
        }
        #pragma unroll
        for (int mt = 0; mt < 2; mt++)
            #pragma unroll
            for (int h = 0; h < 2; h++) {
                float s0 = c[mt][0][h*2]*sc, s1 = c[mt][0][h*2+1]*sc;
                float s2 = c[mt][1][h*2]*sc, s3 = c[mt][1][h*2+1]*sc;
                float mx = fmaxf(fmaxf(s0, s1), fmaxf(s2, s3));
                mx = fmaxf(mx, __shfl_xor_sync(0xffffffffu, mx, 1));
                mx = fmaxf(mx, __shfl_xor_sync(0xffffffffu, mx, 2));
                float mnew = fmaxf(mrow[mt][h], mx);
                float fac = __expf(mrow[mt][h] - mnew);
                mrow[mt][h] = mnew;
                float p0 = __expf(s0 - mnew), p1 = __expf(s1 - mnew);
                float p2 = __expf(s2 - mnew), p3 = __expf(s3 - mnew);
                c[mt][0][h*2] = p0; c[mt][0][h*2+1] = p1;
                c[mt][1][h*2] = p2; c[mt][1][h*2+1] = p3;
                float rs = p0 + p1 + p2 + p3;
                rs += __shfl_xor_sync(0xffffffffu, rs, 1);
                rs += __shfl_xor_sync(0xffffffffu, rs, 2);
                lrow[mt][h] = lrow[mt][h]*fac + rs;
                #pragma unroll
                for (int nt = 0; nt < 4; nt++) { of[mt][nt][h*2] *= fac; of[mt][nt][h*2+1] *= fac; }
            }
        uint32_t pah[2][4], pal[2][4];
        #pragma unroll
        for (int mt = 0; mt < 2; mt++) {
            __nv_bfloat16 hx, lx, hy, ly;
            split_bf(c[mt][0][0], hx, lx); split_bf(c[mt][0][1], hy, ly);
            pah[mt][0] = pack_bf2(hx, hy); pal[mt][0] = pack_bf2(lx, ly);
            split_bf(c[mt][0][2], hx, lx); split_bf(c[mt][0][3], hy, ly);
            pah[mt][1] = pack_bf2(hx, hy); pal[mt][1] = pack_bf2(lx, ly);
            split_bf(c[mt][1][0], hx, lx); split_bf(c[mt][1][1], hy, ly);
            pah[mt][2] = pack_bf2(hx, hy); pal[mt][2] = pack_bf2(lx, ly);
            split_bf(c[mt][1][2], hx, lx); split_bf(c[mt][1][3], hy, ly);
            pah[mt][3] = pack_bf2(hx, hy); pal[mt][3] = pack_bf2(lx, ly);
        }
        uint32_t bvh[4][2], bvl[4][2];
        #pragma unroll
        for (int dh = 0; dh < 2; dh++) {
            int rowh = dh*16 + (lane & 15);
            uint32_t r4[4];
            ldmx4(r4, Vb + rowh*1024 + (((((j0 >> 3) + (lane >> 4)) ^ (rowh & 7))) * 16));
            bvh[dh*2+0][0] = r4[0]; bvh[dh*2+0][1] = r4[2];
            bvh[dh*2+1][0] = r4[1]; bvh[dh*2+1][1] = r4[3];
            int rowl = rowh + 32;
            ldmx4(r4, Vb + rowl*1024 + (((((j0 >> 3) + (lane >> 4)) ^ (rowl & 7))) * 16));
            bvl[dh*2+0][0] = r4[0]; bvl[dh*2+0][1] = r4[2];
            bvl[dh*2+1][0] = r4[1]; bvl[dh*2+1][1] = r4[3];
        }
        #pragma unroll
        for (int mt = 0; mt < 2; mt++)
            #pragma unroll
            for (int nt = 0; nt < 4; nt++) {
                mma_bf(of[mt][nt], pah[mt], bvh[nt][0], bvh[nt][1]);
                mma_bf(of[mt][nt], pal[mt], bvh[nt][0], bvh[nt][1]);
                mma_bf(of[mt][nt], pah[mt], bvl[nt][0], bvl[nt][1]);
            }
    }

    const int b = bh >> 2, h4 = bh & 3;
    #pragma unroll
    for (int mt = 0; mt < 2; mt++)
        #pragma unroll
        for (int h = 0; h < 2; h++) {
            float inv = 1.f / lrow[mt][h];
            int q = q0 + mt*16 + (lane >> 2) + h*8;
            __nv_bfloat16* base = g_obufs + ((size_t)(b*NNODE + q))*384 + h4*DHD;
            #pragma unroll
            for (int nt = 0; nt < 4; nt++) {
                int d = nt*8 + 2*(lane & 3);
                float v0 = of[mt][nt][h*2]   * inv;
                float v1 = of[mt][nt][h*2+1] * inv;
                __nv_bfloat16 h0, l0, h1, l1;
                split_bf(v0, h0, l0); split_bf(v1, h1, l1);
                *(uint32_t*)(base + d)       = pack_bf2(h0, h1);
                *(uint32_t*)(base + 128 + d) = pack_bf2(l0, l1);
                *(uint32_t*)(base + 256 + d) = pack_bf2(h0, h1);
            }
        }
}

// ---------------- finalize / combine / final ----------------
__global__ void k_fin12(const float* __restrict__ gn1, const float* __restrict__ bn1,
                        const float* __restrict__ gn2, const float* __restrict__ bn2) {
    int t = threadIdx.x;
    int which = t >> 7, c = t & 127;
    const float* g = which ? gn2 : gn1;
    const float* b = which ? bn2 : bn1;
    float s  = g_sums[which*256 + c];
    float s2 = g_sums[which*256 + 128 + c];
    float m  = s / (float)NT;
    float v  = s2 / (float)NT - m*m;
    float scale = g[c] * rsqrtf(v + 1e-5f);
    g_scale[which*128 + c] = scale;
    g_shift[which*128 + c] = b[c] - m*scale;
}
__global__ void k_fin3(const float* __restrict__ g, const float* __restrict__ b) {
    int c = threadIdx.x;
    float s  = g_sums[2*256 + c];
    float s2 = g_sums[2*256 + 128 + c];
    float m  = s / (float)NT;
    float v  = s2 / (float)NT - m*m;
    float scale = g[c] * rsqrtf(v + 1e-5f);
    g_scale[2*128 + c] = scale;
    g_shift[2*128 + c] = b[c] - m*scale;
}

__global__ void k_combine() {   // combs(split) = bn1(hlocal)+bn2(hattn); no fp32 copy
    int i = blockIdx.x * blockDim.x + threadIdx.x;
    int c = (i*4) & 127;
    int r = (i*4) >> 7;
    float4 a  = *(const float4*)(g_hlocal + (size_t)i*4);
    float4 bb = *(const float4*)(g_hattn + (size_t)i*4);
    float4 s1 = *(const float4*)(g_scale + c);
    float4 h1 = *(const float4*)(g_shift + c);
    float4 s2 = *(const float4*)(g_scale + 128 + c);
    float4 h2 = *(const float4*)(g_shift + 128 + c);
    float4 o;
    o.x = a.x*s1.x + h1.x + bb.x*s2.x + h2.x;
    o.y = a.y*s1.y + h1.y + bb.y*s2.y + h2.y;
    o.z = a.z*s1.z + h1.z + bb.z*s2.z + h2.z;
    o.w = a.w*s1.w + h1.w + bb.w*s2.w + h2.w;
    float vv[4] = {o.x, o.y, o.z, o.w};
    __nv_bfloat16 hi[4], lo[4];
    #pragma unroll
    for (int k = 0; k < 4; k++) split_bf(vv[k], hi[k], lo[k]);
    __nv_bfloat16* dst = g_combs + (size_t)r*384 + c;
    *(uint32_t*)(dst)       = pack_bf2(hi[0], hi[1]);
    *(uint32_t*)(dst + 2)   = pack_bf2(hi[2], hi[3]);
    *(uint32_t*)(dst + 128) = pack_bf2(lo[0], lo[1]);
    *(uint32_t*)(dst + 130) = pack_bf2(lo[2], lo[3]);
    *(uint32_t*)(dst + 256) = pack_bf2(hi[0], hi[1]);
    *(uint32_t*)(dst + 258) = pack_bf2(hi[2], hi[3]);
}

__global__ void k_final(float* __restrict__ out) {
    int i = blockIdx.x * blockDim.x + threadIdx.x;
    int c = (i*4) & 127;
    float4 a  = *(const float4*)(g_out2 + (size_t)i*4);
    float4 s3 = *(const float4*)(g_scale + 256 + c);
    float4 h3 = *(const float4*)(g_shift + 256 + c);
    float4 o;
    o.x = a.x*s3.x + h3.x;
    o.y = a.y*s3.y + h3.y;
    o.z = a.z*s3.z + h3.z;
    o.w = a.w*s3.w + h3.w;
    *(float4*)(out + (size_t)i*4) = o;
}

// ---------------- launch ----------------
extern "C" void kernel_launch(void* const* d_in, const int* in_sizes, int n_in,
                              void* d_out, int out_size) {
    const float* x   = (const float*)d_in[0];
    const int*   ei  = (const int*)  d_in[1];
    const float* Wc  = (const float*)d_in[2];
    const float* bc  = (const float*)d_in[3];
    const float* ipw = (const float*)d_in[4];
    const float* ipb = (const float*)d_in[5];
    const float* opw = (const float*)d_in[6];
    const float* opb = (const float*)d_in[7];
    const float* gn1 = (const float*)d_in[8];
    const float* bn1 = (const float*)d_in[9];
    const float* gn2 = (const float*)d_in[10];
    const float* bn2 = (const float*)d_in[11];
    const float* gn3 = (const float*)d_in[12];
    const float* bn3 = (const float*)d_in[13];
    const float* Wm1 = (const float*)d_in[14];
    const float* bm1 = (const float*)d_in[15];
    const float* Wm2 = (const float*)d_in[16];
    const float* bm2 = (const float*)d_in[17];
    const int* src = ei;
    const int* dst = ei + EE;

    void *p_hlocal, *p_hattn, *p_out2, *p_aggs, *p_obufs, *p_combs, *p_hiddens;
    void *p_Wcs, *p_opws, *p_Wm1s, *p_Wm2s;
    cudaGetSymbolAddress(&p_hlocal, g_hlocal);
    cudaGetSymbolAddress(&p_hattn,  g_hattn);
    cudaGetSymbolAddress(&p_out2,   g_out2);
    cudaGetSymbolAddress(&p_aggs,   g_aggs);
    cudaGetSymbolAddress(&p_obufs,  g_obufs);
    cudaGetSymbolAddress(&p_combs,  g_combs);
    cudaGetSymbolAddress(&p_hiddens,g_hiddens);
    cudaGetSymbolAddress(&p_Wcs,    g_Wcs);
    cudaGetSymbolAddress(&p_opws,   g_opws);
    cudaGetSymbolAddress(&p_Wm1s,   g_Wm1s);
    cudaGetSymbolAddress(&p_Wm2s,   g_Wm2s);

    cudaFuncSetAttribute(k_fattn, cudaFuncAttributeMaxDynamicSharedMemorySize, FA_SMEM);
    cudaFuncSetAttribute(k_qkv,         cudaFuncAttributeMaxDynamicSharedMemorySize, MG_SMEM);
    cudaFuncSetAttribute(k_mgemm<1,0>,  cudaFuncAttributeMaxDynamicSharedMemorySize, MG_SMEM);
    cudaFuncSetAttribute(k_mgemm<1,1>,  cudaFuncAttributeMaxDynamicSharedMemorySize, MG_SMEM);
    cudaFuncSetAttribute(k_mgemm<2,-1>, cudaFuncAttributeMaxDynamicSharedMemorySize, MG_SMEM);
    cudaFuncSetAttribute(k_mgemm<4,2>,  cudaFuncAttributeMaxDynamicSharedMemorySize, MG_SMEM);

    static cudaStream_t s2 = nullptr;
    static cudaEvent_t e_fork = nullptr, e0 = nullptr, e_prepw = nullptr, e_loc = nullptr;
    if (s2 == nullptr) {
        cudaStreamCreateWithFlags(&s2, cudaStreamNonBlocking);
        cudaEventCreateWithFlags(&e_fork, cudaEventDisableTiming);
        cudaEventCreateWithFlags(&e0,     cudaEventDisableTiming);
        cudaEventCreateWithFlags(&e_prepw,cudaEventDisableTiming);
        cudaEventCreateWithFlags(&e_loc,  cudaEventDisableTiming);
    }

    // ---- fork immediately ----
    cudaEventRecord(e_fork, 0);
    cudaStreamWaitEvent(s2, e_fork, 0);

    // ---- side stream: weight splits first ----
    k_prep_w<<<576, 256, 0, s2>>>(Wc, ipw, opw, Wm1, Wm2);
    cudaEventRecord(e_prepw, s2);

    // ---- main: zero ----
    k_zero<<<NT/256, 256>>>();
    cudaEventRecord(e0, 0);

    // ---- side: CSR chain + agg + local GEMM ----
    cudaStreamWaitEvent(s2, e0, 0);
    k_deg<<<EE/256, 256, 0, s2>>>(dst);
    k_scan<<<1, 1024, 0, s2>>>();
    k_fill<<<EE/256, 256, 0, s2>>>(src, dst);
    k_agg<<<NT, 128, 0, s2>>>(x);
    k_mgemm<1,0><<<dim3(NT/128, 1), 256, MG_SMEM, s2>>>(
        (const __nv_bfloat16*)p_aggs, (const __nv_bfloat16*)p_Wcs, bc, x, (float*)p_hlocal, 384, 128);
    cudaEventRecord(e_loc, s2);

    // ---- main: QKV -> attention -> out_proj ----
    cudaStreamWaitEvent(0, e_prepw, 0);
    k_qkv<<<dim3(NT/128, 3), 256, MG_SMEM>>>(x, ipb);

    k_fattn<<<BB*HH, 512, FA_SMEM>>>();

    k_mgemm<1,1><<<dim3(NT/128, 1), 256, MG_SMEM>>>(
        (const __nv_bfloat16*)p_obufs, (const __nv_bfloat16*)p_opws, opb, x, (float*)p_hattn, 384, 128);

    // ---- join, finish ----
    cudaStreamWaitEvent(0, e_loc, 0);
    k_fin12<<<1, 256>>>(gn1, bn1, gn2, bn2);
    k_combine<<<NT*CC/4/256, 256>>>();

    k_mgemm<2,-1><<<dim3(NT/128, 2), 256, MG_SMEM>>>(
        (const __nv_bfloat16*)p_combs, (const __nv_bfloat16*)p_Wm1s, bm1, nullptr, nullptr, 384, 256);

    k_mgemm<4,2><<<dim3(NT/128, 1), 256, MG_SMEM>>>(
        (const __nv_bfloat16*)p_hiddens, (const __nv_bfloat16*)p_Wm2s, bm2, nullptr, (float*)p_out2, 768, 128);

    k_fin3<<<1, 128>>>(gn3, bn3);
    k_final<<<NT*CC/4/256, 256>>>((float*)d_out);
}

// round 12
// speedup vs baseline: 1.5726x; 1.0971x over previous
#include <cuda_runtime.h>
#include <cuda_bf16.h>
#include <cuda_fp16.h>
#include <math.h>
#include <stdint.h>

#define NT  32768
#define CC  128
#define BB  64
#define NNODE 512
#define HH  4
#define DHD 32
#define EE  524288

// ---------------- scratch ----------------
__device__ int   g_deg[NT];
__device__ int   g_off[NT+1];
__device__ int   g_cur[NT];
__device__ int   g_nbr[EE];
__device__ float g_hlocal[NT*CC];
__device__ float g_hattn[NT*CC];
__device__ float g_out2[NT*CC];
__device__ float g_sums[3*2*CC];
__device__ float g_scale[3*CC];
__device__ float g_shift[3*CC];

__device__ __nv_bfloat16 g_aggs[NT*384];     // [hi|lo|hi]
__device__ __nv_bfloat16 g_obufs[NT*384];
__device__ __nv_bfloat16 g_combs[NT*384];
__device__ __nv_bfloat16 g_hiddens[NT*768];
__device__ __nv_bfloat16 g_Wcs[128*384];     // [hi|hi|lo]
__device__ __nv_bfloat16 g_ipws[384*384];
__device__ __nv_bfloat16 g_opws[128*384];
__device__ __nv_bfloat16 g_Wm1s[256*384];
__device__ __nv_bfloat16 g_Wm2s[128*768];
// attention operands (fp16): Q split [hi(32)|lo(32)], K/V single
__device__ __half g_qs[BB*HH*NNODE*64];
__device__ __half g_ks[BB*HH*NNODE*32];
__device__ __half g_vs[BB*HH*NNODE*32];

// ---------------- helpers ----------------
__device__ __forceinline__ uint32_t smem_u32(const void* p) {
    uint32_t a;
    asm("{ .reg .u64 t; cvta.to.shared.u64 t, %1; cvt.u32.u64 %0, t; }" : "=r"(a) : "l"(p));
    return a;
}
__device__ __forceinline__ uint32_t pack_bf2(__nv_bfloat16 a, __nv_bfloat16 b) {
    return (uint32_t)__bfloat16_as_ushort(a) | ((uint32_t)__bfloat16_as_ushort(b) << 16);
}
__device__ __forceinline__ uint32_t pack_h2(__half a, __half b) {
    return (uint32_t)__half_as_ushort(a) | ((uint32_t)__half_as_ushort(b) << 16);
}
__device__ __forceinline__ void split_bf(float v, __nv_bfloat16& hi, __nv_bfloat16& lo) {
    hi = __float2bfloat16(v);
    lo = __float2bfloat16(v - __bfloat162float(hi));
}
__device__ __forceinline__ void split_h(float v, __half& hi, __half& lo) {
    hi = __float2half(v);
    lo = __float2half(v - __half2float(hi));
}
__device__ __forceinline__ void ldmx4(uint32_t* r, uint32_t addr) {
    asm volatile("ldmatrix.sync.aligned.m8n8.x4.shared.b16 {%0,%1,%2,%3}, [%4];"
        : "=r"(r[0]), "=r"(r[1]), "=r"(r[2]), "=r"(r[3]) : "r"(addr));
}
__device__ __forceinline__ void mma_bf(float* c, const uint32_t* a, uint32_t b0, uint32_t b1) {
    asm volatile("mma.sync.aligned.m16n8k16.row.col.f32.bf16.bf16.f32 "
        "{%0,%1,%2,%3}, {%4,%5,%6,%7}, {%8,%9}, {%0,%1,%2,%3};"
        : "+f"(c[0]), "+f"(c[1]), "+f"(c[2]), "+f"(c[3])
        : "r"(a[0]), "r"(a[1]), "r"(a[2]), "r"(a[3]), "r"(b0), "r"(b1));
}
__device__ __forceinline__ void mma_f16(float* c, const uint32_t* a, uint32_t b0, uint32_t b1) {
    asm volatile("mma.sync.aligned.m16n8k16.row.col.f32.f16.f16.f32 "
        "{%0,%1,%2,%3}, {%4,%5,%6,%7}, {%8,%9}, {%0,%1,%2,%3};"
        : "+f"(c[0]), "+f"(c[1]), "+f"(c[2]), "+f"(c[3])
        : "r"(a[0]), "r"(a[1]), "r"(a[2]), "r"(a[3]), "r"(b0), "r"(b1));
}
__device__ __forceinline__ void store_a128(__nv_bfloat16* base, int r, int c, float v) {
    __nv_bfloat16 hi, lo; split_bf(v, hi, lo);
    __nv_bfloat16* o = base + (size_t)r * 384;
    o[c] = hi; o[128 + c] = lo; o[256 + c] = hi;
}
__device__ __forceinline__ void store_w(__nv_bfloat16* base, int r, int c, int K, float v) {
    __nv_bfloat16 hi, lo; split_bf(v, hi, lo);
    __nv_bfloat16* o = base + (size_t)(3*r) * K;
    o[c] = hi; o[K + c] = hi; o[2*K + c] = lo;
}

// ---------------- CSR build ----------------
__global__ void k_zero() {
    int i = blockIdx.x * blockDim.x + threadIdx.x;
    if (i < NT) g_deg[i] = 0;
    if (i < 3*2*CC) g_sums[i] = 0.f;
}
__global__ void k_deg(const int* __restrict__ dst) {
    int i = blockIdx.x * blockDim.x + threadIdx.x;
    if (i < EE) atomicAdd(&g_deg[dst[i]], 1);
}
__global__ void k_scan() {
    __shared__ int wsum[32];
    int t = threadIdx.x, lane = t & 31, wp = t >> 5;
    int4 v[8];
    const int4* dp = (const int4*)g_deg + t*8;
    int s = 0;
    #pragma unroll
    for (int i = 0; i < 8; i++) {
        v[i] = dp[i];
        s += v[i].x + v[i].y + v[i].z + v[i].w;
    }
    int incl = s;
    #pragma unroll
    for (int o = 1; o < 32; o <<= 1) {
        int n = __shfl_up_sync(0xffffffffu, incl, o);
        if (lane >= o) incl += n;
    }
    if (lane == 31) wsum[wp] = incl;
    __syncthreads();
    if (wp == 0) {
        int ws = wsum[lane];
        int wi = ws;
        #pragma unroll
        for (int o = 1; o < 32; o <<= 1) {
            int n = __shfl_up_sync(0xffffffffu, wi, o);
            if (lane >= o) wi += n;
        }
        wsum[lane] = wi - ws;  // exclusive
    }
    __syncthreads();
    int run = wsum[wp] + (incl - s);
    int4* op = (int4*)g_off + t*8;
    int4* cp = (int4*)g_cur + t*8;
    #pragma unroll
    for (int i = 0; i < 8; i++) {
        int4 o4;
        o4.x = run; run += v[i].x;
        o4.y = run; run += v[i].y;
        o4.z = run; run += v[i].z;
        o4.w = run; run += v[i].w;
        op[i] = o4; cp[i] = o4;
    }
    if (t == 1023) g_off[NT] = run;
}
__global__ void k_fill(const int* __restrict__ src, const int* __restrict__ dst) {
    int i = blockIdx.x * blockDim.x + threadIdx.x;
    if (i < EE) {
        int p = atomicAdd(&g_cur[dst[i]], 1);
        g_nbr[p] = src[i];
    }
}

// ---------------- weights-only prep (side stream) ----------------
__global__ void k_prep_w(const float* __restrict__ Wc, const float* __restrict__ ipw,
                         const float* __restrict__ opw, const float* __restrict__ Wm1,
                         const float* __restrict__ Wm2) {
    int i = blockIdx.x * 256 + threadIdx.x;
    if (i < 16384) { store_w(g_Wcs, i >> 7, i & 127, 128, Wc[i]); return; }
    i -= 16384;
    if (i < 49152) { store_w(g_ipws, i >> 7, i & 127, 128, ipw[i]); return; }
    i -= 49152;
    if (i < 16384) { store_w(g_opws, i >> 7, i & 127, 128, opw[i]); return; }
    i -= 16384;
    if (i < 32768) { store_w(g_Wm1s, i >> 7, i & 127, 128, Wm1[i]); return; }
    i -= 32768;
    store_w(g_Wm2s, i >> 8, i & 255, 256, Wm2[i]);
}

// ---------------- mean aggregation ----------------
__global__ void k_agg(const float* __restrict__ x) {
    __shared__ int snbr[128];
    int n = blockIdx.x, c = threadIdx.x;
    int s0 = g_off[n], s1 = g_off[n+1];
    float acc = 0.f;
    for (int j0 = s0; j0 < s1; j0 += 128) {
        int m = min(128, s1 - j0);
        __syncthreads();
        if (c < m) snbr[c] = g_nbr[j0 + c];
        __syncthreads();
        for (int jj = 0; jj < m; jj++) acc += x[snbr[jj]*CC + c];
    }
    float d = (float)(s1 - s0);
    store_a128(g_aggs, n, c, acc / fmaxf(d, 1.f));
}

// ---------------- GEMM mainloop ----------------
#define MG_SMEM (2*32768)

__device__ __forceinline__ void mg_mainloop(
    const __nv_bfloat16* __restrict__ Ap, const __nv_bfloat16* __restrict__ Wp,
    int Kp, char* smem, uint32_t sbase, int t, int lane, int mrow, int ncol,
    float acc[4][4][4])
{
    const int nch = Kp >> 6;
    auto load_chunk = [&](int ck, int buf) {
        int kc = ck * 64;
        #pragma unroll
        for (int i = 0; i < 8; i++) {
            int u = t + 256*i;
            int row_all = u >> 3, seg = u & 7;
            int isB = row_all >> 7;
            int row = row_all & 127;
            const __nv_bfloat16* src = (isB ? Wp : Ap) + (size_t)row * Kp + kc + seg*8;
            uint32_t dst = sbase + buf*32768 + isB*16384 + row*128 + ((seg ^ (row & 7)) * 16);
            asm volatile("cp.async.cg.shared.global [%0], [%1], 16;" :: "r"(dst), "l"(src));
        }
        asm volatile("cp.async.commit_group;" ::: "memory");
    };
    load_chunk(0, 0);
    for (int ck = 0; ck < nch; ck++) {
        if (ck + 1 < nch) {
            load_chunk(ck + 1, (ck + 1) & 1);
            asm volatile("cp.async.wait_group 1;" ::: "memory");
        } else {
            asm volatile("cp.async.wait_group 0;" ::: "memory");
        }
        __syncthreads();
        uint32_t Ab = sbase + (ck & 1)*32768;
        uint32_t Bb = Ab + 16384;
        #pragma unroll
        for (int s = 0; s < 4; s++) {
            int segsw = ((s*2 + (lane >> 4)) ^ (lane & 7)) * 16;
            uint32_t af[4][4];
            #pragma unroll
            for (int mt = 0; mt < 4; mt++)
                ldmx4(af[mt], Ab + (mrow + mt*16 + (lane & 15))*128 + segsw);
            uint32_t bf[4][2];
            #pragma unroll
            for (int half = 0; half < 2; half++) {
                uint32_t r4[4];
                ldmx4(r4, Bb + (ncol + half*16 + (lane & 15))*128 + segsw);
                bf[half*2+0][0] = r4[0]; bf[half*2+0][1] = r4[2];
                bf[half*2+1][0] = r4[1]; bf[half*2+1][1] = r4[3];
            }
            #pragma unroll
            for (int mt = 0; mt < 4; mt++)
                #pragma unroll
                for (int nt = 0; nt < 4; nt++)
                    mma_bf(acc[mt][nt], af[mt], bf[nt][0], bf[nt][1]);
        }
        __syncthreads();
    }
}

__device__ __forceinline__ void mg_stats_flush(char* smem, int t, int lane, int ncol,
                                               const float* csum, const float* csq, int which) {
    float* ssum = (float*)smem;
    float* ssq  = ssum + 128;
    if (t < 256) { ((float*)smem)[t] = 0.f; }
    __syncthreads();
    #pragma unroll
    for (int nt = 0; nt < 4; nt++) {
        int c0 = ncol + nt*8 + 2*(lane & 3);
        atomicAdd(&ssum[c0],   csum[nt*2+0]);
        atomicAdd(&ssum[c0+1], csum[nt*2+1]);
        atomicAdd(&ssq[c0],    csq[nt*2+0]);
        atomicAdd(&ssq[c0+1],  csq[nt*2+1]);
    }
    __syncthreads();
    if (t < 128) {
        atomicAdd(&g_sums[which*256 + t],       ssum[t]);
        atomicAdd(&g_sums[which*256 + 128 + t], ssq[t]);
    }
}

// EPI: 1 = +bias+resid(fp32) -> out (+stats) ; 2 = relu -> hiddens ; 4 = +bias+resid(from g_combs hi+lo) -> out (+stats)
template<int EPI, int WHICH>
__global__ __launch_bounds__(256, 2) void k_mgemm(
    const __nv_bfloat16* __restrict__ A, const __nv_bfloat16* __restrict__ W,
    const float* __restrict__ bias, const float* __restrict__ resid,
    float* __restrict__ out, int Kp, int Nout)
{
    extern __shared__ char smem[];
    const int t = threadIdx.x, lane = t & 31, w = t >> 5;
    const int bm = blockIdx.x, bn = blockIdx.y;
    const uint32_t sbase = smem_u32(smem);
    const int mrow = (w >> 2) * 64;
    const int ncol = (w & 3) * 32;
    const __nv_bfloat16* Ap = A + (size_t)bm * 128 * Kp;
    const __nv_bfloat16* Wp = W + (size_t)bn * 128 * Kp;

    float acc[4][4][4];
    #pragma unroll
    for (int a = 0; a < 4; a++)
        #pragma unroll
        for (int b = 0; b < 4; b++)
            #pragma unroll
            for (int c = 0; c < 4; c++) acc[a][b][c] = 0.f;

    mg_mainloop(Ap, Wp, Kp, smem, sbase, t, lane, mrow, ncol, acc);

    float csum[8] = {}, csq[8] = {};
    #pragma unroll
    for (int mt = 0; mt < 4; mt++) {
        int m0 = bm*128 + mrow + mt*16 + (lane >> 2);
        #pragma unroll
        for (int nt = 0; nt < 4; nt++) {
            int nl = ncol + nt*8 + 2*(lane & 3);
            int ng = bn*128 + nl;
            float bv0 = bias[ng], bv1 = bias[ng+1];
            #pragma unroll
            for (int hh = 0; hh < 2; hh++) {
                int m = m0 + hh*8;
                float v0 = acc[mt][nt][hh*2+0] + bv0;
                float v1 = acc[mt][nt][hh*2+1] + bv1;
                if (EPI == 2) {
                    v0 = fmaxf(v0, 0.f); v1 = fmaxf(v1, 0.f);
                    __nv_bfloat16 h0, l0, h1, l1;
                    split_bf(v0, h0, l0); split_bf(v1, h1, l1);
                    __nv_bfloat16* dst = g_hiddens + (size_t)m*768 + ng;
                    *(uint32_t*)(dst)       = pack_bf2(h0, h1);
                    *(uint32_t*)(dst + 256) = pack_bf2(l0, l1);
                    *(uint32_t*)(dst + 512) = pack_bf2(h0, h1);
                } else {
                    if (EPI == 4) {
                        uint32_t hv = *(const uint32_t*)(g_combs + (size_t)m*384 + ng);
                        uint32_t lv = *(const uint32_t*)(g_combs + (size_t)m*384 + 128 + ng);
                        v0 += __bfloat162float(__ushort_as_bfloat16((unsigned short)(hv & 0xffff)))
                            + __bfloat162float(__ushort_as_bfloat16((unsigned short)(lv & 0xffff)));
                        v1 += __bfloat162float(__ushort_as_bfloat16((unsigned short)(hv >> 16)))
                            + __bfloat162float(__ushort_as_bfloat16((unsigned short)(lv >> 16)));
                    } else {
                        const float2 rv = *(const float2*)(resid + (size_t)m*Nout + ng);
                        v0 += rv.x; v1 += rv.y;
                    }
                    *(float2*)(out + (size_t)m*Nout + ng) = make_float2(v0, v1);
                    if (WHICH >= 0) {
                        csum[nt*2+0] += v0; csq[nt*2+0] += v0*v0;
                        csum[nt*2+1] += v1; csq[nt*2+1] += v1*v1;
                    }
                }
            }
        }
    }
    if (EPI != 2 && WHICH >= 0) {
        __syncthreads();
        mg_stats_flush(smem, t, lane, ncol, csum, csq, WHICH);
    }
}

// ---------------- QKV GEMM with inline x fp32 -> split-bf16 conversion; fp16 outputs ----------------
__global__ __launch_bounds__(256, 2) void k_qkv(const float* __restrict__ x,
                                                const float* __restrict__ ipb) {
    extern __shared__ char smem[];
    const int t = threadIdx.x, lane = t & 31, w = t >> 5;
    const int bm = blockIdx.x, bn = blockIdx.y;
    const uint32_t sbase = smem_u32(smem);
    const int mrow = (w >> 2) * 64;
    const int ncol = (w & 3) * 32;
    const float* Xp = x + (size_t)bm * 128 * 128;
    const __nv_bfloat16* Wp = g_ipws + (size_t)bn * 128 * 384;

    float acc[4][4][4];
    #pragma unroll
    for (int a = 0; a < 4; a++)
        #pragma unroll
        for (int b = 0; b < 4; b++)
            #pragma unroll
            for (int c = 0; c < 4; c++) acc[a][b][c] = 0.f;

    auto load_chunk = [&](int ck, int buf) {
        int kc = ck * 64;
        int v = kc >> 7;
        int c0 = kc & 127;
        #pragma unroll
        for (int i = 0; i < 4; i++) {
            int u = t + 256*i;
            int r = u >> 3, s = u & 7;
            const float* srcx = Xp + (size_t)r*128 + c0 + s*8;
            float4 f0 = *(const float4*)(srcx);
            float4 f1 = *(const float4*)(srcx + 4);
            float vals[8] = {f0.x,f0.y,f0.z,f0.w,f1.x,f1.y,f1.z,f1.w};
            uint32_t pk[4];
            if (v == 1) {
                #pragma unroll
                for (int k2 = 0; k2 < 4; k2++) {
                    __nv_bfloat16 h0 = __float2bfloat16(vals[k2*2]);
                    __nv_bfloat16 h1 = __float2bfloat16(vals[k2*2+1]);
                    __nv_bfloat16 l0 = __float2bfloat16(vals[k2*2]   - __bfloat162float(h0));
                    __nv_bfloat16 l1 = __float2bfloat16(vals[k2*2+1] - __bfloat162float(h1));
                    pk[k2] = pack_bf2(l0, l1);
                }
            } else {
                #pragma unroll
                for (int k2 = 0; k2 < 4; k2++)
                    pk[k2] = pack_bf2(__float2bfloat16(vals[k2*2]), __float2bfloat16(vals[k2*2+1]));
            }
            *(uint4*)(smem + buf*32768 + r*128 + ((s ^ (r & 7)) * 16)) = make_uint4(pk[0],pk[1],pk[2],pk[3]);
        }
        #pragma unroll
        for (int i = 0; i < 4; i++) {
            int u = t + 256*i;
            int r = u >> 3, s = u & 7;
            const __nv_bfloat16* src = Wp + (size_t)r * 384 + kc + s*8;
            uint32_t dst = sbase + buf*32768 + 16384 + r*128 + ((s ^ (r & 7)) * 16);
            asm volatile("cp.async.cg.shared.global [%0], [%1], 16;" :: "r"(dst), "l"(src));
        }
        asm volatile("cp.async.commit_group;" ::: "memory");
    };

    load_chunk(0, 0);
    for (int ck = 0; ck < 6; ck++) {
        if (ck + 1 < 6) {
            load_chunk(ck + 1, (ck + 1) & 1);
            asm volatile("cp.async.wait_group 1;" ::: "memory");
        } else {
            asm volatile("cp.async.wait_group 0;" ::: "memory");
        }
        __syncthreads();
        uint32_t Ab = sbase + (ck & 1)*32768;
        uint32_t Bb = Ab + 16384;
        #pragma unroll
        for (int s = 0; s < 4; s++) {
            int segsw = ((s*2 + (lane >> 4)) ^ (lane & 7)) * 16;
            uint32_t af[4][4];
            #pragma unroll
            for (int mt = 0; mt < 4; mt++)
                ldmx4(af[mt], Ab + (mrow + mt*16 + (lane & 15))*128 + segsw);
            uint32_t bf[4][2];
            #pragma unroll
            for (int half = 0; half < 2; half++) {
                uint32_t r4[4];
                ldmx4(r4, Bb + (ncol + half*16 + (lane & 15))*128 + segsw);
                bf[half*2+0][0] = r4[0]; bf[half*2+0][1] = r4[2];
                bf[half*2+1][0] = r4[1]; bf[half*2+1][1] = r4[3];
            }
            #pragma unroll
            for (int mt = 0; mt < 4; mt++)
                #pragma unroll
                for (int nt = 0; nt < 4; nt++)
                    mma_bf(acc[mt][nt], af[mt], bf[nt][0], bf[nt][1]);
        }
        __syncthreads();
    }

    // epilogue: Q -> fp16 split [hi|lo]; K/V -> single fp16
    #pragma unroll
    for (int mt = 0; mt < 4; mt++) {
        int m0 = bm*128 + mrow + mt*16 + (lane >> 2);
        #pragma unroll
        for (int nt = 0; nt < 4; nt++) {
            int nl = ncol + nt*8 + 2*(lane & 3);
            float bv0 = ipb[bn*128 + nl], bv1 = ipb[bn*128 + nl + 1];
            #pragma unroll
            for (int hh = 0; hh < 2; hh++) {
                int m = m0 + hh*8;
                float v0 = acc[mt][nt][hh*2+0] + bv0;
                float v1 = acc[mt][nt][hh*2+1] + bv1;
                int h = nl >> 5, d = nl & 31;
                int bh = (m >> 9)*HH + h;
                int node = m & 511;
                if (bn == 0) {
                    __half h0, l0, h1, l1;
                    split_h(v0, h0, l0); split_h(v1, h1, l1);
                    __half* dst = g_qs + ((size_t)bh*NNODE + node)*64 + d;
                    *(uint32_t*)(dst)      = pack_h2(h0, h1);
                    *(uint32_t*)(dst + 32) = pack_h2(l0, l1);
                } else {
                    __half* dp = (bn == 1) ? g_ks : g_vs;
                    __half* dst = dp + ((size_t)bh*NNODE + node)*32 + d;
                    *(uint32_t*)(dst) = pack_h2(__float2half(v0), __float2half(v1));
                }
            }
        }
    }
}

// ---------------- flash attention: fp16 2-term, 512 threads ----------------
// smem: Q[512][64]h (64KB) | K rows 128B-padded, data 64B (64KB) | Vt[32][512]h (32KB)
#define FA_SMEM (65536 + 65536 + 32768)
__global__ __launch_bounds__(512, 1) void k_fattn() {
    extern __shared__ char sm2[];
    const uint32_t sb = smem_u32(sm2);
    const uint32_t Qb = sb, Kb = sb + 65536, Vb = sb + 131072;
    const int bh = blockIdx.x, t = threadIdx.x, lane = t & 31, w = t >> 5;
    const __half* qg = g_qs + (size_t)bh * NNODE * 64;
    const __half* kg = g_ks + (size_t)bh * NNODE * 32;
    const __half* vg = g_vs + (size_t)bh * NNODE * 32;

    for (int i = t; i < 4096; i += 512) {
        int r = i >> 3, s = i & 7;
        *(float4*)(sm2 + r*128 + ((s ^ (r & 7)) * 16)) = *(const float4*)(qg + r*64 + s*8);
    }
    for (int i = t; i < 2048; i += 512) {
        int r = i >> 2, s = i & 3;
        *(float4*)(sm2 + 65536 + r*128 + ((s ^ (r & 7)) * 16)) = *(const float4*)(kg + r*32 + s*8);
    }
    for (int i = t; i < 2048; i += 512) {
        int j = i & 511, s = i >> 9;   // s in 0..3
        float4 v4 = *(const float4*)(vg + j*32 + s*8);
        const __half* pv = (const __half*)&v4;
        #pragma unroll
        for (int k = 0; k < 8; k++) {
            int d = s*8 + k;           // 0..31
            *(__half*)(sm2 + 131072 + d*1024 + (((j >> 3) ^ (d & 7)) * 16) + (j & 7)*2) = pv[k];
        }
    }
    __syncthreads();

    const int q0 = w * 32;
    uint32_t aqh[2][2][4];
    #pragma unroll
    for (int mt = 0; mt < 2; mt++)
        #pragma unroll
        for (int kc = 0; kc < 2; kc++) {
            int row = q0 + mt*16 + (lane & 15);
            ldmx4(aqh[mt][kc], Qb + row*128 + (((kc*2 + (lane >> 4)) ^ (row & 7)) * 16));
        }

    float of[2][4][4];
    #pragma unroll
    for (int a = 0; a < 2; a++)
        #pragma unroll
        for (int b = 0; b < 4; b++)
            #pragma unroll
            for (int c = 0; c < 4; c++) of[a][b][c] = 0.f;
    float mrow[2][2], lrow[2][2];
    #pragma unroll
    for (int a = 0; a < 2; a++) { mrow[a][0] = -1e30f; mrow[a][1] = -1e30f; lrow[a][0] = 0.f; lrow[a][1] = 0.f; }

    const float sc = 0.17677669529663687f;

    for (int jb = 0; jb < 32; jb++) {
        const int j0 = jb * 16;
        // K fragments (single fp16): data lives in logical segs 0..3
        uint32_t bk[2][2][2];
        #pragma unroll
        for (int kc = 0; kc < 2; kc++) {
            int row = j0 + (lane & 15);
            uint32_t r4[4];
            ldmx4(r4, Kb + row*128 + (((kc*2 + (lane >> 4)) ^ (row & 7)) * 16));
            bk[kc][0][0] = r4[0]; bk[kc][0][1] = r4[2];
            bk[kc][1][0] = r4[1]; bk[kc][1][1] = r4[3];
        }
        float c[2][2][4];
        #pragma unroll
        for (int a = 0; a < 2; a++)
            #pragma unroll
            for (int b = 0; b < 2; b++)
                #pragma unroll
                for (int e = 0; e < 4; e++) c[a][b][e] = 0.f;
        #pragma unroll
        for (int mt = 0; mt < 2; mt++) {
            uint32_t aql[2][4];
            #pragma unroll
            for (int kc = 0; kc < 2; kc++) {
                int row = q0 + mt*16 + (lane & 15);
                ldmx4(aql[kc], Qb + row*128 + ((((kc + 2)*2 + (lane >> 4)) ^ (row & 7)) * 16));
            }
            #pragma unroll
            for (int nt = 0; nt < 2; nt++) {
                mma_f16(c[mt][nt], aqh[mt][0], bk[0][nt][0], bk[0][nt][1]);
                mma_f16(c[mt][nt], aqh[mt][1], bk[1][nt][0], bk[1][nt][1]);
                mma_f16(c[mt][nt], aql[0],     bk[0][nt][0], bk[0][nt][1]);
                mma_f16(c[mt][nt], aql[1],     bk[1][nt][0], bk[1][nt][1]);
            }
        }
        #pragma unroll
        for (int mt = 0; mt < 2; mt++)
            #pragma unroll
            for (int h = 0; h < 2; h++) {
                float s0 = c[mt][0][h*2]*sc, s1 = c[mt][0][h*2+1]*sc;
                float s2 = c[mt][1][h*2]*sc, s3 = c[mt][1][h*2+1]*sc;
                float mx = fmaxf(fmaxf(s0, s1), fmaxf(s2, s3));
                mx = fmaxf(mx, __shfl_xor_sync(0xffffffffu, mx, 1));
                mx = fmaxf(mx, __shfl_xor_sync(0xffffffffu, mx, 2));
                float mnew = fmaxf(mrow[mt][h], mx);
                float fac = __expf(mrow[mt][h] - mnew);
                mrow[mt][h] = mnew;
                float p0 = __expf(s0 - mnew), p1 = __expf(s1 - mnew);
                float p2 = __expf(s2 - mnew), p3 = __expf(s3 - mnew);
                c[mt][0][h*2] = p0; c[mt][0][h*2+1] = p1;
                c[mt][1][h*2] = p2; c[mt][1][h*2+1] = p3;
                float rs = p0 + p1 + p2 + p3;
                rs += __shfl_xor_sync(0xffffffffu, rs, 1);
                rs += __shfl_xor_sync(0xffffffffu, rs, 2);
                lrow[mt][h] = lrow[mt][h]*fac + rs;
                #pragma unroll
                for (int nt = 0; nt < 4; nt++) { of[mt][nt][h*2] *= fac; of[mt][nt][h*2+1] *= fac; }
            }
        // P fragments: fp16 hi/lo
        uint32_t pah[2][4], pal[2][4];
        #pragma unroll
        for (int mt = 0; mt < 2; mt++) {
            __half hx, lx, hy, ly;
            split_h(c[mt][0][0], hx, lx); split_h(c[mt][0][1], hy, ly);
            pah[mt][0] = pack_h2(hx, hy); pal[mt][0] = pack_h2(lx, ly);
            split_h(c[mt][0][2], hx, lx); split_h(c[mt][0][3], hy, ly);
            pah[mt][1] = pack_h2(hx, hy); pal[mt][1] = pack_h2(lx, ly);
            split_h(c[mt][1][0], hx, lx); split_h(c[mt][1][1], hy, ly);
            pah[mt][2] = pack_h2(hx, hy); pal[mt][2] = pack_h2(lx, ly);
            split_h(c[mt][1][2], hx, lx); split_h(c[mt][1][3], hy, ly);
            pah[mt][3] = pack_h2(hx, hy); pal[mt][3] = pack_h2(lx, ly);
        }
        // V fragments (single fp16): rows 0..31
        uint32_t bvh[4][2];
        #pragma unroll
        for (int dh = 0; dh < 2; dh++) {
            int rowh = dh*16 + (lane & 15);
            uint32_t r4[4];
            ldmx4(r4, Vb + rowh*1024 + (((((j0 >> 3) + (lane >> 4)) ^ (rowh & 7))) * 16));
            bvh[dh*2+0][0] = r4[0]; bvh[dh*2+0][1] = r4[2];
            bvh[dh*2+1][0] = r4[1]; bvh[dh*2+1][1] = r4[3];
        }
        #pragma unroll
        for (int mt = 0; mt < 2; mt++)
            #pragma unroll
            for (int nt = 0; nt < 4; nt++) {
                mma_f16(of[mt][nt], pah[mt], bvh[nt][0], bvh[nt][1]);
                mma_f16(of[mt][nt], pal[mt], bvh[nt][0], bvh[nt][1]);
            }
    }

    const int b = bh >> 2, h4 = bh & 3;
    #pragma unroll
    for (int mt = 0; mt < 2; mt++)
        #pragma unroll
        for (int h = 0; h < 2; h++) {
            float inv = 1.f / lrow[mt][h];
            int q = q0 + mt*16 + (lane >> 2) + h*8;
            __nv_bfloat16* base = g_obufs + ((size_t)(b*NNODE + q))*384 + h4*DHD;
            #pragma unroll
            for (int nt = 0; nt < 4; nt++) {
                int d = nt*8 + 2*(lane & 3);
                float v0 = of[mt][nt][h*2]   * inv;
                float v1 = of[mt][nt][h*2+1] * inv;
                __nv_bfloat16 h0, l0, h1, l1;
                split_bf(v0, h0, l0); split_bf(v1, h1, l1);
                *(uint32_t*)(base + d)       = pack_bf2(h0, h1);
                *(uint32_t*)(base + 128 + d) = pack_bf2(l0, l1);
                *(uint32_t*)(base + 256 + d) = pack_bf2(h0, h1);
            }
        }
}

// ---------------- finalize / combine / final ----------------
__global__ void k_fin12(const float* __restrict__ gn1, const float* __restrict__ bn1,
                        const float* __restrict__ gn2, const float* __restrict__ bn2) {
    int t = threadIdx.x;
    int which = t >> 7, c = t & 127;
    const float* g = which ? gn2 : gn1;
    const float* b = which ? bn2 : bn1;
    float s  = g_sums[which*256 + c];
    float s2 = g_sums[which*256 + 128 + c];
    float m  = s / (float)NT;
    float v  = s2 / (float)NT - m*m;
    float scale = g[c] * rsqrtf(v + 1e-5f);
    g_scale[which*128 + c] = scale;
    g_shift[which*128 + c] = b[c] - m*scale;
}
__global__ void k_fin3(const float* __restrict__ g, const float* __restrict__ b) {
    int c = threadIdx.x;
    float s  = g_sums[2*256 + c];
    float s2 = g_sums[2*256 + 128 + c];
    float m  = s / (float)NT;
    float v  = s2 / (float)NT - m*m;
    float scale = g[c] * rsqrtf(v + 1e-5f);
    g_scale[2*128 + c] = scale;
    g_shift[2*128 + c] = b[c] - m*scale;
}

__global__ void k_combine() {   // combs(split) = bn1(hlocal)+bn2(hattn)
    int i = blockIdx.x * blockDim.x + threadIdx.x;
    int c = (i*4) & 127;
    int r = (i*4) >> 7;
    float4 a  = *(const float4*)(g_hlocal + (size_t)i*4);
    float4 bb = *(const float4*)(g_hattn + (size_t)i*4);
    float4 s1 = *(const float4*)(g_scale + c);
    float4 h1 = *(const float4*)(g_shift + c);
    float4 s2 = *(const float4*)(g_scale + 128 + c);
    float4 h2 = *(const float4*)(g_shift + 128 + c);
    float4 o;
    o.x = a.x*s1.x + h1.x + bb.x*s2.x + h2.x;
    o.y = a.y*s1.y + h1.y + bb.y*s2.y + h2.y;
    o.z = a.z*s1.z + h1.z + bb.z*s2.z + h2.z;
    o.w = a.w*s1.w + h1.w + bb.w*s2.w + h2.w;
    float vv[4] = {o.x, o.y, o.z, o.w};
    __nv_bfloat16 hi[4], lo[4];
    #pragma unroll
    for (int k = 0; k < 4; k++) split_bf(vv[k], hi[k], lo[k]);
    __nv_bfloat16* dst = g_combs + (size_t)r*384 + c;
    *(uint32_t*)(dst)       = pack_bf2(hi[0], hi[1]);
    *(uint32_t*)(dst + 2)   = pack_bf2(hi[2], hi[3]);
    *(uint32_t*)(dst + 128) = pack_bf2(lo[0], lo[1]);
    *(uint32_t*)(dst + 130) = pack_bf2(lo[2], lo[3]);
    *(uint32_t*)(dst + 256) = pack_bf2(hi[0], hi[1]);
    *(uint32_t*)(dst + 258) = pack_bf2(hi[2], hi[3]);
}

__global__ void k_final(float* __restrict__ out) {
    int i = blockIdx.x * blockDim.x + threadIdx.x;
    int c = (i*4) & 127;
    float4 a  = *(const float4*)(g_out2 + (size_t)i*4);
    float4 s3 = *(const float4*)(g_scale + 256 + c);
    float4 h3 = *(const float4*)(g_shift + 256 + c);
    float4 o;
    o.x = a.x*s3.x + h3.x;
    o.y = a.y*s3.y + h3.y;
    o.z = a.z*s3.z + h3.z;
    o.w = a.w*s3.w + h3.w;
    *(float4*)(out + (size_t)i*4) = o;
}

// ---------------- launch ----------------
extern "C" void kernel_launch(void* const* d_in, const int* in_sizes, int n_in,
                              void* d_out, int out_size) {
    const float* x   = (const float*)d_in[0];
    const int*   ei  = (const int*)  d_in[1];
    const float* Wc  = (const float*)d_in[2];
    const float* bc  = (const float*)d_in[3];
    const float* ipw = (const float*)d_in[4];
    const float* ipb = (const float*)d_in[5];
    const float* opw = (const float*)d_in[6];
    const float* opb = (const float*)d_in[7];
    const float* gn1 = (const float*)d_in[8];
    const float* bn1 = (const float*)d_in[9];
    const float* gn2 = (const float*)d_in[10];
    const float* bn2 = (const float*)d_in[11];
    const float* gn3 = (const float*)d_in[12];
    const float* bn3 = (const float*)d_in[13];
    const float* Wm1 = (const float*)d_in[14];
    const float* bm1 = (const float*)d_in[15];
    const float* Wm2 = (const float*)d_in[16];
    const float* bm2 = (const float*)d_in[17];
    const int* src = ei;
    const int* dst = ei + EE;

    void *p_hlocal, *p_hattn, *p_out2, *p_aggs, *p_obufs, *p_combs, *p_hiddens;
    void *p_Wcs, *p_opws, *p_Wm1s, *p_Wm2s;
    cudaGetSymbolAddress(&p_hlocal, g_hlocal);
    cudaGetSymbolAddress(&p_hattn,  g_hattn);
    cudaGetSymbolAddress(&p_out2,   g_out2);
    cudaGetSymbolAddress(&p_aggs,   g_aggs);
    cudaGetSymbolAddress(&p_obufs,  g_obufs);
    cudaGetSymbolAddress(&p_combs,  g_combs);
    cudaGetSymbolAddress(&p_hiddens,g_hiddens);
    cudaGetSymbolAddress(&p_Wcs,    g_Wcs);
    cudaGetSymbolAddress(&p_opws,   g_opws);
    cudaGetSymbolAddress(&p_Wm1s,   g_Wm1s);
    cudaGetSymbolAddress(&p_Wm2s,   g_Wm2s);

    cudaFuncSetAttribute(k_fattn, cudaFuncAttributeMaxDynamicSharedMemorySize, FA_SMEM);
    cudaFuncSetAttribute(k_qkv,         cudaFuncAttributeMaxDynamicSharedMemorySize, MG_SMEM);
    cudaFuncSetAttribute(k_mgemm<1,0>,  cudaFuncAttributeMaxDynamicSharedMemorySize, MG_SMEM);
    cudaFuncSetAttribute(k_mgemm<1,1>,  cudaFuncAttributeMaxDynamicSharedMemorySize, MG_SMEM);
    cudaFuncSetAttribute(k_mgemm<2,-1>, cudaFuncAttributeMaxDynamicSharedMemorySize, MG_SMEM);
    cudaFuncSetAttribute(k_mgemm<4,2>,  cudaFuncAttributeMaxDynamicSharedMemorySize, MG_SMEM);

    static cudaStream_t s2 = nullptr;
    static cudaEvent_t e_fork = nullptr, e0 = nullptr, e_prepw = nullptr, e_loc = nullptr;
    if (s2 == nullptr) {
        cudaStreamCreateWithFlags(&s2, cudaStreamNonBlocking);
        cudaEventCreateWithFlags(&e_fork, cudaEventDisableTiming);
        cudaEventCreateWithFlags(&e0,     cudaEventDisableTiming);
        cudaEventCreateWithFlags(&e_prepw,cudaEventDisableTiming);
        cudaEventCreateWithFlags(&e_loc,  cudaEventDisableTiming);
    }

    // ---- fork immediately ----
    cudaEventRecord(e_fork, 0);
    cudaStreamWaitEvent(s2, e_fork, 0);

    // ---- side stream: weight splits first ----
    k_prep_w<<<576, 256, 0, s2>>>(Wc, ipw, opw, Wm1, Wm2);
    cudaEventRecord(e_prepw, s2);

    // ---- main: zero ----
    k_zero<<<NT/256, 256>>>();
    cudaEventRecord(e0, 0);

    // ---- side: CSR chain + agg + local GEMM ----
    cudaStreamWaitEvent(s2, e0, 0);
    k_deg<<<EE/256, 256, 0, s2>>>(dst);
    k_scan<<<1, 1024, 0, s2>>>();
    k_fill<<<EE/256, 256, 0, s2>>>(src, dst);
    k_agg<<<NT, 128, 0, s2>>>(x);
    k_mgemm<1,0><<<dim3(NT/128, 1), 256, MG_SMEM, s2>>>(
        (const __nv_bfloat16*)p_aggs, (const __nv_bfloat16*)p_Wcs, bc, x, (float*)p_hlocal, 384, 128);
    cudaEventRecord(e_loc, s2);

    // ---- main: QKV -> attention -> out_proj ----
    cudaStreamWaitEvent(0, e_prepw, 0);
    k_qkv<<<dim3(NT/128, 3), 256, MG_SMEM>>>(x, ipb);

    k_fattn<<<BB*HH, 512, FA_SMEM>>>();

    k_mgemm<1,1><<<dim3(NT/128, 1), 256, MG_SMEM>>>(
        (const __nv_bfloat16*)p_obufs, (const __nv_bfloat16*)p_opws, opb, x, (float*)p_hattn, 384, 128);

    // ---- join, finish ----
    cudaStreamWaitEvent(0, e_loc, 0);
    k_fin12<<<1, 256>>>(gn1, bn1, gn2, bn2);
    k_combine<<<NT*CC/4/256, 256>>>();

    k_mgemm<2,-1><<<dim3(NT/128, 2), 256, MG_SMEM>>>(
        (const __nv_bfloat16*)p_combs, (const __nv_bfloat16*)p_Wm1s, bm1, nullptr, nullptr, 384, 256);

    k_mgemm<4,2><<<dim3(NT/128, 1), 256, MG_SMEM>>>(
        (const __nv_bfloat16*)p_hiddens, (const __nv_bfloat16*)p_Wm2s, bm2, nullptr, (float*)p_out2, 768, 128);

    k_fin3<<<1, 128>>>(gn3, bn3);
    k_final<<<NT*CC/4/256, 256>>>((float*)d_out);
}